// round 1
// baseline (speedup 1.0000x reference)
#include <cuda_runtime.h>
#include <math.h>

// Problem constants
#define NV 1024          // num nodes
#define NE 32768         // edges per adjacency
#define EMBD 128
#define HIDD 64
#define REPD 32

// ---------------- scratch (static device globals; no allocation) ----------------
__device__ float g_A[3][NV][NV];        // per-path dense adjacencies (max L=3)
__device__ float g_p1[16][512][512];    // conv1+pool output
__device__ float g_p2[4][257][257];     // conv2+pool output
__device__ float g_t1[16][514][514];    // tconv1 output
__device__ float g_att[3][NV][NV];      // attended adjacencies
__device__ float g_M[NV][NV];
__device__ float g_Mt[NV][NV];
__device__ float g_M0[NV][NV];
__device__ float g_An[NV][NV];
__device__ float g_dinv[NV];
__device__ float g_XW[NV][HIDD];
__device__ float g_H[NV][HIDD];
__device__ float g_HW[NV][REPD];

// ---------------- kernels ----------------

__global__ void scatter_edges(const int* __restrict__ e, float* __restrict__ A) {
    int k = blockIdx.x * blockDim.x + threadIdx.x;
    if (k < NE) {
        int r = e[k];
        int c = e[NE + k];
        atomicAdd(&A[r * NV + c], 1.0f);
    }
}

// conv1 (3x3, pad1, L->16) + relu + maxpool2 fused.  out: p1[16][512][512]
template <int L>
__global__ void conv1pool(const float* __restrict__ A, const float* __restrict__ w,
                          const float* __restrict__ b, float* __restrict__ p1) {
    __shared__ float sw[16 * L * 9];
    __shared__ float sb[16];
    int t = threadIdx.y * 16 + threadIdx.x;
    for (int i = t; i < 16 * L * 9; i += 256) sw[i] = w[i];
    if (t < 16) sb[t] = b[t];
    __syncthreads();
    int x = blockIdx.x * 16 + threadIdx.x;
    int y = blockIdx.y * 16 + threadIdx.y;
    if (x >= 512 || y >= 512) return;

    float patch[L][4][4];
#pragma unroll
    for (int l = 0; l < L; l++)
#pragma unroll
        for (int r = 0; r < 4; r++) {
            int iy = 2 * y - 1 + r;
#pragma unroll
            for (int c = 0; c < 4; c++) {
                int ix = 2 * x - 1 + c;
                patch[l][r][c] = (iy >= 0 && iy < NV && ix >= 0 && ix < NV)
                                     ? A[((size_t)l * NV + iy) * NV + ix] : 0.0f;
            }
        }
#pragma unroll
    for (int oc = 0; oc < 16; oc++) {
        float m = -1e30f;
#pragma unroll
        for (int py = 0; py < 2; py++)
#pragma unroll
            for (int px = 0; px < 2; px++) {
                float s = sb[oc];
#pragma unroll
                for (int l = 0; l < L; l++)
#pragma unroll
                    for (int ky = 0; ky < 3; ky++)
#pragma unroll
                        for (int kx = 0; kx < 3; kx++)
                            s += sw[((oc * L + l) * 3 + ky) * 3 + kx] * patch[l][py + ky][px + kx];
                m = fmaxf(m, fmaxf(s, 0.0f));
            }
        p1[((size_t)oc * 512 + y) * 512 + x] = m;
    }
}

// conv2 (3x3, pad2, 16->4) + relu + maxpool2 fused.  in: p1[16][512][512], out: p2[4][257][257]
__global__ void conv2pool(const float* __restrict__ p1, const float* __restrict__ w,
                          const float* __restrict__ b, float* __restrict__ p2) {
    __shared__ float sw[576];
    __shared__ float sb[4];
    int t = threadIdx.y * 16 + threadIdx.x;
    for (int i = t; i < 576; i += 256) sw[i] = w[i];
    if (t < 4) sb[t] = b[t];
    __syncthreads();
    int x = blockIdx.x * 16 + threadIdx.x;
    int y = blockIdx.y * 16 + threadIdx.y;
    if (x >= 257 || y >= 257) return;

    float acc[4][2][2];
#pragma unroll
    for (int oc = 0; oc < 4; oc++)
#pragma unroll
        for (int py = 0; py < 2; py++)
#pragma unroll
            for (int px = 0; px < 2; px++) acc[oc][py][px] = sb[oc];

    for (int ci = 0; ci < 16; ci++) {
        float patch[4][4];
#pragma unroll
        for (int r = 0; r < 4; r++) {
            int iy = 2 * y - 2 + r;
#pragma unroll
            for (int c = 0; c < 4; c++) {
                int ix = 2 * x - 2 + c;
                patch[r][c] = (iy >= 0 && iy < 512 && ix >= 0 && ix < 512)
                                  ? p1[((size_t)ci * 512 + iy) * 512 + ix] : 0.0f;
            }
        }
#pragma unroll
        for (int oc = 0; oc < 4; oc++)
#pragma unroll
            for (int ky = 0; ky < 3; ky++)
#pragma unroll
                for (int kx = 0; kx < 3; kx++) {
                    float wv = sw[((oc * 16 + ci) * 3 + ky) * 3 + kx];
                    acc[oc][0][0] += wv * patch[ky][kx];
                    acc[oc][0][1] += wv * patch[ky][kx + 1];
                    acc[oc][1][0] += wv * patch[ky + 1][kx];
                    acc[oc][1][1] += wv * patch[ky + 1][kx + 1];
                }
    }
#pragma unroll
    for (int oc = 0; oc < 4; oc++) {
        float m = fmaxf(fmaxf(acc[oc][0][0], acc[oc][0][1]), fmaxf(acc[oc][1][0], acc[oc][1][1]));
        p2[((size_t)oc * 257 + y) * 257 + x] = fmaxf(m, 0.0f);
    }
}

// tconv1 (k2 s2, 4->16) + relu.  in: p2[4][257][257], out: t1[16][514][514]
__global__ void tconv1k(const float* __restrict__ p2, const float* __restrict__ w,
                        const float* __restrict__ b, float* __restrict__ t1) {
    int idx = blockIdx.x * blockDim.x + threadIdx.x;
    if (idx >= 514 * 514) return;
    int ox = idx % 514, oy = idx / 514;
    int ky = (oy + 1) & 1, kx = (ox + 1) & 1;   // single contributing tap (parity)
    int iy = (oy - 1 + ky) >> 1, ix = (ox - 1 + kx) >> 1;
    float v[4];
#pragma unroll
    for (int ci = 0; ci < 4; ci++) v[ci] = p2[((size_t)ci * 257 + iy) * 257 + ix];
#pragma unroll
    for (int co = 0; co < 16; co++) {
        float s = b[co];
#pragma unroll
        for (int ci = 0; ci < 4; ci++) s += w[((co * 4 + ci) * 2 + ky) * 2 + kx] * v[ci];
        t1[((size_t)co * 514 + oy) * 514 + ox] = fmaxf(s, 0.0f);
    }
}

// tconv2 (k2 s2, 16->L) + sigmoid + crop + elementwise multiply by adjacency.
template <int L>
__global__ void tconv2att(const float* __restrict__ t1, const float* __restrict__ w,
                          const float* __restrict__ b, const float* __restrict__ A,
                          float* __restrict__ att) {
    int idx = blockIdx.x * blockDim.x + threadIdx.x;
    if (idx >= NV * NV) return;
    int x = idx % NV, y = idx / NV;
    int ky = (y + 1) & 1, kx = (x + 1) & 1;
    int iy = (y - 1 + ky) >> 1, ix = (x - 1 + kx) >> 1;
    float v[16];
#pragma unroll
    for (int ci = 0; ci < 16; ci++) v[ci] = t1[((size_t)ci * 514 + iy) * 514 + ix];
#pragma unroll
    for (int l = 0; l < L; l++) {
        float s = b[l];
#pragma unroll
        for (int ci = 0; ci < 16; ci++) s += w[((l * 16 + ci) * 2 + ky) * 2 + kx] * v[ci];
        float sg = 1.0f / (1.0f + expf(-s));
        att[(size_t)l * NV * NV + idx] = A[(size_t)l * NV * NV + idx] * sg;
    }
}

// row sums with self-loop fixup -> dinv = rsqrt(deg) (deg>0 guaranteed by fill=1)
__global__ void row_dinv(const float* __restrict__ A, float* __restrict__ dinv) {
    int row = blockIdx.x;
    const float* r = A + (size_t)row * NV;
    float s = 0.0f;
    for (int j = threadIdx.x; j < NV; j += 256) s += r[j];
    __shared__ float sh[256];
    sh[threadIdx.x] = s;
    __syncthreads();
    for (int o = 128; o > 0; o >>= 1) {
        if (threadIdx.x < o) sh[threadIdx.x] += sh[threadIdx.x + o];
        __syncthreads();
    }
    if (threadIdx.x == 0) {
        float d = sh[0];
        if (r[row] == 0.0f) d += 1.0f;   // add_remaining_self_loops(fill=1)
        dinv[row] = d > 0.0f ? rsqrtf(d) : 0.0f;
    }
}

// out[i][j] = dinv[i] * B[i][j] * dinv[j], B = A with diag fill
__global__ void gcn_scale(const float* __restrict__ A, const float* __restrict__ dinv,
                          float* __restrict__ out) {
    int idx = blockIdx.x * blockDim.x + threadIdx.x;
    if (idx >= NV * NV) return;
    int i = idx / NV, j = idx % NV;
    float v = A[idx];
    if (i == j && v == 0.0f) v = 1.0f;
    out[idx] = dinv[i] * v * dinv[j];
}

__global__ void emax(const float* __restrict__ a, const float* __restrict__ b,
                     float* __restrict__ o) {
    int idx = blockIdx.x * blockDim.x + threadIdx.x;
    if (idx < NV * NV) o[idx] = fmaxf(a[idx], b[idx]);
}

__global__ void bias_relu64(float* __restrict__ H, const float* __restrict__ bias) {
    int idx = blockIdx.x * blockDim.x + threadIdx.x;
    if (idx < NV * HIDD) H[idx] = fmaxf(H[idx] + bias[idx % HIDD], 0.0f);
}

__global__ void bias_add32(float* __restrict__ O, const float* __restrict__ bias) {
    int idx = blockIdx.x * blockDim.x + threadIdx.x;
    if (idx < NV * REPD) O[idx] += bias[idx % REPD];
}

// C(MxNn) = A(MxK, rm) * B(KxNn, rm).  BM=BN=64, BK=16, 16x16 threads, 4x4 microtile.
// M % 64 == 0, K % 16 == 0; Nn arbitrary (guarded).
__global__ void sgemm64(const float* __restrict__ A, const float* __restrict__ B,
                        float* __restrict__ C, int M, int Nn, int K) {
    __shared__ float As[16][64];
    __shared__ float Bs[16][64];
    int tx = threadIdx.x, ty = threadIdx.y;
    int tid = ty * 16 + tx;
    int m0 = blockIdx.y * 64, n0 = blockIdx.x * 64;
    float acc[4][4];
#pragma unroll
    for (int i = 0; i < 4; i++)
#pragma unroll
        for (int j = 0; j < 4; j++) acc[i][j] = 0.0f;

    int la_r = tid / 16, la_k = tid % 16;   // A loads: rows la_r+16r, col la_k
    int lb_k = tid / 64, lb_n = tid % 64;   // B loads: row lb_k+4r, col lb_n

    for (int k0 = 0; k0 < K; k0 += 16) {
#pragma unroll
        for (int r = 0; r < 4; r++)
            As[la_k][la_r + 16 * r] = A[(size_t)(m0 + la_r + 16 * r) * K + k0 + la_k];
#pragma unroll
        for (int r = 0; r < 4; r++) {
            int kk = lb_k + 4 * r;
            Bs[kk][lb_n] = (n0 + lb_n < Nn) ? B[(size_t)(k0 + kk) * Nn + n0 + lb_n] : 0.0f;
        }
        __syncthreads();
#pragma unroll
        for (int k = 0; k < 16; k++) {
            float a[4], b[4];
#pragma unroll
            for (int i = 0; i < 4; i++) a[i] = As[k][ty * 4 + i];
#pragma unroll
            for (int j = 0; j < 4; j++) b[j] = Bs[k][tx * 4 + j];
#pragma unroll
            for (int i = 0; i < 4; i++)
#pragma unroll
                for (int j = 0; j < 4; j++) acc[i][j] += a[i] * b[j];
        }
        __syncthreads();
    }
#pragma unroll
    for (int i = 0; i < 4; i++) {
        int row = m0 + ty * 4 + i;
#pragma unroll
        for (int j = 0; j < 4; j++) {
            int col = n0 + tx * 4 + j;
            if (col < Nn) C[(size_t)row * Nn + col] = acc[i][j];
        }
    }
}

// ---------------- host orchestration ----------------

extern "C" void kernel_launch(void* const* d_in, const int* in_sizes, int n_in,
                              void* d_out, int out_size) {
    const float* x = (const float*)d_in[0];
    const int* edges[5];
    for (int i = 0; i < 5; i++) edges[i] = (const int*)d_in[1 + i];
    const float* pb[2][8];
    for (int b = 0; b < 2; b++)
        for (int i = 0; i < 8; i++) pb[b][i] = (const float*)d_in[6 + b * 8 + i];
    const float* w1    = (const float*)d_in[22];
    const float* bias1 = (const float*)d_in[23];
    const float* w2    = (const float*)d_in[24];
    const float* bias2 = (const float*)d_in[25];
    float* out = (float*)d_out;

    float *A_, *p1_, *p2_, *t1_, *att_, *M_, *Mt_, *M0_, *An_, *dinv_, *XW_, *H_, *HW_;
    cudaGetSymbolAddress((void**)&A_,   g_A);
    cudaGetSymbolAddress((void**)&p1_,  g_p1);
    cudaGetSymbolAddress((void**)&p2_,  g_p2);
    cudaGetSymbolAddress((void**)&t1_,  g_t1);
    cudaGetSymbolAddress((void**)&att_, g_att);
    cudaGetSymbolAddress((void**)&M_,   g_M);
    cudaGetSymbolAddress((void**)&Mt_,  g_Mt);
    cudaGetSymbolAddress((void**)&M0_,  g_M0);
    cudaGetSymbolAddress((void**)&An_,  g_An);
    cudaGetSymbolAddress((void**)&dinv_, g_dinv);
    cudaGetSymbolAddress((void**)&XW_,  g_XW);
    cudaGetSymbolAddress((void**)&H_,   g_H);
    cudaGetSymbolAddress((void**)&HW_,  g_HW);

    const size_t PLANE = (size_t)NV * NV;
    dim3 blk16(16, 16);

    for (int path = 0; path < 2; path++) {
        const int L = (path == 0) ? 2 : 3;
        cudaMemsetAsync(A_, 0, (size_t)L * PLANE * sizeof(float), 0);
        for (int i = 0; i < L; i++) {
            const int* ee = (path == 0) ? edges[i] : edges[2 + i];
            scatter_edges<<<(NE + 255) / 256, 256>>>(ee, A_ + (size_t)i * PLANE);
        }
        const float* const* P = pb[path];
        if (L == 2) conv1pool<2><<<dim3(32, 32), blk16>>>(A_, P[0], P[1], p1_);
        else        conv1pool<3><<<dim3(32, 32), blk16>>>(A_, P[0], P[1], p1_);
        conv2pool<<<dim3(17, 17), blk16>>>(p1_, P[2], P[3], p2_);
        tconv1k<<<(514 * 514 + 255) / 256, 256>>>(p2_, P[4], P[5], t1_);
        if (L == 2) tconv2att<2><<<(NV * NV) / 256, 256>>>(t1_, P[6], P[7], A_, att_);
        else        tconv2att<3><<<(NV * NV) / 256, 256>>>(t1_, P[6], P[7], A_, att_);

        // M-chain: M = gcn_norm(att[0]); then M = gcn_norm(M @ att[i])
        row_dinv<<<NV, 256>>>(att_, dinv_);
        gcn_scale<<<(NV * NV) / 256, 256>>>(att_, dinv_, M_);
        for (int i = 1; i < L; i++) {
            sgemm64<<<dim3(NV / 64, NV / 64), blk16>>>(M_, att_ + (size_t)i * PLANE, Mt_, NV, NV, NV);
            row_dinv<<<NV, 256>>>(Mt_, dinv_);
            float* dst = (i == L - 1 && path == 0) ? M0_ : M_;
            gcn_scale<<<(NV * NV) / 256, 256>>>(Mt_, dinv_, dst);
        }
    }

    // A = max(M0, M1); An = gcn_norm(A)
    emax<<<(NV * NV) / 256, 256>>>(M0_, M_, Mt_);
    row_dinv<<<NV, 256>>>(Mt_, dinv_);
    gcn_scale<<<(NV * NV) / 256, 256>>>(Mt_, dinv_, An_);

    // GCN layers
    sgemm64<<<dim3(1, NV / 64), blk16>>>(x, w1, XW_, NV, HIDD, EMBD);     // x @ w1
    sgemm64<<<dim3(1, NV / 64), blk16>>>(An_, XW_, H_, NV, HIDD, NV);     // An @ xw1
    bias_relu64<<<(NV * HIDD + 255) / 256, 256>>>(H_, bias1);
    sgemm64<<<dim3(1, NV / 64), blk16>>>(H_, w2, HW_, NV, REPD, HIDD);    // h @ w2
    sgemm64<<<dim3(1, NV / 64), blk16>>>(An_, HW_, out, NV, REPD, NV);    // An @ hw2
    bias_add32<<<(NV * REPD + 255) / 256, 256>>>(out, bias2);
}

// round 2
// speedup vs baseline: 1.3632x; 1.3632x over previous
#include <cuda_runtime.h>
#include <math.h>
#include <stdint.h>

// Problem constants
#define NV 1024          // num nodes
#define NE 32768         // edges per adjacency
#define EMBD 128
#define HIDD 64
#define REPD 32

// ---------------- scratch (static device globals; no allocation) ----------------
__device__ float g_A[3][NV][NV];        // per-path dense adjacencies (max L=3)
__device__ float g_p1[16][512][512];    // conv1+pool output
__device__ float g_p2[4][257][257];     // conv2+pool output
__device__ float g_t1[16][514][514];    // tconv1 output
__device__ float g_att[3][NV][NV];      // attended adjacencies
__device__ float g_M[NV][NV];
__device__ float g_Mt[NV][NV];
__device__ float g_M0[NV][NV];
__device__ float g_An[NV][NV];
__device__ float g_dinv[NV];
__device__ float g_XW[NV][HIDD];
__device__ float g_H[NV][HIDD];
__device__ float g_HW[NV][REPD];

// ---------------- kernels ----------------

__global__ void scatter_edges(const int* __restrict__ e, float* __restrict__ A) {
    int k = blockIdx.x * blockDim.x + threadIdx.x;
    if (k < NE) {
        int r = e[k];
        int c = e[NE + k];
        atomicAdd(&A[r * NV + c], 1.0f);
    }
}

// conv1 (3x3, pad1, L->16) + relu + maxpool2 fused.  out: p1[16][512][512]
template <int L>
__global__ void conv1pool(const float* __restrict__ A, const float* __restrict__ w,
                          const float* __restrict__ b, float* __restrict__ p1) {
    __shared__ float sw[16 * L * 9];
    __shared__ float sb[16];
    int t = threadIdx.y * 16 + threadIdx.x;
    for (int i = t; i < 16 * L * 9; i += 256) sw[i] = w[i];
    if (t < 16) sb[t] = b[t];
    __syncthreads();
    int x = blockIdx.x * 16 + threadIdx.x;
    int y = blockIdx.y * 16 + threadIdx.y;
    if (x >= 512 || y >= 512) return;

    float patch[L][4][4];
#pragma unroll
    for (int l = 0; l < L; l++)
#pragma unroll
        for (int r = 0; r < 4; r++) {
            int iy = 2 * y - 1 + r;
#pragma unroll
            for (int c = 0; c < 4; c++) {
                int ix = 2 * x - 1 + c;
                patch[l][r][c] = (iy >= 0 && iy < NV && ix >= 0 && ix < NV)
                                     ? A[((size_t)l * NV + iy) * NV + ix] : 0.0f;
            }
        }
#pragma unroll
    for (int oc = 0; oc < 16; oc++) {
        float m = -1e30f;
#pragma unroll
        for (int py = 0; py < 2; py++)
#pragma unroll
            for (int px = 0; px < 2; px++) {
                float s = sb[oc];
#pragma unroll
                for (int l = 0; l < L; l++)
#pragma unroll
                    for (int ky = 0; ky < 3; ky++)
#pragma unroll
                        for (int kx = 0; kx < 3; kx++)
                            s += sw[((oc * L + l) * 3 + ky) * 3 + kx] * patch[l][py + ky][px + kx];
                m = fmaxf(m, fmaxf(s, 0.0f));
            }
        p1[((size_t)oc * 512 + y) * 512 + x] = m;
    }
}

// conv2 (3x3, pad2, 16->4) + relu + maxpool2 fused.  in: p1[16][512][512], out: p2[4][257][257]
__global__ void conv2pool(const float* __restrict__ p1, const float* __restrict__ w,
                          const float* __restrict__ b, float* __restrict__ p2) {
    __shared__ float sw[576];
    __shared__ float sb[4];
    int t = threadIdx.y * 16 + threadIdx.x;
    for (int i = t; i < 576; i += 256) sw[i] = w[i];
    if (t < 4) sb[t] = b[t];
    __syncthreads();
    int x = blockIdx.x * 16 + threadIdx.x;
    int y = blockIdx.y * 16 + threadIdx.y;
    if (x >= 257 || y >= 257) return;

    float acc[4][2][2];
#pragma unroll
    for (int oc = 0; oc < 4; oc++)
#pragma unroll
        for (int py = 0; py < 2; py++)
#pragma unroll
            for (int px = 0; px < 2; px++) acc[oc][py][px] = sb[oc];

    for (int ci = 0; ci < 16; ci++) {
        float patch[4][4];
#pragma unroll
        for (int r = 0; r < 4; r++) {
            int iy = 2 * y - 2 + r;
#pragma unroll
            for (int c = 0; c < 4; c++) {
                int ix = 2 * x - 2 + c;
                patch[r][c] = (iy >= 0 && iy < 512 && ix >= 0 && ix < 512)
                                  ? p1[((size_t)ci * 512 + iy) * 512 + ix] : 0.0f;
            }
        }
#pragma unroll
        for (int oc = 0; oc < 4; oc++)
#pragma unroll
            for (int ky = 0; ky < 3; ky++)
#pragma unroll
                for (int kx = 0; kx < 3; kx++) {
                    float wv = sw[((oc * 16 + ci) * 3 + ky) * 3 + kx];
                    acc[oc][0][0] += wv * patch[ky][kx];
                    acc[oc][0][1] += wv * patch[ky][kx + 1];
                    acc[oc][1][0] += wv * patch[ky + 1][kx];
                    acc[oc][1][1] += wv * patch[ky + 1][kx + 1];
                }
    }
#pragma unroll
    for (int oc = 0; oc < 4; oc++) {
        float m = fmaxf(fmaxf(acc[oc][0][0], acc[oc][0][1]), fmaxf(acc[oc][1][0], acc[oc][1][1]));
        p2[((size_t)oc * 257 + y) * 257 + x] = fmaxf(m, 0.0f);
    }
}

// tconv1 (k2 s2, 4->16) + relu.  in: p2[4][257][257], out: t1[16][514][514]
__global__ void tconv1k(const float* __restrict__ p2, const float* __restrict__ w,
                        const float* __restrict__ b, float* __restrict__ t1) {
    int idx = blockIdx.x * blockDim.x + threadIdx.x;
    if (idx >= 514 * 514) return;
    int ox = idx % 514, oy = idx / 514;
    int ky = (oy + 1) & 1, kx = (ox + 1) & 1;   // single contributing tap (parity)
    int iy = (oy - 1 + ky) >> 1, ix = (ox - 1 + kx) >> 1;
    float v[4];
#pragma unroll
    for (int ci = 0; ci < 4; ci++) v[ci] = p2[((size_t)ci * 257 + iy) * 257 + ix];
#pragma unroll
    for (int co = 0; co < 16; co++) {
        float s = b[co];
#pragma unroll
        for (int ci = 0; ci < 4; ci++) s += w[((co * 4 + ci) * 2 + ky) * 2 + kx] * v[ci];
        t1[((size_t)co * 514 + oy) * 514 + ox] = fmaxf(s, 0.0f);
    }
}

// tconv2 (k2 s2, 16->L) + sigmoid + crop + elementwise multiply by adjacency.
template <int L>
__global__ void tconv2att(const float* __restrict__ t1, const float* __restrict__ w,
                          const float* __restrict__ b, const float* __restrict__ A,
                          float* __restrict__ att) {
    int idx = blockIdx.x * blockDim.x + threadIdx.x;
    if (idx >= NV * NV) return;
    int x = idx % NV, y = idx / NV;
    int ky = (y + 1) & 1, kx = (x + 1) & 1;
    int iy = (y - 1 + ky) >> 1, ix = (x - 1 + kx) >> 1;
    float v[16];
#pragma unroll
    for (int ci = 0; ci < 16; ci++) v[ci] = t1[((size_t)ci * 514 + iy) * 514 + ix];
#pragma unroll
    for (int l = 0; l < L; l++) {
        float s = b[l];
#pragma unroll
        for (int ci = 0; ci < 16; ci++) s += w[((l * 16 + ci) * 2 + ky) * 2 + kx] * v[ci];
        float sg = 1.0f / (1.0f + expf(-s));
        att[(size_t)l * NV * NV + idx] = A[(size_t)l * NV * NV + idx] * sg;
    }
}

// row sums with self-loop fixup -> dinv = rsqrt(deg)
__global__ void row_dinv(const float* __restrict__ A, float* __restrict__ dinv) {
    int row = blockIdx.x;
    const float* r = A + (size_t)row * NV;
    float s = 0.0f;
    for (int j = threadIdx.x; j < NV; j += 256) s += r[j];
    __shared__ float sh[256];
    sh[threadIdx.x] = s;
    __syncthreads();
    for (int o = 128; o > 0; o >>= 1) {
        if (threadIdx.x < o) sh[threadIdx.x] += sh[threadIdx.x + o];
        __syncthreads();
    }
    if (threadIdx.x == 0) {
        float d = sh[0];
        if (r[row] == 0.0f) d += 1.0f;   // add_remaining_self_loops(fill=1)
        dinv[row] = d > 0.0f ? rsqrtf(d) : 0.0f;
    }
}

// out[i][j] = dinv[i] * B[i][j] * dinv[j], B = A with diag fill
__global__ void gcn_scale(const float* __restrict__ A, const float* __restrict__ dinv,
                          float* __restrict__ out) {
    int idx = blockIdx.x * blockDim.x + threadIdx.x;
    if (idx >= NV * NV) return;
    int i = idx / NV, j = idx % NV;
    float v = A[idx];
    if (i == j && v == 0.0f) v = 1.0f;
    out[idx] = dinv[i] * v * dinv[j];
}

__global__ void emax(const float* __restrict__ a, const float* __restrict__ b,
                     float* __restrict__ o) {
    int idx = blockIdx.x * blockDim.x + threadIdx.x;
    if (idx < NV * NV) o[idx] = fmaxf(a[idx], b[idx]);
}

__global__ void bias_relu64(float* __restrict__ H, const float* __restrict__ bias) {
    int idx = blockIdx.x * blockDim.x + threadIdx.x;
    if (idx < NV * HIDD) H[idx] = fmaxf(H[idx] + bias[idx % HIDD], 0.0f);
}

__global__ void bias_add32(float* __restrict__ O, const float* __restrict__ bias) {
    int idx = blockIdx.x * blockDim.x + threadIdx.x;
    if (idx < NV * REPD) O[idx] += bias[idx % REPD];
}

// ---------------- tf32 tensor-core GEMM ----------------
// C(M x Nn) = A(M x K) * B(K x Nn), all row-major fp32, accumulate fp32.
// Requirements: M % 128 == 0, Nn % 64 == 0, K % 16 == 0.
// Block: 256 threads (8 warps, 4x2 m*n layout), tile 128x64x16, double-buffered.

__device__ __forceinline__ uint32_t f2tf(float f) {
    uint32_t r;
    asm("cvt.rna.tf32.f32 %0, %1;" : "=r"(r) : "f"(f));
    return r;
}

__global__ void __launch_bounds__(256) tf32gemm(const float* __restrict__ A,
                                                const float* __restrict__ B,
                                                float* __restrict__ C,
                                                int M, int Nn, int K) {
    __shared__ float As[2][16][136];   // [k][m], stride 136 -> conflict-free frag loads
    __shared__ float Bs[2][16][72];    // [k][n], stride 72

    const int tid = threadIdx.x;
    const int lane = tid & 31;
    const int wid = tid >> 5;
    const int wr = wid & 3;            // warp m index (0..3): rows wr*32 .. +31
    const int wc = wid >> 2;           // warp n index (0..1): cols wc*32 .. +31
    const int m0 = blockIdx.y * 128;
    const int n0 = blockIdx.x * 64;

    float acc[2][4][4];
#pragma unroll
    for (int mi = 0; mi < 2; mi++)
#pragma unroll
        for (int ni = 0; ni < 4; ni++)
#pragma unroll
            for (int r = 0; r < 4; r++) acc[mi][ni][r] = 0.0f;

    // global load slots
    const int ar = tid >> 2;                 // 0..63
    const int ac4 = (tid & 3) << 2;          // 0,4,8,12
    const int bk = tid >> 4;                 // 0..15
    const int bn4 = (tid & 15) << 2;         // 0..60

    float4 av0, av1, bv;
    const int T = K >> 4;

    // prefetch tile 0
    {
        av0 = *(const float4*)&A[(size_t)(m0 + ar) * K + ac4];
        av1 = *(const float4*)&A[(size_t)(m0 + 64 + ar) * K + ac4];
        bv  = *(const float4*)&B[(size_t)bk * Nn + n0 + bn4];
    }
    // store tile 0
    {
        As[0][ac4 + 0][ar] = __uint_as_float(f2tf(av0.x));
        As[0][ac4 + 1][ar] = __uint_as_float(f2tf(av0.y));
        As[0][ac4 + 2][ar] = __uint_as_float(f2tf(av0.z));
        As[0][ac4 + 3][ar] = __uint_as_float(f2tf(av0.w));
        As[0][ac4 + 0][ar + 64] = __uint_as_float(f2tf(av1.x));
        As[0][ac4 + 1][ar + 64] = __uint_as_float(f2tf(av1.y));
        As[0][ac4 + 2][ar + 64] = __uint_as_float(f2tf(av1.z));
        As[0][ac4 + 3][ar + 64] = __uint_as_float(f2tf(av1.w));
        float4 bt;
        bt.x = __uint_as_float(f2tf(bv.x));
        bt.y = __uint_as_float(f2tf(bv.y));
        bt.z = __uint_as_float(f2tf(bv.z));
        bt.w = __uint_as_float(f2tf(bv.w));
        *(float4*)&Bs[0][bk][bn4] = bt;
    }
    __syncthreads();

    for (int t = 0; t < T; t++) {
        int cur = t & 1;
        if (t + 1 < T) {
            int kb = (t + 1) << 4;
            av0 = *(const float4*)&A[(size_t)(m0 + ar) * K + kb + ac4];
            av1 = *(const float4*)&A[(size_t)(m0 + 64 + ar) * K + kb + ac4];
            bv  = *(const float4*)&B[(size_t)(kb + bk) * Nn + n0 + bn4];
        }

#pragma unroll
        for (int ks = 0; ks < 2; ks++) {
            const int k0 = ks * 8;
            uint32_t a[2][4], b[4][2];
            const int kl = k0 + (lane & 3);
            const int rl = lane >> 2;
#pragma unroll
            for (int mi = 0; mi < 2; mi++) {
                int m = wr * 32 + mi * 16 + rl;
                a[mi][0] = __float_as_uint(As[cur][kl][m]);
                a[mi][1] = __float_as_uint(As[cur][kl][m + 8]);
                a[mi][2] = __float_as_uint(As[cur][kl + 4][m]);
                a[mi][3] = __float_as_uint(As[cur][kl + 4][m + 8]);
            }
#pragma unroll
            for (int ni = 0; ni < 4; ni++) {
                int n = wc * 32 + ni * 8 + rl;
                b[ni][0] = __float_as_uint(Bs[cur][kl][n]);
                b[ni][1] = __float_as_uint(Bs[cur][kl + 4][n]);
            }
#pragma unroll
            for (int mi = 0; mi < 2; mi++)
#pragma unroll
                for (int ni = 0; ni < 4; ni++) {
                    asm volatile(
                        "mma.sync.aligned.m16n8k8.row.col.f32.tf32.tf32.f32 "
                        "{%0,%1,%2,%3}, {%4,%5,%6,%7}, {%8,%9}, {%0,%1,%2,%3};"
                        : "+f"(acc[mi][ni][0]), "+f"(acc[mi][ni][1]),
                          "+f"(acc[mi][ni][2]), "+f"(acc[mi][ni][3])
                        : "r"(a[mi][0]), "r"(a[mi][1]), "r"(a[mi][2]), "r"(a[mi][3]),
                          "r"(b[ni][0]), "r"(b[ni][1]));
                }
        }

        if (t + 1 < T) {
            int nxt = (t + 1) & 1;
            As[nxt][ac4 + 0][ar] = __uint_as_float(f2tf(av0.x));
            As[nxt][ac4 + 1][ar] = __uint_as_float(f2tf(av0.y));
            As[nxt][ac4 + 2][ar] = __uint_as_float(f2tf(av0.z));
            As[nxt][ac4 + 3][ar] = __uint_as_float(f2tf(av0.w));
            As[nxt][ac4 + 0][ar + 64] = __uint_as_float(f2tf(av1.x));
            As[nxt][ac4 + 1][ar + 64] = __uint_as_float(f2tf(av1.y));
            As[nxt][ac4 + 2][ar + 64] = __uint_as_float(f2tf(av1.z));
            As[nxt][ac4 + 3][ar + 64] = __uint_as_float(f2tf(av1.w));
            float4 bt;
            bt.x = __uint_as_float(f2tf(bv.x));
            bt.y = __uint_as_float(f2tf(bv.y));
            bt.z = __uint_as_float(f2tf(bv.z));
            bt.w = __uint_as_float(f2tf(bv.w));
            *(float4*)&Bs[nxt][bk][bn4] = bt;
            __syncthreads();
        }
    }

    // epilogue
#pragma unroll
    for (int mi = 0; mi < 2; mi++) {
        int row = m0 + wr * 32 + mi * 16 + (lane >> 2);
#pragma unroll
        for (int ni = 0; ni < 4; ni++) {
            int col = n0 + wc * 32 + ni * 8 + ((lane & 3) << 1);
            float2 v0 = make_float2(acc[mi][ni][0], acc[mi][ni][1]);
            float2 v1 = make_float2(acc[mi][ni][2], acc[mi][ni][3]);
            *(float2*)&C[(size_t)row * Nn + col] = v0;
            *(float2*)&C[(size_t)(row + 8) * Nn + col] = v1;
        }
    }
}

// C(MxNn) = A(MxK, rm) * B(KxNn, rm).  BM=BN=64, BK=16, 16x16 threads, 4x4 microtile.
__global__ void sgemm64(const float* __restrict__ A, const float* __restrict__ B,
                        float* __restrict__ C, int M, int Nn, int K) {
    __shared__ float As[16][64];
    __shared__ float Bs[16][64];
    int tx = threadIdx.x, ty = threadIdx.y;
    int tid = ty * 16 + tx;
    int m0 = blockIdx.y * 64, n0 = blockIdx.x * 64;
    float acc[4][4];
#pragma unroll
    for (int i = 0; i < 4; i++)
#pragma unroll
        for (int j = 0; j < 4; j++) acc[i][j] = 0.0f;

    int la_r = tid / 16, la_k = tid % 16;
    int lb_k = tid / 64, lb_n = tid % 64;

    for (int k0 = 0; k0 < K; k0 += 16) {
#pragma unroll
        for (int r = 0; r < 4; r++)
            As[la_k][la_r + 16 * r] = A[(size_t)(m0 + la_r + 16 * r) * K + k0 + la_k];
#pragma unroll
        for (int r = 0; r < 4; r++) {
            int kk = lb_k + 4 * r;
            Bs[kk][lb_n] = (n0 + lb_n < Nn) ? B[(size_t)(k0 + kk) * Nn + n0 + lb_n] : 0.0f;
        }
        __syncthreads();
#pragma unroll
        for (int k = 0; k < 16; k++) {
            float a[4], b[4];
#pragma unroll
            for (int i = 0; i < 4; i++) a[i] = As[k][ty * 4 + i];
#pragma unroll
            for (int j = 0; j < 4; j++) b[j] = Bs[k][tx * 4 + j];
#pragma unroll
            for (int i = 0; i < 4; i++)
#pragma unroll
                for (int j = 0; j < 4; j++) acc[i][j] += a[i] * b[j];
        }
        __syncthreads();
    }
#pragma unroll
    for (int i = 0; i < 4; i++) {
        int row = m0 + ty * 4 + i;
#pragma unroll
        for (int j = 0; j < 4; j++) {
            int col = n0 + tx * 4 + j;
            if (col < Nn) C[(size_t)row * Nn + col] = acc[i][j];
        }
    }
}

// ---------------- host orchestration ----------------

extern "C" void kernel_launch(void* const* d_in, const int* in_sizes, int n_in,
                              void* d_out, int out_size) {
    const float* x = (const float*)d_in[0];
    const int* edges[5];
    for (int i = 0; i < 5; i++) edges[i] = (const int*)d_in[1 + i];
    const float* pb[2][8];
    for (int b = 0; b < 2; b++)
        for (int i = 0; i < 8; i++) pb[b][i] = (const float*)d_in[6 + b * 8 + i];
    const float* w1    = (const float*)d_in[22];
    const float* bias1 = (const float*)d_in[23];
    const float* w2    = (const float*)d_in[24];
    const float* bias2 = (const float*)d_in[25];
    float* out = (float*)d_out;

    float *A_, *p1_, *p2_, *t1_, *att_, *M_, *Mt_, *M0_, *An_, *dinv_, *XW_, *H_, *HW_;
    cudaGetSymbolAddress((void**)&A_,   g_A);
    cudaGetSymbolAddress((void**)&p1_,  g_p1);
    cudaGetSymbolAddress((void**)&p2_,  g_p2);
    cudaGetSymbolAddress((void**)&t1_,  g_t1);
    cudaGetSymbolAddress((void**)&att_, g_att);
    cudaGetSymbolAddress((void**)&M_,   g_M);
    cudaGetSymbolAddress((void**)&Mt_,  g_Mt);
    cudaGetSymbolAddress((void**)&M0_,  g_M0);
    cudaGetSymbolAddress((void**)&An_,  g_An);
    cudaGetSymbolAddress((void**)&dinv_, g_dinv);
    cudaGetSymbolAddress((void**)&XW_,  g_XW);
    cudaGetSymbolAddress((void**)&H_,   g_H);
    cudaGetSymbolAddress((void**)&HW_,  g_HW);

    const size_t PLANE = (size_t)NV * NV;
    dim3 blk16(16, 16);

    for (int path = 0; path < 2; path++) {
        const int L = (path == 0) ? 2 : 3;
        cudaMemsetAsync(A_, 0, (size_t)L * PLANE * sizeof(float), 0);
        for (int i = 0; i < L; i++) {
            const int* ee = (path == 0) ? edges[i] : edges[2 + i];
            scatter_edges<<<(NE + 255) / 256, 256>>>(ee, A_ + (size_t)i * PLANE);
        }
        const float* const* P = pb[path];
        if (L == 2) conv1pool<2><<<dim3(32, 32), blk16>>>(A_, P[0], P[1], p1_);
        else        conv1pool<3><<<dim3(32, 32), blk16>>>(A_, P[0], P[1], p1_);
        conv2pool<<<dim3(17, 17), blk16>>>(p1_, P[2], P[3], p2_);
        tconv1k<<<(514 * 514 + 255) / 256, 256>>>(p2_, P[4], P[5], t1_);
        if (L == 2) tconv2att<2><<<(NV * NV) / 256, 256>>>(t1_, P[6], P[7], A_, att_);
        else        tconv2att<3><<<(NV * NV) / 256, 256>>>(t1_, P[6], P[7], A_, att_);

        // M-chain: M = gcn_norm(att[0]); then M = gcn_norm(M @ att[i])
        row_dinv<<<NV, 256>>>(att_, dinv_);
        gcn_scale<<<(NV * NV) / 256, 256>>>(att_, dinv_, M_);
        for (int i = 1; i < L; i++) {
            tf32gemm<<<dim3(NV / 64, NV / 128), 256>>>(M_, att_ + (size_t)i * PLANE, Mt_, NV, NV, NV);
            row_dinv<<<NV, 256>>>(Mt_, dinv_);
            float* dst = (i == L - 1 && path == 0) ? M0_ : M_;
            gcn_scale<<<(NV * NV) / 256, 256>>>(Mt_, dinv_, dst);
        }
    }

    // A = max(M0, M1); An = gcn_norm(A)
    emax<<<(NV * NV) / 256, 256>>>(M0_, M_, Mt_);
    row_dinv<<<NV, 256>>>(Mt_, dinv_);
    gcn_scale<<<(NV * NV) / 256, 256>>>(Mt_, dinv_, An_);

    // GCN layers (fp32 for accuracy: mixed-sign operands, cheap anyway)
    sgemm64<<<dim3(1, NV / 64), blk16>>>(x, w1, XW_, NV, HIDD, EMBD);     // x @ w1
    sgemm64<<<dim3(1, NV / 64), blk16>>>(An_, XW_, H_, NV, HIDD, NV);     // An @ xw1
    bias_relu64<<<(NV * HIDD + 255) / 256, 256>>>(H_, bias1);
    sgemm64<<<dim3(1, NV / 64), blk16>>>(H_, w2, HW_, NV, REPD, HIDD);    // h @ w2
    sgemm64<<<dim3(1, NV / 64), blk16>>>(An_, HW_, out, NV, REPD, NV);    // An @ hw2
    bias_add32<<<(NV * REPD + 255) / 256, 256>>>(out, bias2);
}

// round 3
// speedup vs baseline: 1.7653x; 1.2949x over previous
#include <cuda_runtime.h>
#include <math.h>
#include <stdint.h>

// Problem constants
#define NV 1024
#define NE 32768
#define EMBD 128
#define HIDD 64
#define REPD 32

// ---------------- scratch (static device globals) ----------------
__device__ float g_A[2][3][NV][NV];       // per-path dense adjacencies
__device__ float g_p1[2][16][512][512];
__device__ float g_p2[2][4][257][257];
__device__ float g_t1[2][16][514][514];
__device__ float g_att[2][3][NV][NV];
__device__ float g_M[2][NV][NV];
__device__ float g_Mt[2][NV][NV];
__device__ float g_An[NV][NV];
__device__ float g_dinv[2][NV];
__device__ float g_XW[NV][HIDD];
__device__ float g_H[NV][HIDD];
__device__ float g_HW[NV][REPD];

// ---------------- param structs ----------------
struct Sc5 { const int* e[5]; float* A[5]; };
struct PathPtrs {
    const float* in[2]; const float* w[2]; const float* b[2]; float* out[2];
};
struct Att2 {
    const float* t1[2]; const float* w[2]; const float* b[2];
    const float* A[2]; float* att[2];
};
struct RD2 { const float* in[2]; float* dv[2]; };
struct GS2 { const float* in[2]; const float* dv[2]; float* out[2]; };
struct GB2 { const float* A[2]; const float* B[2]; float* C[2]; };

// ---------------- kernels ----------------

__global__ void scatter_all(Sc5 s) {
    int j = blockIdx.y;
    int k = blockIdx.x * blockDim.x + threadIdx.x;
    if (k < NE) {
        const int* e = s.e[j];
        atomicAdd(&s.A[j][e[k] * NV + e[NE + k]], 1.0f);
    }
}

// conv1 (3x3, pad1, L->16) + relu + maxpool2 fused. out: [16][512][512]
template <int L>
__device__ __forceinline__ void conv1_impl(const float* __restrict__ A,
                                           const float* __restrict__ w,
                                           const float* __restrict__ b,
                                           float* __restrict__ p1) {
    __shared__ float sw[16 * 3 * 9];
    __shared__ float sb[16];
    int t = threadIdx.y * 16 + threadIdx.x;
    for (int i = t; i < 16 * L * 9; i += 256) sw[i] = w[i];
    if (t < 16) sb[t] = b[t];
    __syncthreads();
    int x = blockIdx.x * 16 + threadIdx.x;
    int y = blockIdx.y * 16 + threadIdx.y;

    float patch[L][4][4];
#pragma unroll
    for (int l = 0; l < L; l++)
#pragma unroll
        for (int r = 0; r < 4; r++) {
            int iy = 2 * y - 1 + r;
#pragma unroll
            for (int c = 0; c < 4; c++) {
                int ix = 2 * x - 1 + c;
                patch[l][r][c] = (iy >= 0 && iy < NV && ix >= 0 && ix < NV)
                                     ? A[((size_t)l * NV + iy) * NV + ix] : 0.0f;
            }
        }
#pragma unroll
    for (int oc = 0; oc < 16; oc++) {
        float m = -1e30f;
#pragma unroll
        for (int py = 0; py < 2; py++)
#pragma unroll
            for (int px = 0; px < 2; px++) {
                float s = sb[oc];
#pragma unroll
                for (int l = 0; l < L; l++)
#pragma unroll
                    for (int ky = 0; ky < 3; ky++)
#pragma unroll
                        for (int kx = 0; kx < 3; kx++)
                            s += sw[((oc * L + l) * 3 + ky) * 3 + kx] * patch[l][py + ky][px + kx];
                m = fmaxf(m, fmaxf(s, 0.0f));
            }
        p1[((size_t)oc * 512 + y) * 512 + x] = m;
    }
}

__global__ void conv1pool_both(PathPtrs p) {
    int path = blockIdx.z;
    if (path == 0) conv1_impl<2>(p.in[0], p.w[0], p.b[0], p.out[0]);
    else           conv1_impl<3>(p.in[1], p.w[1], p.b[1], p.out[1]);
}

// conv2 (3x3, pad2, 16->4) + relu + maxpool2, ci split across quads.
// block (4,8,8): x=ci-group, y=ox, z=oy. grid (33,33,2).
__global__ void conv2pool_both(PathPtrs pp) {
    int path = blockIdx.z;
    const float* p1 = pp.in[path];
    const float* w = pp.w[path];
    const float* bb = pp.b[path];
    float* p2 = pp.out[path];

    __shared__ float sw[576];
    __shared__ float sb[4];
    int tx = threadIdx.x, ty = threadIdx.y, tz = threadIdx.z;
    int t = (tz * 8 + ty) * 4 + tx;
    for (int i = t; i < 576; i += 256) sw[i] = w[i];
    if (t < 4) sb[t] = bb[t];
    __syncthreads();

    int x = blockIdx.x * 8 + ty;
    int y = blockIdx.y * 8 + tz;

    float acc[4][2][2];
#pragma unroll
    for (int oc = 0; oc < 4; oc++)
#pragma unroll
        for (int py = 0; py < 2; py++)
#pragma unroll
            for (int px = 0; px < 2; px++) acc[oc][py][px] = 0.0f;

#pragma unroll
    for (int cc = 0; cc < 4; cc++) {
        int ci = tx * 4 + cc;
        float patch[4][4];
#pragma unroll
        for (int r = 0; r < 4; r++) {
            int iy = 2 * y - 2 + r;
#pragma unroll
            for (int c = 0; c < 4; c++) {
                int ix = 2 * x - 2 + c;
                patch[r][c] = (iy >= 0 && iy < 512 && ix >= 0 && ix < 512)
                                  ? p1[((size_t)ci * 512 + iy) * 512 + ix] : 0.0f;
            }
        }
#pragma unroll
        for (int oc = 0; oc < 4; oc++)
#pragma unroll
            for (int ky = 0; ky < 3; ky++)
#pragma unroll
                for (int kx = 0; kx < 3; kx++) {
                    float wv = sw[((oc * 16 + ci) * 3 + ky) * 3 + kx];
                    acc[oc][0][0] += wv * patch[ky][kx];
                    acc[oc][0][1] += wv * patch[ky][kx + 1];
                    acc[oc][1][0] += wv * patch[ky + 1][kx];
                    acc[oc][1][1] += wv * patch[ky + 1][kx + 1];
                }
    }
    // reduce across the 4 ci-groups (tx occupies lane bits 0..1)
#pragma unroll
    for (int oc = 0; oc < 4; oc++)
#pragma unroll
        for (int py = 0; py < 2; py++)
#pragma unroll
            for (int px = 0; px < 2; px++) {
                float v = acc[oc][py][px];
                v += __shfl_xor_sync(0xFFFFFFFF, v, 1);
                v += __shfl_xor_sync(0xFFFFFFFF, v, 2);
                acc[oc][py][px] = v;
            }
    if (tx == 0 && x < 257 && y < 257) {
#pragma unroll
        for (int oc = 0; oc < 4; oc++) {
            float m = fmaxf(fmaxf(acc[oc][0][0], acc[oc][0][1]),
                            fmaxf(acc[oc][1][0], acc[oc][1][1])) + sb[oc];
            p2[((size_t)oc * 257 + y) * 257 + x] = fmaxf(m, 0.0f);
        }
    }
}

// tconv1 (k2 s2, 4->16) + relu, both paths in one grid.
__global__ void tconv1_both(PathPtrs pp) {
    int gidx = blockIdx.x * blockDim.x + threadIdx.x;
    const int PL = 514 * 514;
    if (gidx >= 2 * PL) return;
    int path = gidx / PL;
    int idx = gidx - path * PL;
    const float* p2 = pp.in[path];
    const float* w = pp.w[path];
    const float* b = pp.b[path];
    float* t1 = pp.out[path];
    int ox = idx % 514, oy = idx / 514;
    int ky = (oy + 1) & 1, kx = (ox + 1) & 1;
    int iy = (oy - 1 + ky) >> 1, ix = (ox - 1 + kx) >> 1;
    float v[4];
#pragma unroll
    for (int ci = 0; ci < 4; ci++) v[ci] = p2[((size_t)ci * 257 + iy) * 257 + ix];
#pragma unroll
    for (int co = 0; co < 16; co++) {
        float s = b[co];
#pragma unroll
        for (int ci = 0; ci < 4; ci++) s += w[((co * 4 + ci) * 2 + ky) * 2 + kx] * v[ci];
        t1[((size_t)co * 514 + oy) * 514 + ox] = fmaxf(s, 0.0f);
    }
}

// tconv2 (k2 s2, 16->L) + sigmoid + crop + multiply adjacency, both paths.
template <int L>
__device__ __forceinline__ void tconv2_impl(const float* __restrict__ t1,
                                            const float* __restrict__ w,
                                            const float* __restrict__ b,
                                            const float* __restrict__ A,
                                            float* __restrict__ att, int idx) {
    int x = idx % NV, y = idx / NV;
    int ky = (y + 1) & 1, kx = (x + 1) & 1;
    int iy = (y - 1 + ky) >> 1, ix = (x - 1 + kx) >> 1;
    float v[16];
#pragma unroll
    for (int ci = 0; ci < 16; ci++) v[ci] = t1[((size_t)ci * 514 + iy) * 514 + ix];
#pragma unroll
    for (int l = 0; l < L; l++) {
        float s = b[l];
#pragma unroll
        for (int ci = 0; ci < 16; ci++) s += w[((l * 16 + ci) * 2 + ky) * 2 + kx] * v[ci];
        float sg = 1.0f / (1.0f + expf(-s));
        att[(size_t)l * NV * NV + idx] = A[(size_t)l * NV * NV + idx] * sg;
    }
}

__global__ void tconv2att_both(Att2 a) {
    int gidx = blockIdx.x * blockDim.x + threadIdx.x;
    const int PL = NV * NV;
    if (gidx >= 2 * PL) return;
    int path = gidx / PL;
    int idx = gidx - path * PL;
    if (path == 0) tconv2_impl<2>(a.t1[0], a.w[0], a.b[0], a.A[0], a.att[0], idx);
    else           tconv2_impl<3>(a.t1[1], a.w[1], a.b[1], a.A[1], a.att[1], idx);
}

// row sums (self-loop fixup) -> rsqrt.  grid (NV, nplanes)
__global__ void row_dinvN(RD2 rd) {
    int p = blockIdx.y;
    int row = blockIdx.x;
    const float* r = rd.in[p] + (size_t)row * NV;
    float s = 0.0f;
    for (int j = threadIdx.x; j < NV; j += 256) s += r[j];
    __shared__ float sh[256];
    sh[threadIdx.x] = s;
    __syncthreads();
    for (int o = 128; o > 0; o >>= 1) {
        if (threadIdx.x < o) sh[threadIdx.x] += sh[threadIdx.x + o];
        __syncthreads();
    }
    if (threadIdx.x == 0) {
        float d = sh[0];
        if (r[row] == 0.0f) d += 1.0f;
        rd.dv[p][row] = d > 0.0f ? rsqrtf(d) : 0.0f;
    }
}

// out = dinv[i] * (A with diag fill) * dinv[j].  grid (NV*NV/256, nplanes)
__global__ void gcn_scaleN(GS2 gs) {
    int p = blockIdx.y;
    int idx = blockIdx.x * blockDim.x + threadIdx.x;
    int i = idx >> 10, j = idx & 1023;
    float v = gs.in[p][idx];
    if (i == j && v == 0.0f) v = 1.0f;
    gs.out[p][idx] = gs.dv[p][i] * v * gs.dv[p][j];
}

__global__ void emax(const float* __restrict__ a, const float* __restrict__ b,
                     float* __restrict__ o) {
    int idx = blockIdx.x * blockDim.x + threadIdx.x;
    if (idx < NV * NV) o[idx] = fmaxf(a[idx], b[idx]);
}

__global__ void bias_relu64(float* __restrict__ H, const float* __restrict__ bias) {
    int idx = blockIdx.x * blockDim.x + threadIdx.x;
    if (idx < NV * HIDD) H[idx] = fmaxf(H[idx] + bias[idx & (HIDD - 1)], 0.0f);
}

__global__ void bias_add32(float* __restrict__ O, const float* __restrict__ bias) {
    int idx = blockIdx.x * blockDim.x + threadIdx.x;
    if (idx < NV * REPD) O[idx] += bias[idx & (REPD - 1)];
}

// ---------------- tf32 tensor-core GEMM (batched over z) ----------------
__device__ __forceinline__ uint32_t f2tf(float f) {
    uint32_t r;
    asm("cvt.rna.tf32.f32 %0, %1;" : "=r"(r) : "f"(f));
    return r;
}

__global__ void __launch_bounds__(256) tf32gemm_b(GB2 g, int M, int Nn, int K) {
    const float* __restrict__ A = g.A[blockIdx.z];
    const float* __restrict__ B = g.B[blockIdx.z];
    float* __restrict__ C = g.C[blockIdx.z];

    __shared__ float As[2][16][136];
    __shared__ float Bs[2][16][72];

    const int tid = threadIdx.x;
    const int lane = tid & 31;
    const int wid = tid >> 5;
    const int wr = wid & 3;
    const int wc = wid >> 2;
    const int m0 = blockIdx.y * 128;
    const int n0 = blockIdx.x * 64;

    float acc[2][4][4];
#pragma unroll
    for (int mi = 0; mi < 2; mi++)
#pragma unroll
        for (int ni = 0; ni < 4; ni++)
#pragma unroll
            for (int r = 0; r < 4; r++) acc[mi][ni][r] = 0.0f;

    const int ar = tid >> 2;
    const int ac4 = (tid & 3) << 2;
    const int bk = tid >> 4;
    const int bn4 = (tid & 15) << 2;

    float4 av0, av1, bv;
    const int T = K >> 4;

    av0 = *(const float4*)&A[(size_t)(m0 + ar) * K + ac4];
    av1 = *(const float4*)&A[(size_t)(m0 + 64 + ar) * K + ac4];
    bv  = *(const float4*)&B[(size_t)bk * Nn + n0 + bn4];

    As[0][ac4 + 0][ar] = __uint_as_float(f2tf(av0.x));
    As[0][ac4 + 1][ar] = __uint_as_float(f2tf(av0.y));
    As[0][ac4 + 2][ar] = __uint_as_float(f2tf(av0.z));
    As[0][ac4 + 3][ar] = __uint_as_float(f2tf(av0.w));
    As[0][ac4 + 0][ar + 64] = __uint_as_float(f2tf(av1.x));
    As[0][ac4 + 1][ar + 64] = __uint_as_float(f2tf(av1.y));
    As[0][ac4 + 2][ar + 64] = __uint_as_float(f2tf(av1.z));
    As[0][ac4 + 3][ar + 64] = __uint_as_float(f2tf(av1.w));
    {
        float4 bt;
        bt.x = __uint_as_float(f2tf(bv.x));
        bt.y = __uint_as_float(f2tf(bv.y));
        bt.z = __uint_as_float(f2tf(bv.z));
        bt.w = __uint_as_float(f2tf(bv.w));
        *(float4*)&Bs[0][bk][bn4] = bt;
    }
    __syncthreads();

    for (int t = 0; t < T; t++) {
        int cur = t & 1;
        if (t + 1 < T) {
            int kb = (t + 1) << 4;
            av0 = *(const float4*)&A[(size_t)(m0 + ar) * K + kb + ac4];
            av1 = *(const float4*)&A[(size_t)(m0 + 64 + ar) * K + kb + ac4];
            bv  = *(const float4*)&B[(size_t)(kb + bk) * Nn + n0 + bn4];
        }
#pragma unroll
        for (int ks = 0; ks < 2; ks++) {
            const int k0 = ks * 8;
            uint32_t a[2][4], b[4][2];
            const int kl = k0 + (lane & 3);
            const int rl = lane >> 2;
#pragma unroll
            for (int mi = 0; mi < 2; mi++) {
                int m = wr * 32 + mi * 16 + rl;
                a[mi][0] = __float_as_uint(As[cur][kl][m]);
                a[mi][1] = __float_as_uint(As[cur][kl][m + 8]);
                a[mi][2] = __float_as_uint(As[cur][kl + 4][m]);
                a[mi][3] = __float_as_uint(As[cur][kl + 4][m + 8]);
            }
#pragma unroll
            for (int ni = 0; ni < 4; ni++) {
                int n = wc * 32 + ni * 8 + rl;
                b[ni][0] = __float_as_uint(Bs[cur][kl][n]);
                b[ni][1] = __float_as_uint(Bs[cur][kl + 4][n]);
            }
#pragma unroll
            for (int mi = 0; mi < 2; mi++)
#pragma unroll
                for (int ni = 0; ni < 4; ni++) {
                    asm volatile(
                        "mma.sync.aligned.m16n8k8.row.col.f32.tf32.tf32.f32 "
                        "{%0,%1,%2,%3}, {%4,%5,%6,%7}, {%8,%9}, {%0,%1,%2,%3};"
                        : "+f"(acc[mi][ni][0]), "+f"(acc[mi][ni][1]),
                          "+f"(acc[mi][ni][2]), "+f"(acc[mi][ni][3])
                        : "r"(a[mi][0]), "r"(a[mi][1]), "r"(a[mi][2]), "r"(a[mi][3]),
                          "r"(b[ni][0]), "r"(b[ni][1]));
                }
        }
        if (t + 1 < T) {
            int nxt = (t + 1) & 1;
            As[nxt][ac4 + 0][ar] = __uint_as_float(f2tf(av0.x));
            As[nxt][ac4 + 1][ar] = __uint_as_float(f2tf(av0.y));
            As[nxt][ac4 + 2][ar] = __uint_as_float(f2tf(av0.z));
            As[nxt][ac4 + 3][ar] = __uint_as_float(f2tf(av0.w));
            As[nxt][ac4 + 0][ar + 64] = __uint_as_float(f2tf(av1.x));
            As[nxt][ac4 + 1][ar + 64] = __uint_as_float(f2tf(av1.y));
            As[nxt][ac4 + 2][ar + 64] = __uint_as_float(f2tf(av1.z));
            As[nxt][ac4 + 3][ar + 64] = __uint_as_float(f2tf(av1.w));
            float4 bt;
            bt.x = __uint_as_float(f2tf(bv.x));
            bt.y = __uint_as_float(f2tf(bv.y));
            bt.z = __uint_as_float(f2tf(bv.z));
            bt.w = __uint_as_float(f2tf(bv.w));
            *(float4*)&Bs[nxt][bk][bn4] = bt;
            __syncthreads();
        }
    }
#pragma unroll
    for (int mi = 0; mi < 2; mi++) {
        int row = m0 + wr * 32 + mi * 16 + (lane >> 2);
#pragma unroll
        for (int ni = 0; ni < 4; ni++) {
            int col = n0 + wc * 32 + ni * 8 + ((lane & 3) << 1);
            *(float2*)&C[(size_t)row * Nn + col] = make_float2(acc[mi][ni][0], acc[mi][ni][1]);
            *(float2*)&C[(size_t)(row + 8) * Nn + col] = make_float2(acc[mi][ni][2], acc[mi][ni][3]);
        }
    }
}

// plain fp32 64x64 tile GEMM (for tiny x@w1, H@w2)
__global__ void sgemm64(const float* __restrict__ A, const float* __restrict__ B,
                        float* __restrict__ C, int M, int Nn, int K) {
    __shared__ float As[16][64];
    __shared__ float Bs[16][64];
    int tx = threadIdx.x, ty = threadIdx.y;
    int tid = ty * 16 + tx;
    int m0 = blockIdx.y * 64, n0 = blockIdx.x * 64;
    float acc[4][4];
#pragma unroll
    for (int i = 0; i < 4; i++)
#pragma unroll
        for (int j = 0; j < 4; j++) acc[i][j] = 0.0f;
    int la_r = tid / 16, la_k = tid % 16;
    int lb_k = tid / 64, lb_n = tid % 64;
    for (int k0 = 0; k0 < K; k0 += 16) {
#pragma unroll
        for (int r = 0; r < 4; r++)
            As[la_k][la_r + 16 * r] = A[(size_t)(m0 + la_r + 16 * r) * K + k0 + la_k];
#pragma unroll
        for (int r = 0; r < 4; r++) {
            int kk = lb_k + 4 * r;
            Bs[kk][lb_n] = (n0 + lb_n < Nn) ? B[(size_t)(k0 + kk) * Nn + n0 + lb_n] : 0.0f;
        }
        __syncthreads();
#pragma unroll
        for (int k = 0; k < 16; k++) {
            float a[4], b[4];
#pragma unroll
            for (int i = 0; i < 4; i++) a[i] = As[k][ty * 4 + i];
#pragma unroll
            for (int j = 0; j < 4; j++) b[j] = Bs[k][tx * 4 + j];
#pragma unroll
            for (int i = 0; i < 4; i++)
#pragma unroll
                for (int j = 0; j < 4; j++) acc[i][j] += a[i] * b[j];
        }
        __syncthreads();
    }
#pragma unroll
    for (int i = 0; i < 4; i++) {
        int row = m0 + ty * 4 + i;
#pragma unroll
        for (int j = 0; j < 4; j++) {
            int col = n0 + tx * 4 + j;
            if (col < Nn) C[(size_t)row * Nn + col] = acc[i][j];
        }
    }
}

// split-K fp32 GEMM: C(1024 x Nn) += A(1024x1024) @ B(1024xNn) over K-slice.
// grid (KS, M/64); block 16x16; C must be pre-zeroed; atomicAdd epilogue.
__global__ void sgemmKS(const float* __restrict__ A, const float* __restrict__ B,
                        float* __restrict__ C, int Nn, int K, int KS) {
    __shared__ float As[16][64];
    __shared__ float Bs[16][64];
    int tx = threadIdx.x, ty = threadIdx.y;
    int tid = ty * 16 + tx;
    int m0 = blockIdx.y * 64;
    int kLen = K / KS;
    int kStart = blockIdx.x * kLen;
    float acc[4][4];
#pragma unroll
    for (int i = 0; i < 4; i++)
#pragma unroll
        for (int j = 0; j < 4; j++) acc[i][j] = 0.0f;
    int la_r = tid / 16, la_k = tid % 16;
    int lb_k = tid / 64, lb_n = tid % 64;
    for (int k0 = kStart; k0 < kStart + kLen; k0 += 16) {
#pragma unroll
        for (int r = 0; r < 4; r++)
            As[la_k][la_r + 16 * r] = A[(size_t)(m0 + la_r + 16 * r) * K + k0 + la_k];
#pragma unroll
        for (int r = 0; r < 4; r++) {
            int kk = lb_k + 4 * r;
            Bs[kk][lb_n] = (lb_n < Nn) ? B[(size_t)(k0 + kk) * Nn + lb_n] : 0.0f;
        }
        __syncthreads();
#pragma unroll
        for (int k = 0; k < 16; k++) {
            float a[4], b[4];
#pragma unroll
            for (int i = 0; i < 4; i++) a[i] = As[k][ty * 4 + i];
#pragma unroll
            for (int j = 0; j < 4; j++) b[j] = Bs[k][tx * 4 + j];
#pragma unroll
            for (int i = 0; i < 4; i++)
#pragma unroll
                for (int j = 0; j < 4; j++) acc[i][j] += a[i] * b[j];
        }
        __syncthreads();
    }
#pragma unroll
    for (int i = 0; i < 4; i++) {
        int row = m0 + ty * 4 + i;
#pragma unroll
        for (int j = 0; j < 4; j++) {
            int col = tx * 4 + j;
            if (col < Nn) atomicAdd(&C[(size_t)row * Nn + col], acc[i][j]);
        }
    }
}

// ---------------- host orchestration ----------------

extern "C" void kernel_launch(void* const* d_in, const int* in_sizes, int n_in,
                              void* d_out, int out_size) {
    const float* x = (const float*)d_in[0];
    const int* edges[5];
    for (int i = 0; i < 5; i++) edges[i] = (const int*)d_in[1 + i];
    const float* pbp[2][8];
    for (int b = 0; b < 2; b++)
        for (int i = 0; i < 8; i++) pbp[b][i] = (const float*)d_in[6 + b * 8 + i];
    const float* w1    = (const float*)d_in[22];
    const float* bias1 = (const float*)d_in[23];
    const float* w2    = (const float*)d_in[24];
    const float* bias2 = (const float*)d_in[25];
    float* out = (float*)d_out;

    float *A_, *p1_, *p2_, *t1_, *att_, *M_, *Mt_, *An_, *dinv_, *XW_, *H_, *HW_;
    cudaGetSymbolAddress((void**)&A_,    g_A);
    cudaGetSymbolAddress((void**)&p1_,   g_p1);
    cudaGetSymbolAddress((void**)&p2_,   g_p2);
    cudaGetSymbolAddress((void**)&t1_,   g_t1);
    cudaGetSymbolAddress((void**)&att_,  g_att);
    cudaGetSymbolAddress((void**)&M_,    g_M);
    cudaGetSymbolAddress((void**)&Mt_,   g_Mt);
    cudaGetSymbolAddress((void**)&An_,   g_An);
    cudaGetSymbolAddress((void**)&dinv_, g_dinv);
    cudaGetSymbolAddress((void**)&XW_,   g_XW);
    cudaGetSymbolAddress((void**)&H_,    g_H);
    cudaGetSymbolAddress((void**)&HW_,   g_HW);

    const size_t PLANE = (size_t)NV * NV;
    dim3 blk16(16, 16);

    // per-path base pointers
    float* Ab[2]   = { A_,   A_   + 3 * PLANE };
    float* p1b[2]  = { p1_,  p1_  + (size_t)16 * 512 * 512 };
    float* p2b[2]  = { p2_,  p2_  + (size_t)4 * 257 * 257 };
    float* t1b[2]  = { t1_,  t1_  + (size_t)16 * 514 * 514 };
    float* attb[2] = { att_, att_ + 3 * PLANE };
    float* Mb[2]   = { M_,   M_   + PLANE };
    float* Mtb[2]  = { Mt_,  Mt_  + PLANE };
    float* dvb[2]  = { dinv_, dinv_ + NV };

    // -------- independent setup: memsets + tiny x@w1 --------
    cudaMemsetAsync(A_, 0, 6 * PLANE * sizeof(float), 0);
    cudaMemsetAsync(H_, 0, (size_t)NV * HIDD * sizeof(float), 0);
    cudaMemsetAsync(out, 0, (size_t)NV * REPD * sizeof(float), 0);
    sgemm64<<<dim3(1, NV / 64), blk16>>>(x, w1, XW_, NV, HIDD, EMBD);

    // -------- scatter all 5 edge lists (one launch) --------
    Sc5 sc;
    sc.e[0] = edges[0]; sc.A[0] = Ab[0];
    sc.e[1] = edges[1]; sc.A[1] = Ab[0] + PLANE;
    sc.e[2] = edges[2]; sc.A[2] = Ab[1];
    sc.e[3] = edges[3]; sc.A[3] = Ab[1] + PLANE;
    sc.e[4] = edges[4]; sc.A[4] = Ab[1] + 2 * PLANE;
    scatter_all<<<dim3((NE + 255) / 256, 5), 256>>>(sc);

    // -------- conv encoder (both paths batched) --------
    PathPtrs c1 = {{Ab[0], Ab[1]}, {pbp[0][0], pbp[1][0]}, {pbp[0][1], pbp[1][1]}, {p1b[0], p1b[1]}};
    conv1pool_both<<<dim3(32, 32, 2), blk16>>>(c1);

    PathPtrs c2 = {{p1b[0], p1b[1]}, {pbp[0][2], pbp[1][2]}, {pbp[0][3], pbp[1][3]}, {p2b[0], p2b[1]}};
    conv2pool_both<<<dim3(33, 33, 2), dim3(4, 8, 8)>>>(c2);

    PathPtrs t1p = {{p2b[0], p2b[1]}, {pbp[0][4], pbp[1][4]}, {pbp[0][5], pbp[1][5]}, {t1b[0], t1b[1]}};
    tconv1_both<<<(2 * 514 * 514 + 255) / 256, 256>>>(t1p);

    Att2 a2 = {{t1b[0], t1b[1]}, {pbp[0][6], pbp[1][6]}, {pbp[0][7], pbp[1][7]},
               {Ab[0], Ab[1]}, {attb[0], attb[1]}};
    tconv2att_both<<<(2 * NV * NV + 255) / 256, 256>>>(a2);

    // -------- M-chain --------
    // M[p] = gcn_norm(att[p][0])
    {
        RD2 rd = {{attb[0], attb[1]}, {dvb[0], dvb[1]}};
        row_dinvN<<<dim3(NV, 2), 256>>>(rd);
        GS2 gs = {{attb[0], attb[1]}, {dvb[0], dvb[1]}, {Mb[0], Mb[1]}};
        gcn_scaleN<<<dim3(NV * NV / 256, 2), 256>>>(gs);
    }
    // hop 1 (both paths batched): Mt[p] = M[p] @ att[p][1]; M[p] = gcn_norm(Mt[p])
    {
        GB2 gb = {{Mb[0], Mb[1]}, {attb[0] + PLANE, attb[1] + PLANE}, {Mtb[0], Mtb[1]}};
        tf32gemm_b<<<dim3(NV / 64, NV / 128, 2), 256>>>(gb, NV, NV, NV);
        RD2 rd = {{Mtb[0], Mtb[1]}, {dvb[0], dvb[1]}};
        row_dinvN<<<dim3(NV, 2), 256>>>(rd);
        GS2 gs = {{Mtb[0], Mtb[1]}, {dvb[0], dvb[1]}, {Mb[0], Mb[1]}};
        gcn_scaleN<<<dim3(NV * NV / 256, 2), 256>>>(gs);
    }
    // hop 2 (path 1 only): Mt[1] = M[1] @ att[1][2]; M[1] = gcn_norm(Mt[1])
    {
        GB2 gb = {{Mb[1], Mb[1]}, {attb[1] + 2 * PLANE, attb[1] + 2 * PLANE}, {Mtb[1], Mtb[1]}};
        tf32gemm_b<<<dim3(NV / 64, NV / 128, 1), 256>>>(gb, NV, NV, NV);
        RD2 rd = {{Mtb[1], Mtb[1]}, {dvb[1], dvb[1]}};
        row_dinvN<<<dim3(NV, 1), 256>>>(rd);
        GS2 gs = {{Mtb[1], Mtb[1]}, {dvb[1], dvb[1]}, {Mb[1], Mb[1]}};
        gcn_scaleN<<<dim3(NV * NV / 256, 1), 256>>>(gs);
    }

    // -------- merge + final norm --------
    emax<<<(NV * NV) / 256, 256>>>(Mb[0], Mb[1], Mtb[0]);
    {
        RD2 rd = {{Mtb[0], Mtb[0]}, {dvb[0], dvb[0]}};
        row_dinvN<<<dim3(NV, 1), 256>>>(rd);
        GS2 gs = {{Mtb[0], Mtb[0]}, {dvb[0], dvb[0]}, {An_, An_}};
        gcn_scaleN<<<dim3(NV * NV / 256, 1), 256>>>(gs);
    }

    // -------- GCN layers --------
    sgemmKS<<<dim3(8, NV / 64), blk16>>>(An_, XW_, H_, HIDD, NV, 8);   // H += An @ XW
    bias_relu64<<<(NV * HIDD + 255) / 256, 256>>>(H_, bias1);
    sgemm64<<<dim3(1, NV / 64), blk16>>>(H_, w2, HW_, NV, REPD, HIDD); // HW = H @ w2
    sgemmKS<<<dim3(8, NV / 64), blk16>>>(An_, HW_, out, REPD, NV, 8);  // out += An @ HW
    bias_add32<<<(NV * REPD + 255) / 256, 256>>>(out, bias2);
}

// round 4
// speedup vs baseline: 1.7755x; 1.0057x over previous
#include <cuda_runtime.h>
#include <math.h>
#include <stdint.h>

// Problem constants
#define NV 1024
#define NE 32768
#define EMBD 128
#define HIDD 64
#define REPD 32

// ---------------- scratch (static device globals) ----------------
__device__ float g_A[2][3][NV][NV];
__device__ float g_p1[2][16][512][512];
__device__ float g_p2[2][4][257][257];
__device__ float g_t1[2][16][514][514];
__device__ float g_att[2][3][NV][NV];
__device__ float g_M[2][NV][NV];
__device__ float g_Mt[2][NV][NV];
__device__ float g_An[NV][NV];
__device__ float g_dinv[2][NV];
__device__ float g_XW[NV][HIDD];
__device__ float g_H[NV][HIDD];
__device__ float g_HW[NV][REPD];

// ---------------- param structs ----------------
struct Sc5 { const int* e[5]; float* A[5]; };
struct PathPtrs {
    const float* in[2]; const float* w[2]; const float* b[2]; float* out[2];
};
struct Att2 {
    const float* t1[2]; const float* w[2]; const float* b[2];
    const float* A[2]; float* att[2];
};
struct RD2 { const float* in[2]; float* dv[2]; };
struct GS2 { const float* in[2]; const float* dv[2]; float* out[2]; };
struct GB2 { const float* A[2]; const float* B[2]; float* C[2]; };

// ---------------- kernels ----------------

__global__ void scatter_all(Sc5 s) {
    int j = blockIdx.y;
    int k = blockIdx.x * blockDim.x + threadIdx.x;
    if (k < NE) {
        const int* e = s.e[j];
        atomicAdd(&s.A[j][e[k] * NV + e[NE + k]], 1.0f);
    }
}

// ---- conv1 (3x3, pad1, L->16) + relu + maxpool2, smem-tiled ----
// block 16x16 computes 16x16 pooled outputs (= 32x32 conv region, 34x34 input tile / ch)
template <int L>
__device__ __forceinline__ void conv1_compute(const float* __restrict__ tile,
                                              const float* __restrict__ sw,
                                              const float* __restrict__ sb,
                                              float* __restrict__ p1,
                                              int tx, int ty, int ox, int oy) {
    // per-thread input patch from smem: rows 2ty..2ty+3, cols 2tx..2tx+3 per channel
    float patch[L][4][4];
#pragma unroll
    for (int l = 0; l < L; l++)
#pragma unroll
        for (int r = 0; r < 4; r++)
#pragma unroll
            for (int c = 0; c < 4; c++)
                patch[l][r][c] = tile[(l * 34 + 2 * ty + r) * 36 + 2 * tx + c];
#pragma unroll
    for (int oc = 0; oc < 16; oc++) {
        float m = -1e30f;
#pragma unroll
        for (int py = 0; py < 2; py++)
#pragma unroll
            for (int px = 0; px < 2; px++) {
                float s = sb[oc];
#pragma unroll
                for (int l = 0; l < L; l++)
#pragma unroll
                    for (int ky = 0; ky < 3; ky++)
#pragma unroll
                        for (int kx = 0; kx < 3; kx++)
                            s += sw[((oc * L + l) * 3 + ky) * 3 + kx] * patch[l][py + ky][px + kx];
                m = fmaxf(m, fmaxf(s, 0.0f));
            }
        p1[((size_t)oc * 512 + oy) * 512 + ox] = m;
    }
}

__global__ void conv1pool_both(PathPtrs p) {
    __shared__ float tile[3 * 34 * 36];
    __shared__ float sw[16 * 3 * 9];
    __shared__ float sb[16];
    int path = blockIdx.z;
    const int L = (path == 0) ? 2 : 3;
    const float* A = p.in[path];
    const float* w = p.w[path];
    int tx = threadIdx.x, ty = threadIdx.y;
    int t = ty * 16 + tx;
    for (int i = t; i < 16 * L * 9; i += 256) sw[i] = w[i];
    if (t < 16) sb[t] = p.b[path][t];

    int gy0 = blockIdx.y * 32 - 1, gx0 = blockIdx.x * 32 - 1;
    for (int l = 0; l < L; l++)
        for (int i = t; i < 34 * 34; i += 256) {
            int r = i / 34, c = i % 34;
            int gy = gy0 + r, gx = gx0 + c;
            tile[(l * 34 + r) * 36 + c] = (gy >= 0 && gy < NV && gx >= 0 && gx < NV)
                                              ? A[((size_t)l * NV + gy) * NV + gx] : 0.0f;
        }
    __syncthreads();
    int ox = blockIdx.x * 16 + tx, oy = blockIdx.y * 16 + ty;
    if (path == 0) conv1_compute<2>(tile, sw, sb, p.out[0], tx, ty, ox, oy);
    else           conv1_compute<3>(tile, sw, sb, p.out[1], tx, ty, ox, oy);
}

// ---- conv2 (3x3, pad2, 16->4) + relu + maxpool2, smem-tiled per-channel ----
// block 16x16 -> 16x16 outputs; loop over 16 input channels staging 36x36 tiles.
__global__ void conv2pool_both(PathPtrs pp) {
    __shared__ float tile[36 * 38];
    __shared__ float sw[576];
    __shared__ float sb[4];
    int path = blockIdx.z;
    const float* p1 = pp.in[path];
    float* p2 = pp.out[path];
    int tx = threadIdx.x, ty = threadIdx.y;
    int t = ty * 16 + tx;
    for (int i = t; i < 576; i += 256) sw[i] = pp.w[path][i];
    if (t < 4) sb[t] = pp.b[path][t];

    int gy0 = blockIdx.y * 32 - 2, gx0 = blockIdx.x * 32 - 2;
    float acc[4][2][2];
#pragma unroll
    for (int oc = 0; oc < 4; oc++)
#pragma unroll
        for (int py = 0; py < 2; py++)
#pragma unroll
            for (int px = 0; px < 2; px++) acc[oc][py][px] = 0.0f;

    for (int ci = 0; ci < 16; ci++) {
        __syncthreads();
        for (int i = t; i < 36 * 36; i += 256) {
            int r = i / 36, c = i % 36;
            int gy = gy0 + r, gx = gx0 + c;
            tile[r * 38 + c] = (gy >= 0 && gy < 512 && gx >= 0 && gx < 512)
                                   ? p1[((size_t)ci * 512 + gy) * 512 + gx] : 0.0f;
        }
        __syncthreads();
        float patch[4][4];
#pragma unroll
        for (int r = 0; r < 4; r++)
#pragma unroll
            for (int c = 0; c < 4; c++)
                patch[r][c] = tile[(2 * ty + r) * 38 + 2 * tx + c];
#pragma unroll
        for (int oc = 0; oc < 4; oc++)
#pragma unroll
            for (int ky = 0; ky < 3; ky++)
#pragma unroll
                for (int kx = 0; kx < 3; kx++) {
                    float wv = sw[((oc * 16 + ci) * 3 + ky) * 3 + kx];
                    acc[oc][0][0] += wv * patch[ky][kx];
                    acc[oc][0][1] += wv * patch[ky][kx + 1];
                    acc[oc][1][0] += wv * patch[ky + 1][kx];
                    acc[oc][1][1] += wv * patch[ky + 1][kx + 1];
                }
    }
    int x = blockIdx.x * 16 + tx, y = blockIdx.y * 16 + ty;
    if (x < 257 && y < 257) {
#pragma unroll
        for (int oc = 0; oc < 4; oc++) {
            float m = fmaxf(fmaxf(acc[oc][0][0], acc[oc][0][1]),
                            fmaxf(acc[oc][1][0], acc[oc][1][1])) + sb[oc];
            p2[((size_t)oc * 257 + y) * 257 + x] = fmaxf(m, 0.0f);
        }
    }
}

// ---- tconv1 (k2 s2, 4->16) + relu, x-parity pairs: outputs (2m, 2m+1) share input col m ----
__global__ void tconv1_both(PathPtrs pp) {
    int gidx = blockIdx.x * blockDim.x + threadIdx.x;
    const int PL = 514 * 257;
    if (gidx >= 2 * PL) return;
    int path = gidx / PL;
    int idx = gidx - path * PL;
    const float* p2 = pp.in[path];
    const float* w = pp.w[path];
    const float* b = pp.b[path];
    float* t1 = pp.out[path];
    int m = idx % 257, oy = idx / 257;
    int ky = (oy + 1) & 1;
    int iy = (oy - 1 + ky) >> 1;
    float v[4];
#pragma unroll
    for (int ci = 0; ci < 4; ci++) v[ci] = p2[((size_t)ci * 257 + iy) * 257 + m];
#pragma unroll
    for (int co = 0; co < 16; co++) {
        float s0 = b[co], s1 = b[co];   // s0: x=2m (kx=1), s1: x=2m+1 (kx=0)
#pragma unroll
        for (int ci = 0; ci < 4; ci++) {
            s0 += w[((co * 4 + ci) * 2 + ky) * 2 + 1] * v[ci];
            s1 += w[((co * 4 + ci) * 2 + ky) * 2 + 0] * v[ci];
        }
        *(float2*)&t1[((size_t)co * 514 + oy) * 514 + 2 * m] =
            make_float2(fmaxf(s0, 0.0f), fmaxf(s1, 0.0f));
    }
}

// ---- tconv2 (k2 s2, 16->L) + sigmoid + crop + multiply adjacency, x-parity pairs ----
template <int L>
__device__ __forceinline__ void tconv2_impl(const float* __restrict__ t1,
                                            const float* __restrict__ w,
                                            const float* __restrict__ b,
                                            const float* __restrict__ A,
                                            float* __restrict__ att, int idx) {
    int m = idx & 511, y = idx >> 9;
    int ky = (y + 1) & 1;
    int iy = (y - 1 + ky) >> 1;
    float v[16];
#pragma unroll
    for (int ci = 0; ci < 16; ci++) v[ci] = t1[((size_t)ci * 514 + iy) * 514 + m];
#pragma unroll
    for (int l = 0; l < L; l++) {
        float s0 = b[l], s1 = b[l];
#pragma unroll
        for (int ci = 0; ci < 16; ci++) {
            s0 += w[((l * 16 + ci) * 2 + ky) * 2 + 1] * v[ci];
            s1 += w[((l * 16 + ci) * 2 + ky) * 2 + 0] * v[ci];
        }
        float g0 = 1.0f / (1.0f + expf(-s0));
        float g1 = 1.0f / (1.0f + expf(-s1));
        size_t off = (size_t)l * NV * NV + (size_t)y * NV + 2 * m;
        float2 a = *(const float2*)&A[off];
        *(float2*)&att[off] = make_float2(a.x * g0, a.y * g1);
    }
}

__global__ void tconv2att_both(Att2 a) {
    int gidx = blockIdx.x * blockDim.x + threadIdx.x;
    const int PL = NV * 512;
    int path = gidx / PL;
    int idx = gidx - path * PL;
    if (path == 0) tconv2_impl<2>(a.t1[0], a.w[0], a.b[0], a.A[0], a.att[0], idx);
    else           tconv2_impl<3>(a.t1[1], a.w[1], a.b[1], a.A[1], a.att[1], idx);
}

// ---- row sums (self-loop fixup) -> rsqrt.  grid (NV, nplanes) ----
__global__ void row_dinvN(RD2 rd) {
    int p = blockIdx.y;
    int row = blockIdx.x;
    const float* r = rd.in[p] + (size_t)row * NV;
    float s = 0.0f;
    for (int j = threadIdx.x; j < NV; j += 256) s += r[j];
    __shared__ float sh[256];
    sh[threadIdx.x] = s;
    __syncthreads();
    for (int o = 128; o > 0; o >>= 1) {
        if (threadIdx.x < o) sh[threadIdx.x] += sh[threadIdx.x + o];
        __syncthreads();
    }
    if (threadIdx.x == 0) {
        float d = sh[0];
        if (r[row] == 0.0f) d += 1.0f;
        rd.dv[p][row] = d > 0.0f ? rsqrtf(d) : 0.0f;
    }
}

// ---- fused max-merge + row-sum/dinv: o = max(a,b) rowwise, dv = rsqrt(deg) ----
__global__ void emax_dinv(const float* __restrict__ a, const float* __restrict__ b,
                          float* __restrict__ o, float* __restrict__ dv) {
    int row = blockIdx.x;
    __shared__ float sh[256];
    __shared__ float sdiag;
    float s = 0.0f;
    for (int j = threadIdx.x; j < NV; j += 256) {
        float v = fmaxf(a[(size_t)row * NV + j], b[(size_t)row * NV + j]);
        o[(size_t)row * NV + j] = v;
        if (j == row) sdiag = v;
        s += v;
    }
    sh[threadIdx.x] = s;
    __syncthreads();
    for (int off = 128; off > 0; off >>= 1) {
        if (threadIdx.x < off) sh[threadIdx.x] += sh[threadIdx.x + off];
        __syncthreads();
    }
    if (threadIdx.x == 0) {
        float d = sh[0];
        if (sdiag == 0.0f) d += 1.0f;
        dv[row] = d > 0.0f ? rsqrtf(d) : 0.0f;
    }
}

// ---- out = dinv[i] * (A with diag fill) * dinv[j], float4. grid (NV*NV/1024, nplanes) ----
__global__ void gcn_scale4(GS2 gs) {
    int p = blockIdx.y;
    int idx4 = blockIdx.x * blockDim.x + threadIdx.x;   // float4 index
    int i = idx4 >> 8;              // 256 float4 per row
    int j0 = (idx4 & 255) << 2;
    float4 v = *(const float4*)&gs.in[p][((size_t)i << 10) + j0];
    if (j0 <= i && i < j0 + 4) {
        float* vv = &v.x;
        if (vv[i - j0] == 0.0f) vv[i - j0] = 1.0f;
    }
    float di = gs.dv[p][i];
    float4 dj = *(const float4*)&gs.dv[p][j0];
    v.x *= di * dj.x; v.y *= di * dj.y; v.z *= di * dj.z; v.w *= di * dj.w;
    *(float4*)&gs.out[p][((size_t)i << 10) + j0] = v;
}

__global__ void bias_relu64(float* __restrict__ H, const float* __restrict__ bias) {
    int idx = blockIdx.x * blockDim.x + threadIdx.x;
    if (idx < NV * HIDD) H[idx] = fmaxf(H[idx] + bias[idx & (HIDD - 1)], 0.0f);
}

__global__ void bias_add32(float* __restrict__ O, const float* __restrict__ bias) {
    int idx = blockIdx.x * blockDim.x + threadIdx.x;
    if (idx < NV * REPD) O[idx] += bias[idx & (REPD - 1)];
}

// ---------------- tf32 tensor-core GEMM (batched over z) ----------------
__device__ __forceinline__ uint32_t f2tf(float f) {
    uint32_t r;
    asm("cvt.rna.tf32.f32 %0, %1;" : "=r"(r) : "f"(f));
    return r;
}

__global__ void __launch_bounds__(256) tf32gemm_b(GB2 g, int M, int Nn, int K) {
    const float* __restrict__ A = g.A[blockIdx.z];
    const float* __restrict__ B = g.B[blockIdx.z];
    float* __restrict__ C = g.C[blockIdx.z];

    __shared__ float As[2][16][136];
    __shared__ float Bs[2][16][72];

    const int tid = threadIdx.x;
    const int lane = tid & 31;
    const int wid = tid >> 5;
    const int wr = wid & 3;
    const int wc = wid >> 2;
    const int m0 = blockIdx.y * 128;
    const int n0 = blockIdx.x * 64;

    float acc[2][4][4];
#pragma unroll
    for (int mi = 0; mi < 2; mi++)
#pragma unroll
        for (int ni = 0; ni < 4; ni++)
#pragma unroll
            for (int r = 0; r < 4; r++) acc[mi][ni][r] = 0.0f;

    const int ar = tid >> 2;
    const int ac4 = (tid & 3) << 2;
    const int bk = tid >> 4;
    const int bn4 = (tid & 15) << 2;

    float4 av0, av1, bv;
    const int T = K >> 4;

    av0 = *(const float4*)&A[(size_t)(m0 + ar) * K + ac4];
    av1 = *(const float4*)&A[(size_t)(m0 + 64 + ar) * K + ac4];
    bv  = *(const float4*)&B[(size_t)bk * Nn + n0 + bn4];

    As[0][ac4 + 0][ar] = __uint_as_float(f2tf(av0.x));
    As[0][ac4 + 1][ar] = __uint_as_float(f2tf(av0.y));
    As[0][ac4 + 2][ar] = __uint_as_float(f2tf(av0.z));
    As[0][ac4 + 3][ar] = __uint_as_float(f2tf(av0.w));
    As[0][ac4 + 0][ar + 64] = __uint_as_float(f2tf(av1.x));
    As[0][ac4 + 1][ar + 64] = __uint_as_float(f2tf(av1.y));
    As[0][ac4 + 2][ar + 64] = __uint_as_float(f2tf(av1.z));
    As[0][ac4 + 3][ar + 64] = __uint_as_float(f2tf(av1.w));
    {
        float4 bt;
        bt.x = __uint_as_float(f2tf(bv.x));
        bt.y = __uint_as_float(f2tf(bv.y));
        bt.z = __uint_as_float(f2tf(bv.z));
        bt.w = __uint_as_float(f2tf(bv.w));
        *(float4*)&Bs[0][bk][bn4] = bt;
    }
    __syncthreads();

    for (int t = 0; t < T; t++) {
        int cur = t & 1;
        if (t + 1 < T) {
            int kb = (t + 1) << 4;
            av0 = *(const float4*)&A[(size_t)(m0 + ar) * K + kb + ac4];
            av1 = *(const float4*)&A[(size_t)(m0 + 64 + ar) * K + kb + ac4];
            bv  = *(const float4*)&B[(size_t)(kb + bk) * Nn + n0 + bn4];
        }
#pragma unroll
        for (int ks = 0; ks < 2; ks++) {
            const int k0 = ks * 8;
            uint32_t a[2][4], b[4][2];
            const int kl = k0 + (lane & 3);
            const int rl = lane >> 2;
#pragma unroll
            for (int mi = 0; mi < 2; mi++) {
                int m = wr * 32 + mi * 16 + rl;
                a[mi][0] = __float_as_uint(As[cur][kl][m]);
                a[mi][1] = __float_as_uint(As[cur][kl][m + 8]);
                a[mi][2] = __float_as_uint(As[cur][kl + 4][m]);
                a[mi][3] = __float_as_uint(As[cur][kl + 4][m + 8]);
            }
#pragma unroll
            for (int ni = 0; ni < 4; ni++) {
                int n = wc * 32 + ni * 8 + rl;
                b[ni][0] = __float_as_uint(Bs[cur][kl][n]);
                b[ni][1] = __float_as_uint(Bs[cur][kl + 4][n]);
            }
#pragma unroll
            for (int mi = 0; mi < 2; mi++)
#pragma unroll
                for (int ni = 0; ni < 4; ni++) {
                    asm volatile(
                        "mma.sync.aligned.m16n8k8.row.col.f32.tf32.tf32.f32 "
                        "{%0,%1,%2,%3}, {%4,%5,%6,%7}, {%8,%9}, {%0,%1,%2,%3};"
                        : "+f"(acc[mi][ni][0]), "+f"(acc[mi][ni][1]),
                          "+f"(acc[mi][ni][2]), "+f"(acc[mi][ni][3])
                        : "r"(a[mi][0]), "r"(a[mi][1]), "r"(a[mi][2]), "r"(a[mi][3]),
                          "r"(b[ni][0]), "r"(b[ni][1]));
                }
        }
        if (t + 1 < T) {
            int nxt = (t + 1) & 1;
            As[nxt][ac4 + 0][ar] = __uint_as_float(f2tf(av0.x));
            As[nxt][ac4 + 1][ar] = __uint_as_float(f2tf(av0.y));
            As[nxt][ac4 + 2][ar] = __uint_as_float(f2tf(av0.z));
            As[nxt][ac4 + 3][ar] = __uint_as_float(f2tf(av0.w));
            As[nxt][ac4 + 0][ar + 64] = __uint_as_float(f2tf(av1.x));
            As[nxt][ac4 + 1][ar + 64] = __uint_as_float(f2tf(av1.y));
            As[nxt][ac4 + 2][ar + 64] = __uint_as_float(f2tf(av1.z));
            As[nxt][ac4 + 3][ar + 64] = __uint_as_float(f2tf(av1.w));
            float4 bt;
            bt.x = __uint_as_float(f2tf(bv.x));
            bt.y = __uint_as_float(f2tf(bv.y));
            bt.z = __uint_as_float(f2tf(bv.z));
            bt.w = __uint_as_float(f2tf(bv.w));
            *(float4*)&Bs[nxt][bk][bn4] = bt;
            __syncthreads();
        }
    }
#pragma unroll
    for (int mi = 0; mi < 2; mi++) {
        int row = m0 + wr * 32 + mi * 16 + (lane >> 2);
#pragma unroll
        for (int ni = 0; ni < 4; ni++) {
            int col = n0 + wc * 32 + ni * 8 + ((lane & 3) << 1);
            *(float2*)&C[(size_t)row * Nn + col] = make_float2(acc[mi][ni][0], acc[mi][ni][1]);
            *(float2*)&C[(size_t)(row + 8) * Nn + col] = make_float2(acc[mi][ni][2], acc[mi][ni][3]);
        }
    }
}

// plain fp32 64x64 tile GEMM (for tiny x@w1, H@w2)
__global__ void sgemm64(const float* __restrict__ A, const float* __restrict__ B,
                        float* __restrict__ C, int M, int Nn, int K) {
    __shared__ float As[16][64];
    __shared__ float Bs[16][64];
    int tx = threadIdx.x, ty = threadIdx.y;
    int tid = ty * 16 + tx;
    int m0 = blockIdx.y * 64, n0 = blockIdx.x * 64;
    float acc[4][4];
#pragma unroll
    for (int i = 0; i < 4; i++)
#pragma unroll
        for (int j = 0; j < 4; j++) acc[i][j] = 0.0f;
    int la_r = tid / 16, la_k = tid % 16;
    int lb_k = tid / 64, lb_n = tid % 64;
    for (int k0 = 0; k0 < K; k0 += 16) {
#pragma unroll
        for (int r = 0; r < 4; r++)
            As[la_k][la_r + 16 * r] = A[(size_t)(m0 + la_r + 16 * r) * K + k0 + la_k];
#pragma unroll
        for (int r = 0; r < 4; r++) {
            int kk = lb_k + 4 * r;
            Bs[kk][lb_n] = (n0 + lb_n < Nn) ? B[(size_t)(k0 + kk) * Nn + n0 + lb_n] : 0.0f;
        }
        __syncthreads();
#pragma unroll
        for (int k = 0; k < 16; k++) {
            float a[4], b[4];
#pragma unroll
            for (int i = 0; i < 4; i++) a[i] = As[k][ty * 4 + i];
#pragma unroll
            for (int j = 0; j < 4; j++) b[j] = Bs[k][tx * 4 + j];
#pragma unroll
            for (int i = 0; i < 4; i++)
#pragma unroll
                for (int j = 0; j < 4; j++) acc[i][j] += a[i] * b[j];
        }
        __syncthreads();
    }
#pragma unroll
    for (int i = 0; i < 4; i++) {
        int row = m0 + ty * 4 + i;
#pragma unroll
        for (int j = 0; j < 4; j++) {
            int col = n0 + tx * 4 + j;
            if (col < Nn) C[(size_t)row * Nn + col] = acc[i][j];
        }
    }
}

// split-K fp32 GEMM: C(1024 x Nn) += A(1024x1024) @ B(1024xNn) over K-slice.
__global__ void sgemmKS(const float* __restrict__ A, const float* __restrict__ B,
                        float* __restrict__ C, int Nn, int K, int KS) {
    __shared__ float As[16][64];
    __shared__ float Bs[16][64];
    int tx = threadIdx.x, ty = threadIdx.y;
    int tid = ty * 16 + tx;
    int m0 = blockIdx.y * 64;
    int kLen = K / KS;
    int kStart = blockIdx.x * kLen;
    float acc[4][4];
#pragma unroll
    for (int i = 0; i < 4; i++)
#pragma unroll
        for (int j = 0; j < 4; j++) acc[i][j] = 0.0f;
    int la_r = tid / 16, la_k = tid % 16;
    int lb_k = tid / 64, lb_n = tid % 64;
    for (int k0 = kStart; k0 < kStart + kLen; k0 += 16) {
#pragma unroll
        for (int r = 0; r < 4; r++)
            As[la_k][la_r + 16 * r] = A[(size_t)(m0 + la_r + 16 * r) * K + k0 + la_k];
#pragma unroll
        for (int r = 0; r < 4; r++) {
            int kk = lb_k + 4 * r;
            Bs[kk][lb_n] = (lb_n < Nn) ? B[(size_t)(k0 + kk) * Nn + lb_n] : 0.0f;
        }
        __syncthreads();
#pragma unroll
        for (int k = 0; k < 16; k++) {
            float a[4], b[4];
#pragma unroll
            for (int i = 0; i < 4; i++) a[i] = As[k][ty * 4 + i];
#pragma unroll
            for (int j = 0; j < 4; j++) b[j] = Bs[k][tx * 4 + j];
#pragma unroll
            for (int i = 0; i < 4; i++)
#pragma unroll
                for (int j = 0; j < 4; j++) acc[i][j] += a[i] * b[j];
        }
        __syncthreads();
    }
#pragma unroll
    for (int i = 0; i < 4; i++) {
        int row = m0 + ty * 4 + i;
#pragma unroll
        for (int j = 0; j < 4; j++) {
            int col = tx * 4 + j;
            if (col < Nn) atomicAdd(&C[(size_t)row * Nn + col], acc[i][j]);
        }
    }
}

// ---------------- host orchestration ----------------

extern "C" void kernel_launch(void* const* d_in, const int* in_sizes, int n_in,
                              void* d_out, int out_size) {
    const float* x = (const float*)d_in[0];
    const int* edges[5];
    for (int i = 0; i < 5; i++) edges[i] = (const int*)d_in[1 + i];
    const float* pbp[2][8];
    for (int b = 0; b < 2; b++)
        for (int i = 0; i < 8; i++) pbp[b][i] = (const float*)d_in[6 + b * 8 + i];
    const float* w1    = (const float*)d_in[22];
    const float* bias1 = (const float*)d_in[23];
    const float* w2    = (const float*)d_in[24];
    const float* bias2 = (const float*)d_in[25];
    float* out = (float*)d_out;

    float *A_, *p1_, *p2_, *t1_, *att_, *M_, *Mt_, *An_, *dinv_, *XW_, *H_, *HW_;
    cudaGetSymbolAddress((void**)&A_,    g_A);
    cudaGetSymbolAddress((void**)&p1_,   g_p1);
    cudaGetSymbolAddress((void**)&p2_,   g_p2);
    cudaGetSymbolAddress((void**)&t1_,   g_t1);
    cudaGetSymbolAddress((void**)&att_,  g_att);
    cudaGetSymbolAddress((void**)&M_,    g_M);
    cudaGetSymbolAddress((void**)&Mt_,   g_Mt);
    cudaGetSymbolAddress((void**)&An_,   g_An);
    cudaGetSymbolAddress((void**)&dinv_, g_dinv);
    cudaGetSymbolAddress((void**)&XW_,   g_XW);
    cudaGetSymbolAddress((void**)&H_,    g_H);
    cudaGetSymbolAddress((void**)&HW_,   g_HW);

    const size_t PLANE = (size_t)NV * NV;
    dim3 blk16(16, 16);

    float* Ab[2]   = { A_,   A_   + 3 * PLANE };
    float* p1b[2]  = { p1_,  p1_  + (size_t)16 * 512 * 512 };
    float* p2b[2]  = { p2_,  p2_  + (size_t)4 * 257 * 257 };
    float* t1b[2]  = { t1_,  t1_  + (size_t)16 * 514 * 514 };
    float* attb[2] = { att_, att_ + 3 * PLANE };
    float* Mb[2]   = { M_,   M_   + PLANE };
    float* Mtb[2]  = { Mt_,  Mt_  + PLANE };
    float* dvb[2]  = { dinv_, dinv_ + NV };

    // -------- independent setup --------
    cudaMemsetAsync(A_, 0, 6 * PLANE * sizeof(float), 0);
    cudaMemsetAsync(H_, 0, (size_t)NV * HIDD * sizeof(float), 0);
    cudaMemsetAsync(out, 0, (size_t)NV * REPD * sizeof(float), 0);
    sgemm64<<<dim3(1, NV / 64), blk16>>>(x, w1, XW_, NV, HIDD, EMBD);

    // -------- scatter all 5 edge lists --------
    Sc5 sc;
    sc.e[0] = edges[0]; sc.A[0] = Ab[0];
    sc.e[1] = edges[1]; sc.A[1] = Ab[0] + PLANE;
    sc.e[2] = edges[2]; sc.A[2] = Ab[1];
    sc.e[3] = edges[3]; sc.A[3] = Ab[1] + PLANE;
    sc.e[4] = edges[4]; sc.A[4] = Ab[1] + 2 * PLANE;
    scatter_all<<<dim3((NE + 255) / 256, 5), 256>>>(sc);

    // -------- conv encoder (both paths batched, smem-tiled) --------
    PathPtrs c1 = {{Ab[0], Ab[1]}, {pbp[0][0], pbp[1][0]}, {pbp[0][1], pbp[1][1]}, {p1b[0], p1b[1]}};
    conv1pool_both<<<dim3(32, 32, 2), blk16>>>(c1);

    PathPtrs c2 = {{p1b[0], p1b[1]}, {pbp[0][2], pbp[1][2]}, {pbp[0][3], pbp[1][3]}, {p2b[0], p2b[1]}};
    conv2pool_both<<<dim3(17, 17, 2), blk16>>>(c2);

    PathPtrs t1p = {{p2b[0], p2b[1]}, {pbp[0][4], pbp[1][4]}, {pbp[0][5], pbp[1][5]}, {t1b[0], t1b[1]}};
    tconv1_both<<<(2 * 514 * 257 + 255) / 256, 256>>>(t1p);

    Att2 a2 = {{t1b[0], t1b[1]}, {pbp[0][6], pbp[1][6]}, {pbp[0][7], pbp[1][7]},
               {Ab[0], Ab[1]}, {attb[0], attb[1]}};
    tconv2att_both<<<(2 * NV * 512) / 256, 256>>>(a2);

    // -------- M-chain --------
    {
        RD2 rd = {{attb[0], attb[1]}, {dvb[0], dvb[1]}};
        row_dinvN<<<dim3(NV, 2), 256>>>(rd);
        GS2 gs = {{attb[0], attb[1]}, {dvb[0], dvb[1]}, {Mb[0], Mb[1]}};
        gcn_scale4<<<dim3(NV * NV / 1024, 2), 256>>>(gs);
    }
    {
        GB2 gb = {{Mb[0], Mb[1]}, {attb[0] + PLANE, attb[1] + PLANE}, {Mtb[0], Mtb[1]}};
        tf32gemm_b<<<dim3(NV / 64, NV / 128, 2), 256>>>(gb, NV, NV, NV);
        RD2 rd = {{Mtb[0], Mtb[1]}, {dvb[0], dvb[1]}};
        row_dinvN<<<dim3(NV, 2), 256>>>(rd);
        GS2 gs = {{Mtb[0], Mtb[1]}, {dvb[0], dvb[1]}, {Mb[0], Mb[1]}};
        gcn_scale4<<<dim3(NV * NV / 1024, 2), 256>>>(gs);
    }
    {
        GB2 gb = {{Mb[1], Mb[1]}, {attb[1] + 2 * PLANE, attb[1] + 2 * PLANE}, {Mtb[1], Mtb[1]}};
        tf32gemm_b<<<dim3(NV / 64, NV / 128, 1), 256>>>(gb, NV, NV, NV);
        RD2 rd = {{Mtb[1], Mtb[1]}, {dvb[1], dvb[1]}};
        row_dinvN<<<dim3(NV, 1), 256>>>(rd);
        GS2 gs = {{Mtb[1], Mtb[1]}, {dvb[1], dvb[1]}, {Mb[1], Mb[1]}};
        gcn_scale4<<<dim3(NV * NV / 1024, 1), 256>>>(gs);
    }

    // -------- merge + final norm (fused max + rowsum) --------
    emax_dinv<<<NV, 256>>>(Mb[0], Mb[1], Mtb[0], dvb[0]);
    {
        GS2 gs = {{Mtb[0], Mtb[0]}, {dvb[0], dvb[0]}, {An_, An_}};
        gcn_scale4<<<dim3(NV * NV / 1024, 1), 256>>>(gs);
    }

    // -------- GCN layers --------
    sgemmKS<<<dim3(8, NV / 64), blk16>>>(An_, XW_, H_, HIDD, NV, 8);
    bias_relu64<<<(NV * HIDD + 255) / 256, 256>>>(H_, bias1);
    sgemm64<<<dim3(1, NV / 64), blk16>>>(H_, w2, HW_, NV, REPD, HIDD);
    sgemmKS<<<dim3(8, NV / 64), blk16>>>(An_, HW_, out, REPD, NV, 8);
    bias_add32<<<(NV * REPD + 255) / 256, 256>>>(out, bias2);
}

// round 5
// speedup vs baseline: 2.0389x; 1.1484x over previous
#include <cuda_runtime.h>
#include <math.h>
#include <stdint.h>

// Problem constants
#define NV 1024
#define NE 32768
#define EMBD 128
#define HIDD 64
#define REPD 32

// ---------------- scratch (static device globals) ----------------
__device__ float g_A[2][3][NV][NV];
__device__ float g_p1[2][16][512][512];
__device__ float g_p2[2][4][257][257];
__device__ float g_t1[2][16][514][514];
__device__ float g_att[2][3][NV][NV];
__device__ float g_M[2][NV][NV];
__device__ float g_Mt[2][NV][NV];
__device__ float g_An[NV][NV];
__device__ float g_dinv[6][NV];   // 0,1: att0 p0/p1; 2,3: hop1 p0/p1; 4: hop2; 5: final
__device__ float g_deg[3][NV];
__device__ float g_diag[3][NV];
__device__ float g_XW[NV][HIDD];
__device__ float g_H[NV][HIDD];
__device__ float g_HW[NV][REPD];

// ---------------- param structs ----------------
struct Sc5 { const int* e[5]; float* A[5]; };
struct PathPtrs {
    const float* in[2]; const float* w[2]; const float* b[2]; float* out[2];
};
struct Att2 {
    const float* t1[2]; const float* w[2]; const float* b[2];
    const float* A[2]; float* att[2];
};
struct RD2 { const float* in[2]; float* dv[2]; };
struct GemS {
    const float* A[2]; const float* B[2]; float* C[2];
    const float* dv[2]; float* deg[2]; float* diag[2];
};

// ---------------- kernels ----------------

__global__ void scatter_all(Sc5 s) {
    int j = blockIdx.y;
    int k = blockIdx.x * blockDim.x + threadIdx.x;
    if (k < NE) {
        const int* e = s.e[j];
        atomicAdd(&s.A[j][e[k] * NV + e[NE + k]], 1.0f);
    }
}

// ---- conv1 (3x3, pad1, L->16) + relu + maxpool2, smem-tiled ----
template <int L>
__device__ __forceinline__ void conv1_compute(const float* __restrict__ tile,
                                              const float* __restrict__ sw,
                                              const float* __restrict__ sb,
                                              float* __restrict__ p1,
                                              int tx, int ty, int ox, int oy) {
    float patch[L][4][4];
#pragma unroll
    for (int l = 0; l < L; l++)
#pragma unroll
        for (int r = 0; r < 4; r++)
#pragma unroll
            for (int c = 0; c < 4; c++)
                patch[l][r][c] = tile[(l * 34 + 2 * ty + r) * 36 + 2 * tx + c];
#pragma unroll
    for (int oc = 0; oc < 16; oc++) {
        float m = -1e30f;
#pragma unroll
        for (int py = 0; py < 2; py++)
#pragma unroll
            for (int px = 0; px < 2; px++) {
                float s = sb[oc];
#pragma unroll
                for (int l = 0; l < L; l++)
#pragma unroll
                    for (int ky = 0; ky < 3; ky++)
#pragma unroll
                        for (int kx = 0; kx < 3; kx++)
                            s += sw[((oc * L + l) * 3 + ky) * 3 + kx] * patch[l][py + ky][px + kx];
                m = fmaxf(m, fmaxf(s, 0.0f));
            }
        p1[((size_t)oc * 512 + oy) * 512 + ox] = m;
    }
}

__global__ void conv1pool_both(PathPtrs p) {
    __shared__ float tile[3 * 34 * 36];
    __shared__ float sw[16 * 3 * 9];
    __shared__ float sb[16];
    int path = blockIdx.z;
    const int L = (path == 0) ? 2 : 3;
    const float* A = p.in[path];
    const float* w = p.w[path];
    int tx = threadIdx.x, ty = threadIdx.y;
    int t = ty * 16 + tx;
    for (int i = t; i < 16 * L * 9; i += 256) sw[i] = w[i];
    if (t < 16) sb[t] = p.b[path][t];

    int gy0 = blockIdx.y * 32 - 1, gx0 = blockIdx.x * 32 - 1;
    for (int l = 0; l < L; l++)
        for (int i = t; i < 34 * 34; i += 256) {
            int r = i / 34, c = i % 34;
            int gy = gy0 + r, gx = gx0 + c;
            tile[(l * 34 + r) * 36 + c] = (gy >= 0 && gy < NV && gx >= 0 && gx < NV)
                                              ? A[((size_t)l * NV + gy) * NV + gx] : 0.0f;
        }
    __syncthreads();
    int ox = blockIdx.x * 16 + tx, oy = blockIdx.y * 16 + ty;
    if (path == 0) conv1_compute<2>(tile, sw, sb, p.out[0], tx, ty, ox, oy);
    else           conv1_compute<3>(tile, sw, sb, p.out[1], tx, ty, ox, oy);
}

// ---- conv2 (3x3, pad2, 16->4) + relu + maxpool2 ----
// smem tile per channel, register-prefetch pipelined over the 16-channel loop.
__global__ void conv2pool_both(PathPtrs pp) {
    __shared__ float tile[36 * 38];
    __shared__ float sw[576];
    __shared__ float sb[4];
    int path = blockIdx.z;
    const float* p1 = pp.in[path];
    float* p2 = pp.out[path];
    int tx = threadIdx.x, ty = threadIdx.y;
    int t = ty * 16 + tx;
    for (int i = t; i < 576; i += 256) sw[i] = pp.w[path][i];
    if (t < 4) sb[t] = pp.b[path][t];

    int gy0 = blockIdx.y * 32 - 2, gx0 = blockIdx.x * 32 - 2;

    // load slots: slot s covers smem index t + s*256 (< 36*36 = 1296)
    int srow[6], scol[6], sok[6];
    float r[6];
#pragma unroll
    for (int s = 0; s < 6; s++) {
        int i = t + s * 256;
        srow[s] = i / 36; scol[s] = i % 36;
        sok[s] = (i < 1296);
    }
    // prefetch ci = 0
#pragma unroll
    for (int s = 0; s < 6; s++) {
        if (sok[s]) {
            int gy = gy0 + srow[s], gx = gx0 + scol[s];
            r[s] = (gy >= 0 && gy < 512 && gx >= 0 && gx < 512)
                       ? p1[(size_t)gy * 512 + gx] : 0.0f;
        }
    }

    float acc[4][2][2];
#pragma unroll
    for (int oc = 0; oc < 4; oc++)
#pragma unroll
        for (int py = 0; py < 2; py++)
#pragma unroll
            for (int px = 0; px < 2; px++) acc[oc][py][px] = 0.0f;

    __syncthreads();   // weights + (implicitly) first-iteration ordering

    for (int ci = 0; ci < 16; ci++) {
#pragma unroll
        for (int s = 0; s < 6; s++)
            if (sok[s]) tile[srow[s] * 38 + scol[s]] = r[s];
        __syncthreads();
        // issue next channel's loads BEFORE computing -> latency hidden by FMAs
        if (ci < 15) {
#pragma unroll
            for (int s = 0; s < 6; s++) {
                if (sok[s]) {
                    int gy = gy0 + srow[s], gx = gx0 + scol[s];
                    r[s] = (gy >= 0 && gy < 512 && gx >= 0 && gx < 512)
                               ? p1[((size_t)(ci + 1) * 512 + gy) * 512 + gx] : 0.0f;
                }
            }
        }
        float patch[4][4];
#pragma unroll
        for (int rw = 0; rw < 4; rw++)
#pragma unroll
            for (int c = 0; c < 4; c++)
                patch[rw][c] = tile[(2 * ty + rw) * 38 + 2 * tx + c];
#pragma unroll
        for (int oc = 0; oc < 4; oc++)
#pragma unroll
            for (int ky = 0; ky < 3; ky++)
#pragma unroll
                for (int kx = 0; kx < 3; kx++) {
                    float wv = sw[((oc * 16 + ci) * 3 + ky) * 3 + kx];
                    acc[oc][0][0] += wv * patch[ky][kx];
                    acc[oc][0][1] += wv * patch[ky][kx + 1];
                    acc[oc][1][0] += wv * patch[ky + 1][kx];
                    acc[oc][1][1] += wv * patch[ky + 1][kx + 1];
                }
        __syncthreads();
    }
    int x = blockIdx.x * 16 + tx, y = blockIdx.y * 16 + ty;
    if (x < 257 && y < 257) {
#pragma unroll
        for (int oc = 0; oc < 4; oc++) {
            float m = fmaxf(fmaxf(acc[oc][0][0], acc[oc][0][1]),
                            fmaxf(acc[oc][1][0], acc[oc][1][1])) + sb[oc];
            p2[((size_t)oc * 257 + y) * 257 + x] = fmaxf(m, 0.0f);
        }
    }
}

// ---- tconv1 (k2 s2, 4->16) + relu, x-parity pairs ----
__global__ void tconv1_both(PathPtrs pp) {
    int gidx = blockIdx.x * blockDim.x + threadIdx.x;
    const int PL = 514 * 257;
    if (gidx >= 2 * PL) return;
    int path = gidx / PL;
    int idx = gidx - path * PL;
    const float* p2 = pp.in[path];
    const float* w = pp.w[path];
    const float* b = pp.b[path];
    float* t1 = pp.out[path];
    int m = idx % 257, oy = idx / 257;
    int ky = (oy + 1) & 1;
    int iy = (oy - 1 + ky) >> 1;
    float v[4];
#pragma unroll
    for (int ci = 0; ci < 4; ci++) v[ci] = p2[((size_t)ci * 257 + iy) * 257 + m];
#pragma unroll
    for (int co = 0; co < 16; co++) {
        float s0 = b[co], s1 = b[co];
#pragma unroll
        for (int ci = 0; ci < 4; ci++) {
            s0 += w[((co * 4 + ci) * 2 + ky) * 2 + 1] * v[ci];
            s1 += w[((co * 4 + ci) * 2 + ky) * 2 + 0] * v[ci];
        }
        *(float2*)&t1[((size_t)co * 514 + oy) * 514 + 2 * m] =
            make_float2(fmaxf(s0, 0.0f), fmaxf(s1, 0.0f));
    }
}

// ---- tconv2 (k2 s2, 16->L) + sigmoid + crop + multiply adjacency ----
template <int L>
__device__ __forceinline__ void tconv2_impl(const float* __restrict__ t1,
                                            const float* __restrict__ w,
                                            const float* __restrict__ b,
                                            const float* __restrict__ A,
                                            float* __restrict__ att, int idx) {
    int m = idx & 511, y = idx >> 9;
    int ky = (y + 1) & 1;
    int iy = (y - 1 + ky) >> 1;
    float v[16];
#pragma unroll
    for (int ci = 0; ci < 16; ci++) v[ci] = t1[((size_t)ci * 514 + iy) * 514 + m];
#pragma unroll
    for (int l = 0; l < L; l++) {
        float s0 = b[l], s1 = b[l];
#pragma unroll
        for (int ci = 0; ci < 16; ci++) {
            s0 += w[((l * 16 + ci) * 2 + ky) * 2 + 1] * v[ci];
            s1 += w[((l * 16 + ci) * 2 + ky) * 2 + 0] * v[ci];
        }
        float g0 = 1.0f / (1.0f + expf(-s0));
        float g1 = 1.0f / (1.0f + expf(-s1));
        size_t off = (size_t)l * NV * NV + (size_t)y * NV + 2 * m;
        float2 a = *(const float2*)&A[off];
        *(float2*)&att[off] = make_float2(a.x * g0, a.y * g1);
    }
}

__global__ void tconv2att_both(Att2 a) {
    int gidx = blockIdx.x * blockDim.x + threadIdx.x;
    const int PL = NV * 512;
    int path = gidx / PL;
    int idx = gidx - path * PL;
    if (path == 0) tconv2_impl<2>(a.t1[0], a.w[0], a.b[0], a.A[0], a.att[0], idx);
    else           tconv2_impl<3>(a.t1[1], a.w[1], a.b[1], a.A[1], a.att[1], idx);
}

// ---- row sums (self-loop fixup) -> rsqrt. grid (NV, nplanes) ----
__global__ void row_dinvN(RD2 rd) {
    int p = blockIdx.y;
    int row = blockIdx.x;
    const float* r = rd.in[p] + (size_t)row * NV;
    float s = 0.0f;
    for (int j = threadIdx.x; j < NV; j += 256) s += r[j];
    __shared__ float sh[256];
    sh[threadIdx.x] = s;
    __syncthreads();
    for (int o = 128; o > 0; o >>= 1) {
        if (threadIdx.x < o) sh[threadIdx.x] += sh[threadIdx.x + o];
        __syncthreads();
    }
    if (threadIdx.x == 0) {
        float d = sh[0];
        if (r[row] == 0.0f) d += 1.0f;
        rd.dv[p][row] = d > 0.0f ? rsqrtf(d) : 0.0f;
    }
}

// ---- dinv from GEMM-accumulated deg/diag ----
__global__ void dinv_fix(const float* __restrict__ deg, const float* __restrict__ diag,
                         float* __restrict__ dv, int n) {
    int i = blockIdx.x * blockDim.x + threadIdx.x;
    if (i < n) {
        float d = deg[i];
        if (diag[i] == 0.0f) d += 1.0f;
        dv[i] = d > 0.0f ? rsqrtf(d) : 0.0f;
    }
}

// ---- scaled max-merge + row-sum/dinv.
// o[i][j] = max(dva_i*fix(a)*dva_j, dvb_i*fix(b)*dvb_j); dv = rsqrt(rowsum w/ diag fill)
__global__ void emax_dinv(const float* __restrict__ a, const float* __restrict__ dva,
                          const float* __restrict__ b, const float* __restrict__ dvb,
                          float* __restrict__ o, float* __restrict__ dv) {
    int row = blockIdx.x;
    float dar = dva[row], dbr = dvb[row];
    __shared__ float sh[256];
    __shared__ float sdiag;
    float s = 0.0f;
    for (int j = threadIdx.x; j < NV; j += 256) {
        float va = a[(size_t)row * NV + j];
        if (j == row && va == 0.0f) va = 1.0f;
        va *= dar * dva[j];
        float vb = b[(size_t)row * NV + j];
        if (j == row && vb == 0.0f) vb = 1.0f;
        vb *= dbr * dvb[j];
        float v = fmaxf(va, vb);
        o[(size_t)row * NV + j] = v;
        if (j == row) sdiag = v;
        s += v;
    }
    sh[threadIdx.x] = s;
    __syncthreads();
    for (int off = 128; off > 0; off >>= 1) {
        if (threadIdx.x < off) sh[threadIdx.x] += sh[threadIdx.x + off];
        __syncthreads();
    }
    if (threadIdx.x == 0) {
        float d = sh[0];
        if (sdiag == 0.0f) d += 1.0f;
        dv[row] = d > 0.0f ? rsqrtf(d) : 0.0f;
    }
}

__global__ void bias_relu64(float* __restrict__ H, const float* __restrict__ bias) {
    int idx = blockIdx.x * blockDim.x + threadIdx.x;
    if (idx < NV * HIDD) H[idx] = fmaxf(H[idx] + bias[idx & (HIDD - 1)], 0.0f);
}

// ---------------- tf32 GEMM with fused gcn-norm on A + deg/diag epilogue ----------------
// C = (Dv fix(A) Dv) @ B; deg += rowsums(C); diag[i] = C[i][i].  M=N=K=1024.
__device__ __forceinline__ uint32_t f2tf(float f) {
    uint32_t r;
    asm("cvt.rna.tf32.f32 %0, %1;" : "=r"(r) : "f"(f));
    return r;
}

__device__ __forceinline__ void fix_scale4(float4& v, int row, int kc, float dvr,
                                           const float* __restrict__ dv) {
    float4 dk = *(const float4*)&dv[kc];
    float* p = &v.x;
#pragma unroll
    for (int q = 0; q < 4; q++)
        if (row == kc + q && p[q] == 0.0f) p[q] = 1.0f;
    v.x *= dvr * dk.x; v.y *= dvr * dk.y; v.z *= dvr * dk.z; v.w *= dvr * dk.w;
}

__global__ void __launch_bounds__(256) tf32gemm_s(GemS g) {
    const float* __restrict__ A = g.A[blockIdx.z];
    const float* __restrict__ B = g.B[blockIdx.z];
    float* __restrict__ C = g.C[blockIdx.z];
    const float* __restrict__ dv = g.dv[blockIdx.z];
    float* __restrict__ deg = g.deg[blockIdx.z];
    float* __restrict__ diag = g.diag[blockIdx.z];
    const int Nn = NV, K = NV;

    __shared__ float As[2][16][136];
    __shared__ float Bs[2][16][72];

    const int tid = threadIdx.x;
    const int lane = tid & 31;
    const int wid = tid >> 5;
    const int wr = wid & 3;
    const int wc = wid >> 2;
    const int m0 = blockIdx.y * 128;
    const int n0 = blockIdx.x * 64;

    float acc[2][4][4];
#pragma unroll
    for (int mi = 0; mi < 2; mi++)
#pragma unroll
        for (int ni = 0; ni < 4; ni++)
#pragma unroll
            for (int r = 0; r < 4; r++) acc[mi][ni][r] = 0.0f;

    const int ar = tid >> 2;
    const int ac4 = (tid & 3) << 2;
    const int bk = tid >> 4;
    const int bn4 = (tid & 15) << 2;
    const int rowA0 = m0 + ar, rowA1 = m0 + 64 + ar;
    const float dvr0 = dv[rowA0], dvr1 = dv[rowA1];

    float4 av0, av1, bv;
    const int T = K >> 4;

    av0 = *(const float4*)&A[(size_t)rowA0 * K + ac4];
    av1 = *(const float4*)&A[(size_t)rowA1 * K + ac4];
    bv  = *(const float4*)&B[(size_t)bk * Nn + n0 + bn4];
    fix_scale4(av0, rowA0, ac4, dvr0, dv);
    fix_scale4(av1, rowA1, ac4, dvr1, dv);

    As[0][ac4 + 0][ar] = __uint_as_float(f2tf(av0.x));
    As[0][ac4 + 1][ar] = __uint_as_float(f2tf(av0.y));
    As[0][ac4 + 2][ar] = __uint_as_float(f2tf(av0.z));
    As[0][ac4 + 3][ar] = __uint_as_float(f2tf(av0.w));
    As[0][ac4 + 0][ar + 64] = __uint_as_float(f2tf(av1.x));
    As[0][ac4 + 1][ar + 64] = __uint_as_float(f2tf(av1.y));
    As[0][ac4 + 2][ar + 64] = __uint_as_float(f2tf(av1.z));
    As[0][ac4 + 3][ar + 64] = __uint_as_float(f2tf(av1.w));
    {
        float4 bt;
        bt.x = __uint_as_float(f2tf(bv.x));
        bt.y = __uint_as_float(f2tf(bv.y));
        bt.z = __uint_as_float(f2tf(bv.z));
        bt.w = __uint_as_float(f2tf(bv.w));
        *(float4*)&Bs[0][bk][bn4] = bt;
    }
    __syncthreads();

    for (int t = 0; t < T; t++) {
        int cur = t & 1;
        if (t + 1 < T) {
            int kb = (t + 1) << 4;
            av0 = *(const float4*)&A[(size_t)rowA0 * K + kb + ac4];
            av1 = *(const float4*)&A[(size_t)rowA1 * K + kb + ac4];
            bv  = *(const float4*)&B[(size_t)(kb + bk) * Nn + n0 + bn4];
            fix_scale4(av0, rowA0, kb + ac4, dvr0, dv);
            fix_scale4(av1, rowA1, kb + ac4, dvr1, dv);
        }
#pragma unroll
        for (int ks = 0; ks < 2; ks++) {
            const int k0 = ks * 8;
            uint32_t a[2][4], b[4][2];
            const int kl = k0 + (lane & 3);
            const int rl = lane >> 2;
#pragma unroll
            for (int mi = 0; mi < 2; mi++) {
                int m = wr * 32 + mi * 16 + rl;
                a[mi][0] = __float_as_uint(As[cur][kl][m]);
                a[mi][1] = __float_as_uint(As[cur][kl][m + 8]);
                a[mi][2] = __float_as_uint(As[cur][kl + 4][m]);
                a[mi][3] = __float_as_uint(As[cur][kl + 4][m + 8]);
            }
#pragma unroll
            for (int ni = 0; ni < 4; ni++) {
                int n = wc * 32 + ni * 8 + rl;
                b[ni][0] = __float_as_uint(Bs[cur][kl][n]);
                b[ni][1] = __float_as_uint(Bs[cur][kl + 4][n]);
            }
#pragma unroll
            for (int mi = 0; mi < 2; mi++)
#pragma unroll
                for (int ni = 0; ni < 4; ni++) {
                    asm volatile(
                        "mma.sync.aligned.m16n8k8.row.col.f32.tf32.tf32.f32 "
                        "{%0,%1,%2,%3}, {%4,%5,%6,%7}, {%8,%9}, {%0,%1,%2,%3};"
                        : "+f"(acc[mi][ni][0]), "+f"(acc[mi][ni][1]),
                          "+f"(acc[mi][ni][2]), "+f"(acc[mi][ni][3])
                        : "r"(a[mi][0]), "r"(a[mi][1]), "r"(a[mi][2]), "r"(a[mi][3]),
                          "r"(b[ni][0]), "r"(b[ni][1]));
                }
        }
        if (t + 1 < T) {
            int nxt = (t + 1) & 1;
            As[nxt][ac4 + 0][ar] = __uint_as_float(f2tf(av0.x));
            As[nxt][ac4 + 1][ar] = __uint_as_float(f2tf(av0.y));
            As[nxt][ac4 + 2][ar] = __uint_as_float(f2tf(av0.z));
            As[nxt][ac4 + 3][ar] = __uint_as_float(f2tf(av0.w));
            As[nxt][ac4 + 0][ar + 64] = __uint_as_float(f2tf(av1.x));
            As[nxt][ac4 + 1][ar + 64] = __uint_as_float(f2tf(av1.y));
            As[nxt][ac4 + 2][ar + 64] = __uint_as_float(f2tf(av1.z));
            As[nxt][ac4 + 3][ar + 64] = __uint_as_float(f2tf(av1.w));
            float4 bt;
            bt.x = __uint_as_float(f2tf(bv.x));
            bt.y = __uint_as_float(f2tf(bv.y));
            bt.z = __uint_as_float(f2tf(bv.z));
            bt.w = __uint_as_float(f2tf(bv.w));
            *(float4*)&Bs[nxt][bk][bn4] = bt;
            __syncthreads();
        }
    }

    // epilogue: store C, capture diag, accumulate row sums into deg
    const int rl = lane >> 2;
#pragma unroll
    for (int mi = 0; mi < 2; mi++) {
        int row = m0 + wr * 32 + mi * 16 + rl;
#pragma unroll
        for (int ni = 0; ni < 4; ni++) {
            int col = n0 + wc * 32 + ni * 8 + ((lane & 3) << 1);
            if (row == col) diag[row] = acc[mi][ni][0];
            if (row == col + 1) diag[row] = acc[mi][ni][1];
            if (row + 8 == col) diag[row + 8] = acc[mi][ni][2];
            if (row + 8 == col + 1) diag[row + 8] = acc[mi][ni][3];
            *(float2*)&C[(size_t)row * Nn + col] = make_float2(acc[mi][ni][0], acc[mi][ni][1]);
            *(float2*)&C[(size_t)(row + 8) * Nn + col] = make_float2(acc[mi][ni][2], acc[mi][ni][3]);
        }
    }
    float rs[4] = {0.0f, 0.0f, 0.0f, 0.0f};
#pragma unroll
    for (int mi = 0; mi < 2; mi++)
#pragma unroll
        for (int ni = 0; ni < 4; ni++) {
            rs[mi * 2 + 0] += acc[mi][ni][0] + acc[mi][ni][1];
            rs[mi * 2 + 1] += acc[mi][ni][2] + acc[mi][ni][3];
        }
#pragma unroll
    for (int q = 0; q < 4; q++) {
        rs[q] += __shfl_xor_sync(0xFFFFFFFF, rs[q], 1);
        rs[q] += __shfl_xor_sync(0xFFFFFFFF, rs[q], 2);
    }
    if ((lane & 3) == 0) {
        int rbase = m0 + wr * 32 + rl;
        atomicAdd(&deg[rbase], rs[0]);
        atomicAdd(&deg[rbase + 8], rs[1]);
        atomicAdd(&deg[rbase + 16], rs[2]);
        atomicAdd(&deg[rbase + 24], rs[3]);
    }
}

// plain fp32 64x64 tile GEMM (tiny x@w1, H@w2)
__global__ void sgemm64(const float* __restrict__ A, const float* __restrict__ B,
                        float* __restrict__ C, int M, int Nn, int K) {
    __shared__ float As[16][64];
    __shared__ float Bs[16][64];
    int tx = threadIdx.x, ty = threadIdx.y;
    int tid = ty * 16 + tx;
    int m0 = blockIdx.y * 64, n0 = blockIdx.x * 64;
    float acc[4][4];
#pragma unroll
    for (int i = 0; i < 4; i++)
#pragma unroll
        for (int j = 0; j < 4; j++) acc[i][j] = 0.0f;
    int la_r = tid / 16, la_k = tid % 16;
    int lb_k = tid / 64, lb_n = tid % 64;
    for (int k0 = 0; k0 < K; k0 += 16) {
#pragma unroll
        for (int r = 0; r < 4; r++)
            As[la_k][la_r + 16 * r] = A[(size_t)(m0 + la_r + 16 * r) * K + k0 + la_k];
#pragma unroll
        for (int r = 0; r < 4; r++) {
            int kk = lb_k + 4 * r;
            Bs[kk][lb_n] = (n0 + lb_n < Nn) ? B[(size_t)(k0 + kk) * Nn + n0 + lb_n] : 0.0f;
        }
        __syncthreads();
#pragma unroll
        for (int k = 0; k < 16; k++) {
            float a[4], b[4];
#pragma unroll
            for (int i = 0; i < 4; i++) a[i] = As[k][ty * 4 + i];
#pragma unroll
            for (int j = 0; j < 4; j++) b[j] = Bs[k][tx * 4 + j];
#pragma unroll
            for (int i = 0; i < 4; i++)
#pragma unroll
                for (int j = 0; j < 4; j++) acc[i][j] += a[i] * b[j];
        }
        __syncthreads();
    }
#pragma unroll
    for (int i = 0; i < 4; i++) {
        int row = m0 + ty * 4 + i;
#pragma unroll
        for (int j = 0; j < 4; j++) {
            int col = n0 + tx * 4 + j;
            if (col < Nn) C[(size_t)row * Nn + col] = acc[i][j];
        }
    }
}

// split-K fp32 GEMM with fused gcn-norm on A: C += (Dv fix(A) Dv) @ B.
// grid (KS, M/64); C pre-zeroed; optional bias added by slice 0.
__global__ void sgemmKS(const float* __restrict__ A, const float* __restrict__ dv,
                        const float* __restrict__ B, float* __restrict__ C,
                        int Nn, int K, int KS, const float* __restrict__ bias) {
    __shared__ float As[16][64];
    __shared__ float Bs[16][64];
    int tx = threadIdx.x, ty = threadIdx.y;
    int tid = ty * 16 + tx;
    int m0 = blockIdx.y * 64;
    int kLen = K / KS;
    int kStart = blockIdx.x * kLen;
    float acc[4][4];
#pragma unroll
    for (int i = 0; i < 4; i++)
#pragma unroll
        for (int j = 0; j < 4; j++) acc[i][j] = 0.0f;
    int la_r = tid / 16, la_k = tid % 16;
    int lb_k = tid / 64, lb_n = tid % 64;
    for (int k0 = kStart; k0 < kStart + kLen; k0 += 16) {
#pragma unroll
        for (int r = 0; r < 4; r++) {
            int row = m0 + la_r + 16 * r;
            int kc = k0 + la_k;
            float v = A[(size_t)row * K + kc];
            if (row == kc && v == 0.0f) v = 1.0f;
            As[la_k][la_r + 16 * r] = v * dv[row] * dv[kc];
        }
#pragma unroll
        for (int r = 0; r < 4; r++) {
            int kk = lb_k + 4 * r;
            Bs[kk][lb_n] = (lb_n < Nn) ? B[(size_t)(k0 + kk) * Nn + lb_n] : 0.0f;
        }
        __syncthreads();
#pragma unroll
        for (int k = 0; k < 16; k++) {
            float a[4], b[4];
#pragma unroll
            for (int i = 0; i < 4; i++) a[i] = As[k][ty * 4 + i];
#pragma unroll
            for (int j = 0; j < 4; j++) b[j] = Bs[k][tx * 4 + j];
#pragma unroll
            for (int i = 0; i < 4; i++)
#pragma unroll
                for (int j = 0; j < 4; j++) acc[i][j] += a[i] * b[j];
        }
        __syncthreads();
    }
#pragma unroll
    for (int i = 0; i < 4; i++) {
        int row = m0 + ty * 4 + i;
#pragma unroll
        for (int j = 0; j < 4; j++) {
            int col = tx * 4 + j;
            if (col < Nn) {
                float v = acc[i][j];
                if (bias != nullptr && kStart == 0) v += bias[col];
                atomicAdd(&C[(size_t)row * Nn + col], v);
            }
        }
    }
}

// ---------------- host orchestration ----------------

extern "C" void kernel_launch(void* const* d_in, const int* in_sizes, int n_in,
                              void* d_out, int out_size) {
    const float* x = (const float*)d_in[0];
    const int* edges[5];
    for (int i = 0; i < 5; i++) edges[i] = (const int*)d_in[1 + i];
    const float* pbp[2][8];
    for (int b = 0; b < 2; b++)
        for (int i = 0; i < 8; i++) pbp[b][i] = (const float*)d_in[6 + b * 8 + i];
    const float* w1    = (const float*)d_in[22];
    const float* bias1 = (const float*)d_in[23];
    const float* w2    = (const float*)d_in[24];
    const float* bias2 = (const float*)d_in[25];
    float* out = (float*)d_out;

    float *A_, *p1_, *p2_, *t1_, *att_, *M_, *Mt_, *An_, *dinv_, *deg_, *diag_, *XW_, *H_, *HW_;
    cudaGetSymbolAddress((void**)&A_,    g_A);
    cudaGetSymbolAddress((void**)&p1_,   g_p1);
    cudaGetSymbolAddress((void**)&p2_,   g_p2);
    cudaGetSymbolAddress((void**)&t1_,   g_t1);
    cudaGetSymbolAddress((void**)&att_,  g_att);
    cudaGetSymbolAddress((void**)&M_,    g_M);
    cudaGetSymbolAddress((void**)&Mt_,   g_Mt);
    cudaGetSymbolAddress((void**)&An_,   g_An);
    cudaGetSymbolAddress((void**)&dinv_, g_dinv);
    cudaGetSymbolAddress((void**)&deg_,  g_deg);
    cudaGetSymbolAddress((void**)&diag_, g_diag);
    cudaGetSymbolAddress((void**)&XW_,   g_XW);
    cudaGetSymbolAddress((void**)&H_,    g_H);
    cudaGetSymbolAddress((void**)&HW_,   g_HW);

    const size_t PLANE = (size_t)NV * NV;
    dim3 blk16(16, 16);

    float* Ab[2]   = { A_,   A_   + 3 * PLANE };
    float* p1b[2]  = { p1_,  p1_  + (size_t)16 * 512 * 512 };
    float* p2b[2]  = { p2_,  p2_  + (size_t)4 * 257 * 257 };
    float* t1b[2]  = { t1_,  t1_  + (size_t)16 * 514 * 514 };
    float* attb[2] = { att_, att_ + 3 * PLANE };
    float* Mb[2]   = { M_,   M_   + PLANE };
    float* Mtb[2]  = { Mt_,  Mt_  + PLANE };

    // -------- setup --------
    cudaMemsetAsync(A_, 0, 6 * PLANE * sizeof(float), 0);
    cudaMemsetAsync(deg_, 0, 3 * NV * sizeof(float), 0);
    cudaMemsetAsync(H_, 0, (size_t)NV * HIDD * sizeof(float), 0);
    cudaMemsetAsync(out, 0, (size_t)NV * REPD * sizeof(float), 0);
    sgemm64<<<dim3(1, NV / 64), blk16>>>(x, w1, XW_, NV, HIDD, EMBD);

    // -------- scatter all 5 edge lists --------
    Sc5 sc;
    sc.e[0] = edges[0]; sc.A[0] = Ab[0];
    sc.e[1] = edges[1]; sc.A[1] = Ab[0] + PLANE;
    sc.e[2] = edges[2]; sc.A[2] = Ab[1];
    sc.e[3] = edges[3]; sc.A[3] = Ab[1] + PLANE;
    sc.e[4] = edges[4]; sc.A[4] = Ab[1] + 2 * PLANE;
    scatter_all<<<dim3((NE + 255) / 256, 5), 256>>>(sc);

    // -------- conv encoder (both paths batched) --------
    PathPtrs c1 = {{Ab[0], Ab[1]}, {pbp[0][0], pbp[1][0]}, {pbp[0][1], pbp[1][1]}, {p1b[0], p1b[1]}};
    conv1pool_both<<<dim3(32, 32, 2), blk16>>>(c1);

    PathPtrs c2 = {{p1b[0], p1b[1]}, {pbp[0][2], pbp[1][2]}, {pbp[0][3], pbp[1][3]}, {p2b[0], p2b[1]}};
    conv2pool_both<<<dim3(17, 17, 2), blk16>>>(c2);

    PathPtrs t1p = {{p2b[0], p2b[1]}, {pbp[0][4], pbp[1][4]}, {pbp[0][5], pbp[1][5]}, {t1b[0], t1b[1]}};
    tconv1_both<<<(2 * 514 * 257 + 255) / 256, 256>>>(t1p);

    Att2 a2 = {{t1b[0], t1b[1]}, {pbp[0][6], pbp[1][6]}, {pbp[0][7], pbp[1][7]},
               {Ab[0], Ab[1]}, {attb[0], attb[1]}};
    tconv2att_both<<<(2 * NV * 512) / 256, 256>>>(a2);

    // -------- M-chain, norms fused into GEMMs --------
    // dinv of att0 planes (feeds hop1 A-scaling)
    {
        RD2 rd = {{attb[0], attb[1]}, {dinv_, dinv_ + NV}};
        row_dinvN<<<dim3(NV, 2), 256>>>(rd);
    }
    // hop1 both paths: Mt[p] = norm(att0[p]) @ att1[p], raw + deg/diag
    {
        GemS gs;
        gs.A[0] = attb[0];         gs.A[1] = attb[1];
        gs.B[0] = attb[0] + PLANE; gs.B[1] = attb[1] + PLANE;
        gs.C[0] = Mtb[0];          gs.C[1] = Mtb[1];
        gs.dv[0] = dinv_;          gs.dv[1] = dinv_ + NV;
        gs.deg[0] = deg_;          gs.deg[1] = deg_ + NV;
        gs.diag[0] = diag_;        gs.diag[1] = diag_ + NV;
        tf32gemm_s<<<dim3(NV / 64, NV / 128, 2), 256>>>(gs);
        dinv_fix<<<(2 * NV + 255) / 256, 256>>>(deg_, diag_, dinv_ + 2 * NV, 2 * NV);
    }
    // hop2 path1: M[1] = norm(Mt[1]) @ att2[1], raw + deg/diag
    {
        GemS gs;
        gs.A[0] = Mtb[1];
        gs.B[0] = attb[1] + 2 * PLANE;
        gs.C[0] = Mb[1];
        gs.dv[0] = dinv_ + 3 * NV;
        gs.deg[0] = deg_ + 2 * NV;
        gs.diag[0] = diag_ + 2 * NV;
        gs.A[1] = gs.A[0]; gs.B[1] = gs.B[0]; gs.C[1] = gs.C[0];
        gs.dv[1] = gs.dv[0]; gs.deg[1] = gs.deg[0]; gs.diag[1] = gs.diag[0];
        tf32gemm_s<<<dim3(NV / 64, NV / 128, 1), 256>>>(gs);
        dinv_fix<<<(NV + 255) / 256, 256>>>(deg_ + 2 * NV, diag_ + 2 * NV, dinv_ + 4 * NV, NV);
    }

    // -------- scaled merge: An_raw = max(norm-scaled hop outputs), final dinv --------
    emax_dinv<<<NV, 256>>>(Mtb[0], dinv_ + 2 * NV, Mb[1], dinv_ + 4 * NV, An_, dinv_ + 5 * NV);

    // -------- GCN layers, final norm fused into A-loads --------
    sgemmKS<<<dim3(8, NV / 64), blk16>>>(An_, dinv_ + 5 * NV, XW_, H_, HIDD, NV, 8, nullptr);
    bias_relu64<<<(NV * HIDD + 255) / 256, 256>>>(H_, bias1);
    sgemm64<<<dim3(1, NV / 64), blk16>>>(H_, w2, HW_, NV, REPD, HIDD);
    sgemmKS<<<dim3(8, NV / 64), blk16>>>(An_, dinv_ + 5 * NV, HW_, out, REPD, NV, 8, bias2);
}

// round 6
// speedup vs baseline: 2.1227x; 1.0411x over previous
#include <cuda_runtime.h>
#include <math.h>
#include <stdint.h>

// Problem constants
#define NV 1024
#define NE 32768
#define EMBD 128
#define HIDD 64
#define REPD 32

// ---------------- scratch (static device globals) ----------------
__device__ float g_A[2][3][NV][NV];
__device__ float g_p1[2][16][512][512];
__device__ float g_p2[2][4][257][257];
__device__ float g_att[2][3][NV][NV];
__device__ float g_M[2][NV][NV];
__device__ float g_Mt[2][NV][NV];
__device__ float g_An[NV][NV];
__device__ float g_dinv[6][NV];   // 0,1: att0 p0/p1; 2,3: hop1 p0/p1; 4: hop2; 5: final
__device__ float g_deg[3][NV];
__device__ float g_diag[3][NV];
__device__ float g_XW[NV][HIDD];
__device__ float g_H[NV][HIDD];
__device__ float g_HW[NV][REPD];

// ---------------- param structs ----------------
struct Sc5 { const int* e[5]; float* A[5]; };
struct PathPtrs {
    const float* in[2]; const float* w[2]; const float* b[2]; float* out[2];
};
struct FAtt {
    const float* p2[2]; const float* w1[2]; const float* b1[2];
    const float* w2[2]; const float* b2[2]; const float* A[2]; float* att[2];
};
struct RD2 { const float* in[2]; float* dv[2]; };
struct GemS {
    const float* A[2]; const float* B[2]; float* C[2];
    const float* dv[2]; float* deg[2]; float* diag[2];
};

// ---------------- kernels ----------------

__global__ void scatter_all(Sc5 s) {
    int j = blockIdx.y;
    int k = blockIdx.x * blockDim.x + threadIdx.x;
    if (k < NE) {
        const int* e = s.e[j];
        atomicAdd(&s.A[j][e[k] * NV + e[NE + k]], 1.0f);
    }
}

// ---- conv1 (3x3, pad1, L->16) + relu + maxpool2, smem-tiled, weight-hoisted ----
template <int L>
__device__ __forceinline__ void conv1_compute(const float* __restrict__ tile,
                                              const float* __restrict__ sw,
                                              const float* __restrict__ sb,
                                              float* __restrict__ p1,
                                              int tx, int ty, int ox, int oy) {
    float patch[L][4][4];
#pragma unroll
    for (int l = 0; l < L; l++)
#pragma unroll
        for (int r = 0; r < 4; r++)
#pragma unroll
            for (int c = 0; c < 4; c++)
                patch[l][r][c] = tile[(l * 34 + 2 * ty + r) * 36 + 2 * tx + c];
#pragma unroll
    for (int oc = 0; oc < 16; oc++) {
        float b = sb[oc];
        float s00 = b, s01 = b, s10 = b, s11 = b;   // 4 pool positions, weight reused 4x
#pragma unroll
        for (int l = 0; l < L; l++)
#pragma unroll
            for (int ky = 0; ky < 3; ky++)
#pragma unroll
                for (int kx = 0; kx < 3; kx++) {
                    float w = sw[((oc * L + l) * 3 + ky) * 3 + kx];
                    s00 += w * patch[l][ky][kx];
                    s01 += w * patch[l][ky][kx + 1];
                    s10 += w * patch[l][ky + 1][kx];
                    s11 += w * patch[l][ky + 1][kx + 1];
                }
        float m = fmaxf(fmaxf(fmaxf(s00, s01), fmaxf(s10, s11)), 0.0f);
        p1[((size_t)oc * 512 + oy) * 512 + ox] = m;
    }
}

__global__ void conv1pool_both(PathPtrs p) {
    __shared__ float tile[3 * 34 * 36];
    __shared__ float sw[16 * 3 * 9];
    __shared__ float sb[16];
    int path = blockIdx.z;
    const int L = (path == 0) ? 2 : 3;
    const float* A = p.in[path];
    const float* w = p.w[path];
    int tx = threadIdx.x, ty = threadIdx.y;
    int t = ty * 16 + tx;
    for (int i = t; i < 16 * L * 9; i += 256) sw[i] = w[i];
    if (t < 16) sb[t] = p.b[path][t];

    int gy0 = blockIdx.y * 32 - 1, gx0 = blockIdx.x * 32 - 1;
    for (int l = 0; l < L; l++)
        for (int i = t; i < 34 * 34; i += 256) {
            int r = i / 34, c = i % 34;
            int gy = gy0 + r, gx = gx0 + c;
            tile[(l * 34 + r) * 36 + c] = (gy >= 0 && gy < NV && gx >= 0 && gx < NV)
                                              ? A[((size_t)l * NV + gy) * NV + gx] : 0.0f;
        }
    __syncthreads();
    int ox = blockIdx.x * 16 + tx, oy = blockIdx.y * 16 + ty;
    if (path == 0) conv1_compute<2>(tile, sw, sb, p.out[0], tx, ty, ox, oy);
    else           conv1_compute<3>(tile, sw, sb, p.out[1], tx, ty, ox, oy);
}

// ---- conv2 (3x3, pad2, 16->4) + relu + maxpool2, smem-tiled + prefetch pipelined ----
__global__ void conv2pool_both(PathPtrs pp) {
    __shared__ float tile[36 * 38];
    __shared__ float sw[576];
    __shared__ float sb[4];
    int path = blockIdx.z;
    const float* p1 = pp.in[path];
    float* p2 = pp.out[path];
    int tx = threadIdx.x, ty = threadIdx.y;
    int t = ty * 16 + tx;
    for (int i = t; i < 576; i += 256) sw[i] = pp.w[path][i];
    if (t < 4) sb[t] = pp.b[path][t];

    int gy0 = blockIdx.y * 32 - 2, gx0 = blockIdx.x * 32 - 2;

    int srow[6], scol[6], sok[6];
    float r[6];
#pragma unroll
    for (int s = 0; s < 6; s++) {
        int i = t + s * 256;
        srow[s] = i / 36; scol[s] = i % 36;
        sok[s] = (i < 1296);
    }
#pragma unroll
    for (int s = 0; s < 6; s++) {
        if (sok[s]) {
            int gy = gy0 + srow[s], gx = gx0 + scol[s];
            r[s] = (gy >= 0 && gy < 512 && gx >= 0 && gx < 512)
                       ? p1[(size_t)gy * 512 + gx] : 0.0f;
        }
    }

    float acc[4][2][2];
#pragma unroll
    for (int oc = 0; oc < 4; oc++)
#pragma unroll
        for (int py = 0; py < 2; py++)
#pragma unroll
            for (int px = 0; px < 2; px++) acc[oc][py][px] = 0.0f;

    __syncthreads();

    for (int ci = 0; ci < 16; ci++) {
#pragma unroll
        for (int s = 0; s < 6; s++)
            if (sok[s]) tile[srow[s] * 38 + scol[s]] = r[s];
        __syncthreads();
        if (ci < 15) {
#pragma unroll
            for (int s = 0; s < 6; s++) {
                if (sok[s]) {
                    int gy = gy0 + srow[s], gx = gx0 + scol[s];
                    r[s] = (gy >= 0 && gy < 512 && gx >= 0 && gx < 512)
                               ? p1[((size_t)(ci + 1) * 512 + gy) * 512 + gx] : 0.0f;
                }
            }
        }
        float patch[4][4];
#pragma unroll
        for (int rw = 0; rw < 4; rw++)
#pragma unroll
            for (int c = 0; c < 4; c++)
                patch[rw][c] = tile[(2 * ty + rw) * 38 + 2 * tx + c];
#pragma unroll
        for (int oc = 0; oc < 4; oc++)
#pragma unroll
            for (int ky = 0; ky < 3; ky++)
#pragma unroll
                for (int kx = 0; kx < 3; kx++) {
                    float wv = sw[((oc * 16 + ci) * 3 + ky) * 3 + kx];
                    acc[oc][0][0] += wv * patch[ky][kx];
                    acc[oc][0][1] += wv * patch[ky][kx + 1];
                    acc[oc][1][0] += wv * patch[ky + 1][kx];
                    acc[oc][1][1] += wv * patch[ky + 1][kx + 1];
                }
        __syncthreads();
    }
    int x = blockIdx.x * 16 + tx, y = blockIdx.y * 16 + ty;
    if (x < 257 && y < 257) {
#pragma unroll
        for (int oc = 0; oc < 4; oc++) {
            float m = fmaxf(fmaxf(acc[oc][0][0], acc[oc][0][1]),
                            fmaxf(acc[oc][1][0], acc[oc][1][1])) + sb[oc];
            p2[((size_t)oc * 257 + y) * 257 + x] = fmaxf(m, 0.0f);
        }
    }
}

// ---- fused tconv1 + tconv2 + sigmoid + crop + adjacency multiply ----
// Recomputes the 16 t1 channel values on the fly from 4 p2 values (shared by both
// halves of the x-parity output pair). No t1 buffer.
template <int L>
__device__ __forceinline__ void ftconv_impl(const float* __restrict__ p2,
                                            const float* __restrict__ sw1,
                                            const float* __restrict__ sb1,
                                            const float* __restrict__ sw2,
                                            const float* __restrict__ sb2,
                                            const float* __restrict__ A,
                                            float* __restrict__ att, int idx) {
    int m = idx & 511, y = idx >> 9;
    int ky2 = (y + 1) & 1;
    int iy1 = (y - 1 + ky2) >> 1;            // t1 row (0..511)
    int ky1 = (iy1 + 1) & 1, kx1 = (m + 1) & 1;
    int iy0 = (iy1 - 1 + ky1) >> 1;          // p2 row (0..255)
    int ix0 = (m - 1 + kx1) >> 1;            // p2 col (0..255)

    float p[4];
#pragma unroll
    for (int cj = 0; cj < 4; cj++) p[cj] = p2[((size_t)cj * 257 + iy0) * 257 + ix0];

    // t1 channel values (tconv1 + relu)
    float t1v[16];
#pragma unroll
    for (int ci = 0; ci < 16; ci++) {
        float s = sb1[ci];
#pragma unroll
        for (int cj = 0; cj < 4; cj++)
            s += sw1[((ci * 4 + cj) * 2 + ky1) * 2 + kx1] * p[cj];
        t1v[ci] = fmaxf(s, 0.0f);
    }

    // tconv2 output pair (x = 2m, 2m+1) + sigmoid + adjacency multiply
#pragma unroll
    for (int l = 0; l < L; l++) {
        float s0 = sb2[l], s1 = sb2[l];
#pragma unroll
        for (int ci = 0; ci < 16; ci++) {
            float tv = t1v[ci];
            s0 += sw2[((l * 16 + ci) * 2 + ky2) * 2 + 1] * tv;
            s1 += sw2[((l * 16 + ci) * 2 + ky2) * 2 + 0] * tv;
        }
        float g0 = 1.0f / (1.0f + expf(-s0));
        float g1 = 1.0f / (1.0f + expf(-s1));
        size_t off = (size_t)l * NV * NV + (size_t)y * NV + 2 * m;
        float2 a = *(const float2*)&A[off];
        *(float2*)&att[off] = make_float2(a.x * g0, a.y * g1);
    }
}

__global__ void ftconv_att_both(FAtt fa) {
    __shared__ float sw1[256], sb1[16], sw2[192], sb2[3];
    int gidx = blockIdx.x * blockDim.x + threadIdx.x;
    const int PL = NV * 512;
    int path = gidx / PL;
    int idx = gidx - path * PL;
    const int L = (path == 0) ? 2 : 3;
    int t = threadIdx.x;
    if (t < 256) sw1[t] = fa.w1[path][t];
    if (t < 16) sb1[t] = fa.b1[path][t];
    for (int i = t; i < L * 64; i += 256) sw2[i] = fa.w2[path][i];
    if (t < L) sb2[t] = fa.b2[path][t];
    __syncthreads();
    if (path == 0) ftconv_impl<2>(fa.p2[0], sw1, sb1, sw2, sb2, fa.A[0], fa.att[0], idx);
    else           ftconv_impl<3>(fa.p2[1], sw1, sb1, sw2, sb2, fa.A[1], fa.att[1], idx);
}

// ---- row sums (self-loop fixup) -> rsqrt. grid (NV, nplanes) ----
__global__ void row_dinvN(RD2 rd) {
    int p = blockIdx.y;
    int row = blockIdx.x;
    const float* r = rd.in[p] + (size_t)row * NV;
    float s = 0.0f;
    for (int j = threadIdx.x; j < NV; j += 256) s += r[j];
    __shared__ float sh[256];
    sh[threadIdx.x] = s;
    __syncthreads();
    for (int o = 128; o > 0; o >>= 1) {
        if (threadIdx.x < o) sh[threadIdx.x] += sh[threadIdx.x + o];
        __syncthreads();
    }
    if (threadIdx.x == 0) {
        float d = sh[0];
        if (r[row] == 0.0f) d += 1.0f;
        rd.dv[p][row] = d > 0.0f ? rsqrtf(d) : 0.0f;
    }
}

// ---- dinv from GEMM-accumulated deg/diag ----
__global__ void dinv_fix(const float* __restrict__ deg, const float* __restrict__ diag,
                         float* __restrict__ dv, int n) {
    int i = blockIdx.x * blockDim.x + threadIdx.x;
    if (i < n) {
        float d = deg[i];
        if (diag[i] == 0.0f) d += 1.0f;
        dv[i] = d > 0.0f ? rsqrtf(d) : 0.0f;
    }
}

// ---- scaled max-merge + row-sum/dinv ----
__global__ void emax_dinv(const float* __restrict__ a, const float* __restrict__ dva,
                          const float* __restrict__ b, const float* __restrict__ dvb,
                          float* __restrict__ o, float* __restrict__ dv) {
    int row = blockIdx.x;
    float dar = dva[row], dbr = dvb[row];
    __shared__ float sh[256];
    __shared__ float sdiag;
    float s = 0.0f;
    for (int j = threadIdx.x; j < NV; j += 256) {
        float va = a[(size_t)row * NV + j];
        if (j == row && va == 0.0f) va = 1.0f;
        va *= dar * dva[j];
        float vb = b[(size_t)row * NV + j];
        if (j == row && vb == 0.0f) vb = 1.0f;
        vb *= dbr * dvb[j];
        float v = fmaxf(va, vb);
        o[(size_t)row * NV + j] = v;
        if (j == row) sdiag = v;
        s += v;
    }
    sh[threadIdx.x] = s;
    __syncthreads();
    for (int off = 128; off > 0; off >>= 1) {
        if (threadIdx.x < off) sh[threadIdx.x] += sh[threadIdx.x + off];
        __syncthreads();
    }
    if (threadIdx.x == 0) {
        float d = sh[0];
        if (sdiag == 0.0f) d += 1.0f;
        dv[row] = d > 0.0f ? rsqrtf(d) : 0.0f;
    }
}

__global__ void bias_relu64(float* __restrict__ H, const float* __restrict__ bias) {
    int idx = blockIdx.x * blockDim.x + threadIdx.x;
    if (idx < NV * HIDD) H[idx] = fmaxf(H[idx] + bias[idx & (HIDD - 1)], 0.0f);
}

// ---------------- tf32 GEMM with fused gcn-norm on A + deg/diag epilogue ----------------
__device__ __forceinline__ uint32_t f2tf(float f) {
    uint32_t r;
    asm("cvt.rna.tf32.f32 %0, %1;" : "=r"(r) : "f"(f));
    return r;
}

__device__ __forceinline__ void fix_scale4(float4& v, int row, int kc, float dvr,
                                           const float* __restrict__ dv) {
    float4 dk = *(const float4*)&dv[kc];
    float* p = &v.x;
#pragma unroll
    for (int q = 0; q < 4; q++)
        if (row == kc + q && p[q] == 0.0f) p[q] = 1.0f;
    v.x *= dvr * dk.x; v.y *= dvr * dk.y; v.z *= dvr * dk.z; v.w *= dvr * dk.w;
}

__global__ void __launch_bounds__(256) tf32gemm_s(GemS g) {
    const float* __restrict__ A = g.A[blockIdx.z];
    const float* __restrict__ B = g.B[blockIdx.z];
    float* __restrict__ C = g.C[blockIdx.z];
    const float* __restrict__ dv = g.dv[blockIdx.z];
    float* __restrict__ deg = g.deg[blockIdx.z];
    float* __restrict__ diag = g.diag[blockIdx.z];
    const int Nn = NV, K = NV;

    __shared__ float As[2][16][136];
    __shared__ float Bs[2][16][72];

    const int tid = threadIdx.x;
    const int lane = tid & 31;
    const int wid = tid >> 5;
    const int wr = wid & 3;
    const int wc = wid >> 2;
    const int m0 = blockIdx.y * 128;
    const int n0 = blockIdx.x * 64;

    float acc[2][4][4];
#pragma unroll
    for (int mi = 0; mi < 2; mi++)
#pragma unroll
        for (int ni = 0; ni < 4; ni++)
#pragma unroll
            for (int r = 0; r < 4; r++) acc[mi][ni][r] = 0.0f;

    const int ar = tid >> 2;
    const int ac4 = (tid & 3) << 2;
    const int bk = tid >> 4;
    const int bn4 = (tid & 15) << 2;
    const int rowA0 = m0 + ar, rowA1 = m0 + 64 + ar;
    const float dvr0 = dv[rowA0], dvr1 = dv[rowA1];

    float4 av0, av1, bv;
    const int T = K >> 4;

    av0 = *(const float4*)&A[(size_t)rowA0 * K + ac4];
    av1 = *(const float4*)&A[(size_t)rowA1 * K + ac4];
    bv  = *(const float4*)&B[(size_t)bk * Nn + n0 + bn4];
    fix_scale4(av0, rowA0, ac4, dvr0, dv);
    fix_scale4(av1, rowA1, ac4, dvr1, dv);

    As[0][ac4 + 0][ar] = __uint_as_float(f2tf(av0.x));
    As[0][ac4 + 1][ar] = __uint_as_float(f2tf(av0.y));
    As[0][ac4 + 2][ar] = __uint_as_float(f2tf(av0.z));
    As[0][ac4 + 3][ar] = __uint_as_float(f2tf(av0.w));
    As[0][ac4 + 0][ar + 64] = __uint_as_float(f2tf(av1.x));
    As[0][ac4 + 1][ar + 64] = __uint_as_float(f2tf(av1.y));
    As[0][ac4 + 2][ar + 64] = __uint_as_float(f2tf(av1.z));
    As[0][ac4 + 3][ar + 64] = __uint_as_float(f2tf(av1.w));
    {
        float4 bt;
        bt.x = __uint_as_float(f2tf(bv.x));
        bt.y = __uint_as_float(f2tf(bv.y));
        bt.z = __uint_as_float(f2tf(bv.z));
        bt.w = __uint_as_float(f2tf(bv.w));
        *(float4*)&Bs[0][bk][bn4] = bt;
    }
    __syncthreads();

    for (int t = 0; t < T; t++) {
        int cur = t & 1;
        if (t + 1 < T) {
            int kb = (t + 1) << 4;
            av0 = *(const float4*)&A[(size_t)rowA0 * K + kb + ac4];
            av1 = *(const float4*)&A[(size_t)rowA1 * K + kb + ac4];
            bv  = *(const float4*)&B[(size_t)(kb + bk) * Nn + n0 + bn4];
            fix_scale4(av0, rowA0, kb + ac4, dvr0, dv);
            fix_scale4(av1, rowA1, kb + ac4, dvr1, dv);
        }
#pragma unroll
        for (int ks = 0; ks < 2; ks++) {
            const int k0 = ks * 8;
            uint32_t a[2][4], b[4][2];
            const int kl = k0 + (lane & 3);
            const int rl = lane >> 2;
#pragma unroll
            for (int mi = 0; mi < 2; mi++) {
                int m = wr * 32 + mi * 16 + rl;
                a[mi][0] = __float_as_uint(As[cur][kl][m]);
                a[mi][1] = __float_as_uint(As[cur][kl][m + 8]);
                a[mi][2] = __float_as_uint(As[cur][kl + 4][m]);
                a[mi][3] = __float_as_uint(As[cur][kl + 4][m + 8]);
            }
#pragma unroll
            for (int ni = 0; ni < 4; ni++) {
                int n = wc * 32 + ni * 8 + rl;
                b[ni][0] = __float_as_uint(Bs[cur][kl][n]);
                b[ni][1] = __float_as_uint(Bs[cur][kl + 4][n]);
            }
#pragma unroll
            for (int mi = 0; mi < 2; mi++)
#pragma unroll
                for (int ni = 0; ni < 4; ni++) {
                    asm volatile(
                        "mma.sync.aligned.m16n8k8.row.col.f32.tf32.tf32.f32 "
                        "{%0,%1,%2,%3}, {%4,%5,%6,%7}, {%8,%9}, {%0,%1,%2,%3};"
                        : "+f"(acc[mi][ni][0]), "+f"(acc[mi][ni][1]),
                          "+f"(acc[mi][ni][2]), "+f"(acc[mi][ni][3])
                        : "r"(a[mi][0]), "r"(a[mi][1]), "r"(a[mi][2]), "r"(a[mi][3]),
                          "r"(b[ni][0]), "r"(b[ni][1]));
                }
        }
        if (t + 1 < T) {
            int nxt = (t + 1) & 1;
            As[nxt][ac4 + 0][ar] = __uint_as_float(f2tf(av0.x));
            As[nxt][ac4 + 1][ar] = __uint_as_float(f2tf(av0.y));
            As[nxt][ac4 + 2][ar] = __uint_as_float(f2tf(av0.z));
            As[nxt][ac4 + 3][ar] = __uint_as_float(f2tf(av0.w));
            As[nxt][ac4 + 0][ar + 64] = __uint_as_float(f2tf(av1.x));
            As[nxt][ac4 + 1][ar + 64] = __uint_as_float(f2tf(av1.y));
            As[nxt][ac4 + 2][ar + 64] = __uint_as_float(f2tf(av1.z));
            As[nxt][ac4 + 3][ar + 64] = __uint_as_float(f2tf(av1.w));
            float4 bt;
            bt.x = __uint_as_float(f2tf(bv.x));
            bt.y = __uint_as_float(f2tf(bv.y));
            bt.z = __uint_as_float(f2tf(bv.z));
            bt.w = __uint_as_float(f2tf(bv.w));
            *(float4*)&Bs[nxt][bk][bn4] = bt;
            __syncthreads();
        }
    }

    const int rl = lane >> 2;
#pragma unroll
    for (int mi = 0; mi < 2; mi++) {
        int row = m0 + wr * 32 + mi * 16 + rl;
#pragma unroll
        for (int ni = 0; ni < 4; ni++) {
            int col = n0 + wc * 32 + ni * 8 + ((lane & 3) << 1);
            if (row == col) diag[row] = acc[mi][ni][0];
            if (row == col + 1) diag[row] = acc[mi][ni][1];
            if (row + 8 == col) diag[row + 8] = acc[mi][ni][2];
            if (row + 8 == col + 1) diag[row + 8] = acc[mi][ni][3];
            *(float2*)&C[(size_t)row * Nn + col] = make_float2(acc[mi][ni][0], acc[mi][ni][1]);
            *(float2*)&C[(size_t)(row + 8) * Nn + col] = make_float2(acc[mi][ni][2], acc[mi][ni][3]);
        }
    }
    float rs[4] = {0.0f, 0.0f, 0.0f, 0.0f};
#pragma unroll
    for (int mi = 0; mi < 2; mi++)
#pragma unroll
        for (int ni = 0; ni < 4; ni++) {
            rs[mi * 2 + 0] += acc[mi][ni][0] + acc[mi][ni][1];
            rs[mi * 2 + 1] += acc[mi][ni][2] + acc[mi][ni][3];
        }
#pragma unroll
    for (int q = 0; q < 4; q++) {
        rs[q] += __shfl_xor_sync(0xFFFFFFFF, rs[q], 1);
        rs[q] += __shfl_xor_sync(0xFFFFFFFF, rs[q], 2);
    }
    if ((lane & 3) == 0) {
        int rbase = m0 + wr * 32 + rl;
        atomicAdd(&deg[rbase], rs[0]);
        atomicAdd(&deg[rbase + 8], rs[1]);
        atomicAdd(&deg[rbase + 16], rs[2]);
        atomicAdd(&deg[rbase + 24], rs[3]);
    }
}

// plain fp32 64x64 tile GEMM (tiny x@w1, H@w2)
__global__ void sgemm64(const float* __restrict__ A, const float* __restrict__ B,
                        float* __restrict__ C, int M, int Nn, int K) {
    __shared__ float As[16][64];
    __shared__ float Bs[16][64];
    int tx = threadIdx.x, ty = threadIdx.y;
    int tid = ty * 16 + tx;
    int m0 = blockIdx.y * 64, n0 = blockIdx.x * 64;
    float acc[4][4];
#pragma unroll
    for (int i = 0; i < 4; i++)
#pragma unroll
        for (int j = 0; j < 4; j++) acc[i][j] = 0.0f;
    int la_r = tid / 16, la_k = tid % 16;
    int lb_k = tid / 64, lb_n = tid % 64;
    for (int k0 = 0; k0 < K; k0 += 16) {
#pragma unroll
        for (int r = 0; r < 4; r++)
            As[la_k][la_r + 16 * r] = A[(size_t)(m0 + la_r + 16 * r) * K + k0 + la_k];
#pragma unroll
        for (int r = 0; r < 4; r++) {
            int kk = lb_k + 4 * r;
            Bs[kk][lb_n] = (n0 + lb_n < Nn) ? B[(size_t)(k0 + kk) * Nn + n0 + lb_n] : 0.0f;
        }
        __syncthreads();
#pragma unroll
        for (int k = 0; k < 16; k++) {
            float a[4], b[4];
#pragma unroll
            for (int i = 0; i < 4; i++) a[i] = As[k][ty * 4 + i];
#pragma unroll
            for (int j = 0; j < 4; j++) b[j] = Bs[k][tx * 4 + j];
#pragma unroll
            for (int i = 0; i < 4; i++)
#pragma unroll
                for (int j = 0; j < 4; j++) acc[i][j] += a[i] * b[j];
        }
        __syncthreads();
    }
#pragma unroll
    for (int i = 0; i < 4; i++) {
        int row = m0 + ty * 4 + i;
#pragma unroll
        for (int j = 0; j < 4; j++) {
            int col = n0 + tx * 4 + j;
            if (col < Nn) C[(size_t)row * Nn + col] = acc[i][j];
        }
    }
}

// split-K fp32 GEMM with fused gcn-norm on A: C += (Dv fix(A) Dv) @ B.
__global__ void sgemmKS(const float* __restrict__ A, const float* __restrict__ dv,
                        const float* __restrict__ B, float* __restrict__ C,
                        int Nn, int K, int KS, const float* __restrict__ bias) {
    __shared__ float As[16][64];
    __shared__ float Bs[16][64];
    int tx = threadIdx.x, ty = threadIdx.y;
    int tid = ty * 16 + tx;
    int m0 = blockIdx.y * 64;
    int kLen = K / KS;
    int kStart = blockIdx.x * kLen;
    float acc[4][4];
#pragma unroll
    for (int i = 0; i < 4; i++)
#pragma unroll
        for (int j = 0; j < 4; j++) acc[i][j] = 0.0f;
    int la_r = tid / 16, la_k = tid % 16;
    int lb_k = tid / 64, lb_n = tid % 64;
    for (int k0 = kStart; k0 < kStart + kLen; k0 += 16) {
#pragma unroll
        for (int r = 0; r < 4; r++) {
            int row = m0 + la_r + 16 * r;
            int kc = k0 + la_k;
            float v = A[(size_t)row * K + kc];
            if (row == kc && v == 0.0f) v = 1.0f;
            As[la_k][la_r + 16 * r] = v * dv[row] * dv[kc];
        }
#pragma unroll
        for (int r = 0; r < 4; r++) {
            int kk = lb_k + 4 * r;
            Bs[kk][lb_n] = (lb_n < Nn) ? B[(size_t)(k0 + kk) * Nn + lb_n] : 0.0f;
        }
        __syncthreads();
#pragma unroll
        for (int k = 0; k < 16; k++) {
            float a[4], b[4];
#pragma unroll
            for (int i = 0; i < 4; i++) a[i] = As[k][ty * 4 + i];
#pragma unroll
            for (int j = 0; j < 4; j++) b[j] = Bs[k][tx * 4 + j];
#pragma unroll
            for (int i = 0; i < 4; i++)
#pragma unroll
                for (int j = 0; j < 4; j++) acc[i][j] += a[i] * b[j];
        }
        __syncthreads();
    }
#pragma unroll
    for (int i = 0; i < 4; i++) {
        int row = m0 + ty * 4 + i;
#pragma unroll
        for (int j = 0; j < 4; j++) {
            int col = tx * 4 + j;
            if (col < Nn) {
                float v = acc[i][j];
                if (bias != nullptr && kStart == 0) v += bias[col];
                atomicAdd(&C[(size_t)row * Nn + col], v);
            }
        }
    }
}

// ---------------- host orchestration ----------------

extern "C" void kernel_launch(void* const* d_in, const int* in_sizes, int n_in,
                              void* d_out, int out_size) {
    const float* x = (const float*)d_in[0];
    const int* edges[5];
    for (int i = 0; i < 5; i++) edges[i] = (const int*)d_in[1 + i];
    const float* pbp[2][8];
    for (int b = 0; b < 2; b++)
        for (int i = 0; i < 8; i++) pbp[b][i] = (const float*)d_in[6 + b * 8 + i];
    const float* w1    = (const float*)d_in[22];
    const float* bias1 = (const float*)d_in[23];
    const float* w2    = (const float*)d_in[24];
    const float* bias2 = (const float*)d_in[25];
    float* out = (float*)d_out;

    float *A_, *p1_, *p2_, *att_, *M_, *Mt_, *An_, *dinv_, *deg_, *diag_, *XW_, *H_, *HW_;
    cudaGetSymbolAddress((void**)&A_,    g_A);
    cudaGetSymbolAddress((void**)&p1_,   g_p1);
    cudaGetSymbolAddress((void**)&p2_,   g_p2);
    cudaGetSymbolAddress((void**)&att_,  g_att);
    cudaGetSymbolAddress((void**)&M_,    g_M);
    cudaGetSymbolAddress((void**)&Mt_,   g_Mt);
    cudaGetSymbolAddress((void**)&An_,   g_An);
    cudaGetSymbolAddress((void**)&dinv_, g_dinv);
    cudaGetSymbolAddress((void**)&deg_,  g_deg);
    cudaGetSymbolAddress((void**)&diag_, g_diag);
    cudaGetSymbolAddress((void**)&XW_,   g_XW);
    cudaGetSymbolAddress((void**)&H_,    g_H);
    cudaGetSymbolAddress((void**)&HW_,   g_HW);

    const size_t PLANE = (size_t)NV * NV;
    dim3 blk16(16, 16);

    float* Ab[2]   = { A_,   A_   + 3 * PLANE };
    float* p1b[2]  = { p1_,  p1_  + (size_t)16 * 512 * 512 };
    float* p2b[2]  = { p2_,  p2_  + (size_t)4 * 257 * 257 };
    float* attb[2] = { att_, att_ + 3 * PLANE };
    float* Mb[2]   = { M_,   M_   + PLANE };
    float* Mtb[2]  = { Mt_,  Mt_  + PLANE };

    // -------- setup --------
    cudaMemsetAsync(A_, 0, 6 * PLANE * sizeof(float), 0);
    cudaMemsetAsync(deg_, 0, 3 * NV * sizeof(float), 0);
    cudaMemsetAsync(H_, 0, (size_t)NV * HIDD * sizeof(float), 0);
    cudaMemsetAsync(out, 0, (size_t)NV * REPD * sizeof(float), 0);
    sgemm64<<<dim3(1, NV / 64), blk16>>>(x, w1, XW_, NV, HIDD, EMBD);

    // -------- scatter all 5 edge lists --------
    Sc5 sc;
    sc.e[0] = edges[0]; sc.A[0] = Ab[0];
    sc.e[1] = edges[1]; sc.A[1] = Ab[0] + PLANE;
    sc.e[2] = edges[2]; sc.A[2] = Ab[1];
    sc.e[3] = edges[3]; sc.A[3] = Ab[1] + PLANE;
    sc.e[4] = edges[4]; sc.A[4] = Ab[1] + 2 * PLANE;
    scatter_all<<<dim3((NE + 255) / 256, 5), 256>>>(sc);

    // -------- conv encoder (both paths batched) --------
    PathPtrs c1 = {{Ab[0], Ab[1]}, {pbp[0][0], pbp[1][0]}, {pbp[0][1], pbp[1][1]}, {p1b[0], p1b[1]}};
    conv1pool_both<<<dim3(32, 32, 2), blk16>>>(c1);

    PathPtrs c2 = {{p1b[0], p1b[1]}, {pbp[0][2], pbp[1][2]}, {pbp[0][3], pbp[1][3]}, {p2b[0], p2b[1]}};
    conv2pool_both<<<dim3(17, 17, 2), blk16>>>(c2);

    // fused tconv1 + tconv2 + sigmoid + adjacency multiply
    FAtt fa;
    for (int p = 0; p < 2; p++) {
        fa.p2[p] = p2b[p];
        fa.w1[p] = pbp[p][4]; fa.b1[p] = pbp[p][5];
        fa.w2[p] = pbp[p][6]; fa.b2[p] = pbp[p][7];
        fa.A[p] = Ab[p]; fa.att[p] = attb[p];
    }
    ftconv_att_both<<<(2 * NV * 512) / 256, 256>>>(fa);

    // -------- M-chain, norms fused into GEMMs --------
    {
        RD2 rd = {{attb[0], attb[1]}, {dinv_, dinv_ + NV}};
        row_dinvN<<<dim3(NV, 2), 256>>>(rd);
    }
    {
        GemS gs;
        gs.A[0] = attb[0];         gs.A[1] = attb[1];
        gs.B[0] = attb[0] + PLANE; gs.B[1] = attb[1] + PLANE;
        gs.C[0] = Mtb[0];          gs.C[1] = Mtb[1];
        gs.dv[0] = dinv_;          gs.dv[1] = dinv_ + NV;
        gs.deg[0] = deg_;          gs.deg[1] = deg_ + NV;
        gs.diag[0] = diag_;        gs.diag[1] = diag_ + NV;
        tf32gemm_s<<<dim3(NV / 64, NV / 128, 2), 256>>>(gs);
        dinv_fix<<<(2 * NV + 255) / 256, 256>>>(deg_, diag_, dinv_ + 2 * NV, 2 * NV);
    }
    {
        GemS gs;
        gs.A[0] = Mtb[1];
        gs.B[0] = attb[1] + 2 * PLANE;
        gs.C[0] = Mb[1];
        gs.dv[0] = dinv_ + 3 * NV;
        gs.deg[0] = deg_ + 2 * NV;
        gs.diag[0] = diag_ + 2 * NV;
        gs.A[1] = gs.A[0]; gs.B[1] = gs.B[0]; gs.C[1] = gs.C[0];
        gs.dv[1] = gs.dv[0]; gs.deg[1] = gs.deg[0]; gs.diag[1] = gs.diag[0];
        tf32gemm_s<<<dim3(NV / 64, NV / 128, 1), 256>>>(gs);
        dinv_fix<<<(NV + 255) / 256, 256>>>(deg_ + 2 * NV, diag_ + 2 * NV, dinv_ + 4 * NV, NV);
    }

    // -------- scaled merge + final dinv --------
    emax_dinv<<<NV, 256>>>(Mtb[0], dinv_ + 2 * NV, Mb[1], dinv_ + 4 * NV, An_, dinv_ + 5 * NV);

    // -------- GCN layers, final norm fused into A-loads --------
    sgemmKS<<<dim3(8, NV / 64), blk16>>>(An_, dinv_ + 5 * NV, XW_, H_, HIDD, NV, 8, nullptr);
    bias_relu64<<<(NV * HIDD + 255) / 256, 256>>>(H_, bias1);
    sgemm64<<<dim3(1, NV / 64), blk16>>>(H_, w2, HW_, NV, REPD, HIDD);
    sgemmKS<<<dim3(8, NV / 64), blk16>>>(An_, dinv_ + 5 * NV, HW_, out, REPD, NV, 8, bias2);
}

// round 7
// speedup vs baseline: 2.1561x; 1.0157x over previous
#include <cuda_runtime.h>
#include <math.h>
#include <stdint.h>

// Problem constants
#define NV 1024
#define NE 32768
#define EMBD 128
#define HIDD 64
#define REPD 32

// ---------------- scratch (static device globals) ----------------
__device__ float g_A[2][3][NV][NV];
__device__ float g_p1[2][16][512][512];
__device__ float g_p2[2][4][257][257];
__device__ float g_att[2][3][NV][NV];
__device__ float g_M[2][NV][NV];
__device__ float g_Mt[2][NV][NV];
__device__ float g_An[NV][NV];
__device__ float g_dinv[6][NV];   // 0,1: att0 p0/p1; 2,3: hop1 p0/p1; 4: hop2; 5: final
__device__ float g_deg[5][NV];    // 0,1: att0 (fused in ftconv); 2,3: hop1; 4: hop2
__device__ float g_diag[5][NV];
__device__ float g_XW[NV][HIDD];
__device__ float g_H[NV][HIDD];
__device__ float g_HW[NV][REPD];

// ---------------- param structs ----------------
struct Sc5 { const int* e[5]; float* A[5]; };
struct PathPtrs {
    const float* in[2]; const float* w[2]; const float* b[2]; float* out[2];
};
struct FAtt {
    const float* p2[2]; const float* w1[2]; const float* b1[2];
    const float* w2[2]; const float* b2[2]; const float* A[2]; float* att[2];
    float* deg[2]; float* diag[2];
};
struct GemS {
    const float* A[2]; const float* B[2]; float* C[2];
    const float* dv[2]; float* deg[2]; float* diag[2];
};

// ---------------- kernels ----------------

__global__ void scatter_all(Sc5 s) {
    int j = blockIdx.y;
    int k = blockIdx.x * blockDim.x + threadIdx.x;
    if (k < NE) {
        const int* e = s.e[j];
        atomicAdd(&s.A[j][e[k] * NV + e[NE + k]], 1.0f);
    }
}

// ---- conv1 (3x3, pad1, L->16) + relu + maxpool2, smem-tiled, weight-hoisted ----
template <int L>
__device__ __forceinline__ void conv1_compute(const float* __restrict__ tile,
                                              const float* __restrict__ sw,
                                              const float* __restrict__ sb,
                                              float* __restrict__ p1,
                                              int tx, int ty, int ox, int oy) {
    float patch[L][4][4];
#pragma unroll
    for (int l = 0; l < L; l++)
#pragma unroll
        for (int r = 0; r < 4; r++)
#pragma unroll
            for (int c = 0; c < 4; c++)
                patch[l][r][c] = tile[(l * 34 + 2 * ty + r) * 36 + 2 * tx + c];
#pragma unroll
    for (int oc = 0; oc < 16; oc++) {
        float b = sb[oc];
        float s00 = b, s01 = b, s10 = b, s11 = b;
#pragma unroll
        for (int l = 0; l < L; l++)
#pragma unroll
            for (int ky = 0; ky < 3; ky++)
#pragma unroll
                for (int kx = 0; kx < 3; kx++) {
                    float w = sw[((oc * L + l) * 3 + ky) * 3 + kx];
                    s00 += w * patch[l][ky][kx];
                    s01 += w * patch[l][ky][kx + 1];
                    s10 += w * patch[l][ky + 1][kx];
                    s11 += w * patch[l][ky + 1][kx + 1];
                }
        float m = fmaxf(fmaxf(fmaxf(s00, s01), fmaxf(s10, s11)), 0.0f);
        p1[((size_t)oc * 512 + oy) * 512 + ox] = m;
    }
}

__global__ void conv1pool_both(PathPtrs p) {
    __shared__ float tile[3 * 34 * 36];
    __shared__ float sw[16 * 3 * 9];
    __shared__ float sb[16];
    int path = blockIdx.z;
    const int L = (path == 0) ? 2 : 3;
    const float* A = p.in[path];
    const float* w = p.w[path];
    int tx = threadIdx.x, ty = threadIdx.y;
    int t = ty * 16 + tx;
    for (int i = t; i < 16 * L * 9; i += 256) sw[i] = w[i];
    if (t < 16) sb[t] = p.b[path][t];

    int gy0 = blockIdx.y * 32 - 1, gx0 = blockIdx.x * 32 - 1;
    for (int l = 0; l < L; l++)
        for (int i = t; i < 34 * 34; i += 256) {
            int r = i / 34, c = i % 34;
            int gy = gy0 + r, gx = gx0 + c;
            tile[(l * 34 + r) * 36 + c] = (gy >= 0 && gy < NV && gx >= 0 && gx < NV)
                                              ? A[((size_t)l * NV + gy) * NV + gx] : 0.0f;
        }
    __syncthreads();
    int ox = blockIdx.x * 16 + tx, oy = blockIdx.y * 16 + ty;
    if (path == 0) conv1_compute<2>(tile, sw, sb, p.out[0], tx, ty, ox, oy);
    else           conv1_compute<3>(tile, sw, sb, p.out[1], tx, ty, ox, oy);
}

// ---- conv2 (3x3, pad2, 16->4) + relu + maxpool2 ----
// 4 channels staged per smem phase (8 syncs total), 21-slot register prefetch.
#define C2_SLOTS 21
__global__ void conv2pool_both(PathPtrs pp) {
    __shared__ float tile[4 * 1368];   // 4 x (36*38)
    __shared__ float sw[576];
    __shared__ float sb[4];
    int path = blockIdx.z;
    const float* p1 = pp.in[path];
    float* p2 = pp.out[path];
    int tx = threadIdx.x, ty = threadIdx.y;
    int t = ty * 16 + tx;
    for (int i = t; i < 576; i += 256) sw[i] = pp.w[path][i];
    if (t < 4) sb[t] = pp.b[path][t];

    int gy0 = blockIdx.y * 32 - 2, gx0 = blockIdx.x * 32 - 2;

    // per-slot offsets (5184 = 4 ch * 1296 staged elements)
    int soff[C2_SLOTS], goff[C2_SLOTS];
    unsigned vmask = 0;   // in-bounds
    unsigned emask = 0;   // slot exists
#pragma unroll
    for (int s = 0; s < C2_SLOTS; s++) {
        int i = t + s * 256;
        if (i < 5184) {
            emask |= 1u << s;
            int ch = i / 1296, rem = i - ch * 1296;
            int row = rem / 36, col = rem - row * 36;
            int gy = gy0 + row, gx = gx0 + col;
            soff[s] = ch * 1368 + row * 38 + col;
            goff[s] = (ch * 512 + gy) * 512 + gx;
            if (gy >= 0 && gy < 512 && gx >= 0 && gx < 512) vmask |= 1u << s;
        }
    }

    float r[C2_SLOTS];
    // prefetch group 0 (channels 0..3)
#pragma unroll
    for (int s = 0; s < C2_SLOTS; s++)
        if (emask & (1u << s))
            r[s] = (vmask & (1u << s)) ? p1[goff[s]] : 0.0f;

    float acc[4][2][2];
#pragma unroll
    for (int oc = 0; oc < 4; oc++)
#pragma unroll
        for (int py = 0; py < 2; py++)
#pragma unroll
            for (int px = 0; px < 2; px++) acc[oc][py][px] = 0.0f;

    __syncthreads();   // weights ready

    for (int g = 0; g < 4; g++) {
#pragma unroll
        for (int s = 0; s < C2_SLOTS; s++)
            if (emask & (1u << s)) tile[soff[s]] = r[s];
        __syncthreads();
        if (g < 3) {
            const float* pg = p1 + (size_t)(g + 1) * 4 * 512 * 512;
#pragma unroll
            for (int s = 0; s < C2_SLOTS; s++)
                if (emask & (1u << s))
                    r[s] = (vmask & (1u << s)) ? pg[goff[s]] : 0.0f;
        }
#pragma unroll
        for (int cc = 0; cc < 4; cc++) {
            int ci = g * 4 + cc;
            float patch[4][4];
#pragma unroll
            for (int rw = 0; rw < 4; rw++)
#pragma unroll
                for (int c = 0; c < 4; c++)
                    patch[rw][c] = tile[cc * 1368 + (2 * ty + rw) * 38 + 2 * tx + c];
#pragma unroll
            for (int oc = 0; oc < 4; oc++)
#pragma unroll
                for (int ky = 0; ky < 3; ky++)
#pragma unroll
                    for (int kx = 0; kx < 3; kx++) {
                        float wv = sw[((oc * 16 + ci) * 3 + ky) * 3 + kx];
                        acc[oc][0][0] += wv * patch[ky][kx];
                        acc[oc][0][1] += wv * patch[ky][kx + 1];
                        acc[oc][1][0] += wv * patch[ky + 1][kx];
                        acc[oc][1][1] += wv * patch[ky + 1][kx + 1];
                    }
        }
        __syncthreads();
    }
    int x = blockIdx.x * 16 + tx, y = blockIdx.y * 16 + ty;
    if (x < 257 && y < 257) {
#pragma unroll
        for (int oc = 0; oc < 4; oc++) {
            float m = fmaxf(fmaxf(acc[oc][0][0], acc[oc][0][1]),
                            fmaxf(acc[oc][1][0], acc[oc][1][1])) + sb[oc];
            p2[((size_t)oc * 257 + y) * 257 + x] = fmaxf(m, 0.0f);
        }
    }
}

// ---- fused tconv1 + tconv2 + sigmoid + crop + adjacency multiply + att0 deg/diag ----
template <int L>
__device__ __forceinline__ void ftconv_impl(const float* __restrict__ p2,
                                            const float* __restrict__ sw1,
                                            const float* __restrict__ sb1,
                                            const float* __restrict__ sw2,
                                            const float* __restrict__ sb2,
                                            const float* __restrict__ A,
                                            float* __restrict__ att,
                                            float* __restrict__ deg,
                                            float* __restrict__ diag, int idx) {
    int m = idx & 511, y = idx >> 9;
    int ky2 = (y + 1) & 1;
    int iy1 = (y - 1 + ky2) >> 1;
    int ky1 = (iy1 + 1) & 1, kx1 = (m + 1) & 1;
    int iy0 = (iy1 - 1 + ky1) >> 1;
    int ix0 = (m - 1 + kx1) >> 1;

    float p[4];
#pragma unroll
    for (int cj = 0; cj < 4; cj++) p[cj] = p2[((size_t)cj * 257 + iy0) * 257 + ix0];

    float t1v[16];
#pragma unroll
    for (int ci = 0; ci < 16; ci++) {
        float s = sb1[ci];
#pragma unroll
        for (int cj = 0; cj < 4; cj++)
            s += sw1[((ci * 4 + cj) * 2 + ky1) * 2 + kx1] * p[cj];
        t1v[ci] = fmaxf(s, 0.0f);
    }

    float a0v0 = 0.0f, a0v1 = 0.0f;
#pragma unroll
    for (int l = 0; l < L; l++) {
        float s0 = sb2[l], s1 = sb2[l];
#pragma unroll
        for (int ci = 0; ci < 16; ci++) {
            float tv = t1v[ci];
            s0 += sw2[((l * 16 + ci) * 2 + ky2) * 2 + 1] * tv;
            s1 += sw2[((l * 16 + ci) * 2 + ky2) * 2 + 0] * tv;
        }
        float g0 = 1.0f / (1.0f + expf(-s0));
        float g1 = 1.0f / (1.0f + expf(-s1));
        size_t off = (size_t)l * NV * NV + (size_t)y * NV + 2 * m;
        float2 a = *(const float2*)&A[off];
        float v0 = a.x * g0, v1 = a.y * g1;
        *(float2*)&att[off] = make_float2(v0, v1);
        if (l == 0) { a0v0 = v0; a0v1 = v1; }
    }

    // att0 row-sum (warp covers 32 consecutive m of the same row) + diag capture
    float s = a0v0 + a0v1;
#pragma unroll
    for (int o = 16; o > 0; o >>= 1) s += __shfl_xor_sync(0xFFFFFFFF, s, o);
    if ((threadIdx.x & 31) == 0) atomicAdd(&deg[y], s);
    if (2 * m == y) diag[y] = a0v0;
    else if (2 * m + 1 == y) diag[y] = a0v1;
}

__global__ void ftconv_att_both(FAtt fa) {
    __shared__ float sw1[256], sb1[16], sw2[192], sb2[3];
    int gidx = blockIdx.x * blockDim.x + threadIdx.x;
    const int PL = NV * 512;
    int path = gidx / PL;
    int idx = gidx - path * PL;
    const int L = (path == 0) ? 2 : 3;
    int t = threadIdx.x;
    if (t < 256) sw1[t] = fa.w1[path][t];
    if (t < 16) sb1[t] = fa.b1[path][t];
    for (int i = t; i < L * 64; i += 256) sw2[i] = fa.w2[path][i];
    if (t < L) sb2[t] = fa.b2[path][t];
    __syncthreads();
    if (path == 0)
        ftconv_impl<2>(fa.p2[0], sw1, sb1, sw2, sb2, fa.A[0], fa.att[0],
                       fa.deg[0], fa.diag[0], idx);
    else
        ftconv_impl<3>(fa.p2[1], sw1, sb1, sw2, sb2, fa.A[1], fa.att[1],
                       fa.deg[1], fa.diag[1], idx);
}

// ---- dinv from accumulated deg/diag ----
__global__ void dinv_fix(const float* __restrict__ deg, const float* __restrict__ diag,
                         float* __restrict__ dv, int n) {
    int i = blockIdx.x * blockDim.x + threadIdx.x;
    if (i < n) {
        float d = deg[i];
        if (diag[i] == 0.0f) d += 1.0f;
        dv[i] = d > 0.0f ? rsqrtf(d) : 0.0f;
    }
}

// ---- scaled max-merge + row-sum/dinv ----
__global__ void emax_dinv(const float* __restrict__ a, const float* __restrict__ dva,
                          const float* __restrict__ b, const float* __restrict__ dvb,
                          float* __restrict__ o, float* __restrict__ dv) {
    int row = blockIdx.x;
    float dar = dva[row], dbr = dvb[row];
    __shared__ float sh[256];
    __shared__ float sdiag;
    float s = 0.0f;
    for (int j = threadIdx.x; j < NV; j += 256) {
        float va = a[(size_t)row * NV + j];
        if (j == row && va == 0.0f) va = 1.0f;
        va *= dar * dva[j];
        float vb = b[(size_t)row * NV + j];
        if (j == row && vb == 0.0f) vb = 1.0f;
        vb *= dbr * dvb[j];
        float v = fmaxf(va, vb);
        o[(size_t)row * NV + j] = v;
        if (j == row) sdiag = v;
        s += v;
    }
    sh[threadIdx.x] = s;
    __syncthreads();
    for (int off = 128; off > 0; off >>= 1) {
        if (threadIdx.x < off) sh[threadIdx.x] += sh[threadIdx.x + off];
        __syncthreads();
    }
    if (threadIdx.x == 0) {
        float d = sh[0];
        if (sdiag == 0.0f) d += 1.0f;
        dv[row] = d > 0.0f ? rsqrtf(d) : 0.0f;
    }
}

__global__ void bias_relu64(float* __restrict__ H, const float* __restrict__ bias) {
    int idx = blockIdx.x * blockDim.x + threadIdx.x;
    if (idx < NV * HIDD) H[idx] = fmaxf(H[idx] + bias[idx & (HIDD - 1)], 0.0f);
}

// ---------------- tf32 GEMM with fused gcn-norm on A + deg/diag epilogue ----------------
__device__ __forceinline__ uint32_t f2tf(float f) {
    uint32_t r;
    asm("cvt.rna.tf32.f32 %0, %1;" : "=r"(r) : "f"(f));
    return r;
}

__device__ __forceinline__ void fix_scale4(float4& v, int row, int kc, float dvr,
                                           const float* __restrict__ dv) {
    float4 dk = *(const float4*)&dv[kc];
    float* p = &v.x;
#pragma unroll
    for (int q = 0; q < 4; q++)
        if (row == kc + q && p[q] == 0.0f) p[q] = 1.0f;
    v.x *= dvr * dk.x; v.y *= dvr * dk.y; v.z *= dvr * dk.z; v.w *= dvr * dk.w;
}

__global__ void __launch_bounds__(256) tf32gemm_s(GemS g) {
    const float* __restrict__ A = g.A[blockIdx.z];
    const float* __restrict__ B = g.B[blockIdx.z];
    float* __restrict__ C = g.C[blockIdx.z];
    const float* __restrict__ dv = g.dv[blockIdx.z];
    float* __restrict__ deg = g.deg[blockIdx.z];
    float* __restrict__ diag = g.diag[blockIdx.z];
    const int Nn = NV, K = NV;

    __shared__ float As[2][16][136];
    __shared__ float Bs[2][16][72];

    const int tid = threadIdx.x;
    const int lane = tid & 31;
    const int wid = tid >> 5;
    const int wr = wid & 3;
    const int wc = wid >> 2;
    const int m0 = blockIdx.y * 128;
    const int n0 = blockIdx.x * 64;

    float acc[2][4][4];
#pragma unroll
    for (int mi = 0; mi < 2; mi++)
#pragma unroll
        for (int ni = 0; ni < 4; ni++)
#pragma unroll
            for (int r = 0; r < 4; r++) acc[mi][ni][r] = 0.0f;

    const int ar = tid >> 2;
    const int ac4 = (tid & 3) << 2;
    const int bk = tid >> 4;
    const int bn4 = (tid & 15) << 2;
    const int rowA0 = m0 + ar, rowA1 = m0 + 64 + ar;
    const float dvr0 = dv[rowA0], dvr1 = dv[rowA1];

    float4 av0, av1, bv;
    const int T = K >> 4;

    av0 = *(const float4*)&A[(size_t)rowA0 * K + ac4];
    av1 = *(const float4*)&A[(size_t)rowA1 * K + ac4];
    bv  = *(const float4*)&B[(size_t)bk * Nn + n0 + bn4];
    fix_scale4(av0, rowA0, ac4, dvr0, dv);
    fix_scale4(av1, rowA1, ac4, dvr1, dv);

    As[0][ac4 + 0][ar] = __uint_as_float(f2tf(av0.x));
    As[0][ac4 + 1][ar] = __uint_as_float(f2tf(av0.y));
    As[0][ac4 + 2][ar] = __uint_as_float(f2tf(av0.z));
    As[0][ac4 + 3][ar] = __uint_as_float(f2tf(av0.w));
    As[0][ac4 + 0][ar + 64] = __uint_as_float(f2tf(av1.x));
    As[0][ac4 + 1][ar + 64] = __uint_as_float(f2tf(av1.y));
    As[0][ac4 + 2][ar + 64] = __uint_as_float(f2tf(av1.z));
    As[0][ac4 + 3][ar + 64] = __uint_as_float(f2tf(av1.w));
    {
        float4 bt;
        bt.x = __uint_as_float(f2tf(bv.x));
        bt.y = __uint_as_float(f2tf(bv.y));
        bt.z = __uint_as_float(f2tf(bv.z));
        bt.w = __uint_as_float(f2tf(bv.w));
        *(float4*)&Bs[0][bk][bn4] = bt;
    }
    __syncthreads();

    for (int t = 0; t < T; t++) {
        int cur = t & 1;
        if (t + 1 < T) {
            int kb = (t + 1) << 4;
            av0 = *(const float4*)&A[(size_t)rowA0 * K + kb + ac4];
            av1 = *(const float4*)&A[(size_t)rowA1 * K + kb + ac4];
            bv  = *(const float4*)&B[(size_t)(kb + bk) * Nn + n0 + bn4];
            fix_scale4(av0, rowA0, kb + ac4, dvr0, dv);
            fix_scale4(av1, rowA1, kb + ac4, dvr1, dv);
        }
#pragma unroll
        for (int ks = 0; ks < 2; ks++) {
            const int k0 = ks * 8;
            uint32_t a[2][4], b[4][2];
            const int kl = k0 + (lane & 3);
            const int rl = lane >> 2;
#pragma unroll
            for (int mi = 0; mi < 2; mi++) {
                int m = wr * 32 + mi * 16 + rl;
                a[mi][0] = __float_as_uint(As[cur][kl][m]);
                a[mi][1] = __float_as_uint(As[cur][kl][m + 8]);
                a[mi][2] = __float_as_uint(As[cur][kl + 4][m]);
                a[mi][3] = __float_as_uint(As[cur][kl + 4][m + 8]);
            }
#pragma unroll
            for (int ni = 0; ni < 4; ni++) {
                int n = wc * 32 + ni * 8 + rl;
                b[ni][0] = __float_as_uint(Bs[cur][kl][n]);
                b[ni][1] = __float_as_uint(Bs[cur][kl + 4][n]);
            }
#pragma unroll
            for (int mi = 0; mi < 2; mi++)
#pragma unroll
                for (int ni = 0; ni < 4; ni++) {
                    asm volatile(
                        "mma.sync.aligned.m16n8k8.row.col.f32.tf32.tf32.f32 "
                        "{%0,%1,%2,%3}, {%4,%5,%6,%7}, {%8,%9}, {%0,%1,%2,%3};"
                        : "+f"(acc[mi][ni][0]), "+f"(acc[mi][ni][1]),
                          "+f"(acc[mi][ni][2]), "+f"(acc[mi][ni][3])
                        : "r"(a[mi][0]), "r"(a[mi][1]), "r"(a[mi][2]), "r"(a[mi][3]),
                          "r"(b[ni][0]), "r"(b[ni][1]));
                }
        }
        if (t + 1 < T) {
            int nxt = (t + 1) & 1;
            As[nxt][ac4 + 0][ar] = __uint_as_float(f2tf(av0.x));
            As[nxt][ac4 + 1][ar] = __uint_as_float(f2tf(av0.y));
            As[nxt][ac4 + 2][ar] = __uint_as_float(f2tf(av0.z));
            As[nxt][ac4 + 3][ar] = __uint_as_float(f2tf(av0.w));
            As[nxt][ac4 + 0][ar + 64] = __uint_as_float(f2tf(av1.x));
            As[nxt][ac4 + 1][ar + 64] = __uint_as_float(f2tf(av1.y));
            As[nxt][ac4 + 2][ar + 64] = __uint_as_float(f2tf(av1.z));
            As[nxt][ac4 + 3][ar + 64] = __uint_as_float(f2tf(av1.w));
            float4 bt;
            bt.x = __uint_as_float(f2tf(bv.x));
            bt.y = __uint_as_float(f2tf(bv.y));
            bt.z = __uint_as_float(f2tf(bv.z));
            bt.w = __uint_as_float(f2tf(bv.w));
            *(float4*)&Bs[nxt][bk][bn4] = bt;
            __syncthreads();
        }
    }

    const int rl = lane >> 2;
#pragma unroll
    for (int mi = 0; mi < 2; mi++) {
        int row = m0 + wr * 32 + mi * 16 + rl;
#pragma unroll
        for (int ni = 0; ni < 4; ni++) {
            int col = n0 + wc * 32 + ni * 8 + ((lane & 3) << 1);
            if (row == col) diag[row] = acc[mi][ni][0];
            if (row == col + 1) diag[row] = acc[mi][ni][1];
            if (row + 8 == col) diag[row + 8] = acc[mi][ni][2];
            if (row + 8 == col + 1) diag[row + 8] = acc[mi][ni][3];
            *(float2*)&C[(size_t)row * Nn + col] = make_float2(acc[mi][ni][0], acc[mi][ni][1]);
            *(float2*)&C[(size_t)(row + 8) * Nn + col] = make_float2(acc[mi][ni][2], acc[mi][ni][3]);
        }
    }
    float rs[4] = {0.0f, 0.0f, 0.0f, 0.0f};
#pragma unroll
    for (int mi = 0; mi < 2; mi++)
#pragma unroll
        for (int ni = 0; ni < 4; ni++) {
            rs[mi * 2 + 0] += acc[mi][ni][0] + acc[mi][ni][1];
            rs[mi * 2 + 1] += acc[mi][ni][2] + acc[mi][ni][3];
        }
#pragma unroll
    for (int q = 0; q < 4; q++) {
        rs[q] += __shfl_xor_sync(0xFFFFFFFF, rs[q], 1);
        rs[q] += __shfl_xor_sync(0xFFFFFFFF, rs[q], 2);
    }
    if ((lane & 3) == 0) {
        int rbase = m0 + wr * 32 + rl;
        atomicAdd(&deg[rbase], rs[0]);
        atomicAdd(&deg[rbase + 8], rs[1]);
        atomicAdd(&deg[rbase + 16], rs[2]);
        atomicAdd(&deg[rbase + 24], rs[3]);
    }
}

// plain fp32 64x64 tile GEMM (tiny x@w1, H@w2)
__global__ void sgemm64(const float* __restrict__ A, const float* __restrict__ B,
                        float* __restrict__ C, int M, int Nn, int K) {
    __shared__ float As[16][64];
    __shared__ float Bs[16][64];
    int tx = threadIdx.x, ty = threadIdx.y;
    int tid = ty * 16 + tx;
    int m0 = blockIdx.y * 64, n0 = blockIdx.x * 64;
    float acc[4][4];
#pragma unroll
    for (int i = 0; i < 4; i++)
#pragma unroll
        for (int j = 0; j < 4; j++) acc[i][j] = 0.0f;
    int la_r = tid / 16, la_k = tid % 16;
    int lb_k = tid / 64, lb_n = tid % 64;
    for (int k0 = 0; k0 < K; k0 += 16) {
#pragma unroll
        for (int r = 0; r < 4; r++)
            As[la_k][la_r + 16 * r] = A[(size_t)(m0 + la_r + 16 * r) * K + k0 + la_k];
#pragma unroll
        for (int r = 0; r < 4; r++) {
            int kk = lb_k + 4 * r;
            Bs[kk][lb_n] = (n0 + lb_n < Nn) ? B[(size_t)(k0 + kk) * Nn + n0 + lb_n] : 0.0f;
        }
        __syncthreads();
#pragma unroll
        for (int k = 0; k < 16; k++) {
            float a[4], b[4];
#pragma unroll
            for (int i = 0; i < 4; i++) a[i] = As[k][ty * 4 + i];
#pragma unroll
            for (int j = 0; j < 4; j++) b[j] = Bs[k][tx * 4 + j];
#pragma unroll
            for (int i = 0; i < 4; i++)
#pragma unroll
                for (int j = 0; j < 4; j++) acc[i][j] += a[i] * b[j];
        }
        __syncthreads();
    }
#pragma unroll
    for (int i = 0; i < 4; i++) {
        int row = m0 + ty * 4 + i;
#pragma unroll
        for (int j = 0; j < 4; j++) {
            int col = n0 + tx * 4 + j;
            if (col < Nn) C[(size_t)row * Nn + col] = acc[i][j];
        }
    }
}

// split-K fp32 GEMM with fused gcn-norm on A: C += (Dv fix(A) Dv) @ B.
__global__ void sgemmKS(const float* __restrict__ A, const float* __restrict__ dv,
                        const float* __restrict__ B, float* __restrict__ C,
                        int Nn, int K, int KS, const float* __restrict__ bias) {
    __shared__ float As[16][64];
    __shared__ float Bs[16][64];
    int tx = threadIdx.x, ty = threadIdx.y;
    int tid = ty * 16 + tx;
    int m0 = blockIdx.y * 64;
    int kLen = K / KS;
    int kStart = blockIdx.x * kLen;
    float acc[4][4];
#pragma unroll
    for (int i = 0; i < 4; i++)
#pragma unroll
        for (int j = 0; j < 4; j++) acc[i][j] = 0.0f;
    int la_r = tid / 16, la_k = tid % 16;
    int lb_k = tid / 64, lb_n = tid % 64;
    for (int k0 = kStart; k0 < kStart + kLen; k0 += 16) {
#pragma unroll
        for (int r = 0; r < 4; r++) {
            int row = m0 + la_r + 16 * r;
            int kc = k0 + la_k;
            float v = A[(size_t)row * K + kc];
            if (row == kc && v == 0.0f) v = 1.0f;
            As[la_k][la_r + 16 * r] = v * dv[row] * dv[kc];
        }
#pragma unroll
        for (int r = 0; r < 4; r++) {
            int kk = lb_k + 4 * r;
            Bs[kk][lb_n] = (lb_n < Nn) ? B[(size_t)(k0 + kk) * Nn + lb_n] : 0.0f;
        }
        __syncthreads();
#pragma unroll
        for (int k = 0; k < 16; k++) {
            float a[4], b[4];
#pragma unroll
            for (int i = 0; i < 4; i++) a[i] = As[k][ty * 4 + i];
#pragma unroll
            for (int j = 0; j < 4; j++) b[j] = Bs[k][tx * 4 + j];
#pragma unroll
            for (int i = 0; i < 4; i++)
#pragma unroll
                for (int j = 0; j < 4; j++) acc[i][j] += a[i] * b[j];
        }
        __syncthreads();
    }
#pragma unroll
    for (int i = 0; i < 4; i++) {
        int row = m0 + ty * 4 + i;
#pragma unroll
        for (int j = 0; j < 4; j++) {
            int col = tx * 4 + j;
            if (col < Nn) {
                float v = acc[i][j];
                if (bias != nullptr && kStart == 0) v += bias[col];
                atomicAdd(&C[(size_t)row * Nn + col], v);
            }
        }
    }
}

// ---------------- host orchestration ----------------

extern "C" void kernel_launch(void* const* d_in, const int* in_sizes, int n_in,
                              void* d_out, int out_size) {
    const float* x = (const float*)d_in[0];
    const int* edges[5];
    for (int i = 0; i < 5; i++) edges[i] = (const int*)d_in[1 + i];
    const float* pbp[2][8];
    for (int b = 0; b < 2; b++)
        for (int i = 0; i < 8; i++) pbp[b][i] = (const float*)d_in[6 + b * 8 + i];
    const float* w1    = (const float*)d_in[22];
    const float* bias1 = (const float*)d_in[23];
    const float* w2    = (const float*)d_in[24];
    const float* bias2 = (const float*)d_in[25];
    float* out = (float*)d_out;

    float *A_, *p1_, *p2_, *att_, *M_, *Mt_, *An_, *dinv_, *deg_, *diag_, *XW_, *H_, *HW_;
    cudaGetSymbolAddress((void**)&A_,    g_A);
    cudaGetSymbolAddress((void**)&p1_,   g_p1);
    cudaGetSymbolAddress((void**)&p2_,   g_p2);
    cudaGetSymbolAddress((void**)&att_,  g_att);
    cudaGetSymbolAddress((void**)&M_,    g_M);
    cudaGetSymbolAddress((void**)&Mt_,   g_Mt);
    cudaGetSymbolAddress((void**)&An_,   g_An);
    cudaGetSymbolAddress((void**)&dinv_, g_dinv);
    cudaGetSymbolAddress((void**)&deg_,  g_deg);
    cudaGetSymbolAddress((void**)&diag_, g_diag);
    cudaGetSymbolAddress((void**)&XW_,   g_XW);
    cudaGetSymbolAddress((void**)&H_,    g_H);
    cudaGetSymbolAddress((void**)&HW_,   g_HW);

    const size_t PLANE = (size_t)NV * NV;
    dim3 blk16(16, 16);

    float* Ab[2]   = { A_,   A_   + 3 * PLANE };
    float* p1b[2]  = { p1_,  p1_  + (size_t)16 * 512 * 512 };
    float* p2b[2]  = { p2_,  p2_  + (size_t)4 * 257 * 257 };
    float* attb[2] = { att_, att_ + 3 * PLANE };
    float* Mb[2]   = { M_,   M_   + PLANE };
    float* Mtb[2]  = { Mt_,  Mt_  + PLANE };

    // -------- setup --------
    cudaMemsetAsync(A_, 0, 6 * PLANE * sizeof(float), 0);
    cudaMemsetAsync(deg_, 0, 5 * NV * sizeof(float), 0);
    cudaMemsetAsync(H_, 0, (size_t)NV * HIDD * sizeof(float), 0);
    cudaMemsetAsync(out, 0, (size_t)NV * REPD * sizeof(float), 0);
    sgemm64<<<dim3(1, NV / 64), blk16>>>(x, w1, XW_, NV, HIDD, EMBD);

    // -------- scatter all 5 edge lists --------
    Sc5 sc;
    sc.e[0] = edges[0]; sc.A[0] = Ab[0];
    sc.e[1] = edges[1]; sc.A[1] = Ab[0] + PLANE;
    sc.e[2] = edges[2]; sc.A[2] = Ab[1];
    sc.e[3] = edges[3]; sc.A[3] = Ab[1] + PLANE;
    sc.e[4] = edges[4]; sc.A[4] = Ab[1] + 2 * PLANE;
    scatter_all<<<dim3((NE + 255) / 256, 5), 256>>>(sc);

    // -------- conv encoder (both paths batched) --------
    PathPtrs c1 = {{Ab[0], Ab[1]}, {pbp[0][0], pbp[1][0]}, {pbp[0][1], pbp[1][1]}, {p1b[0], p1b[1]}};
    conv1pool_both<<<dim3(32, 32, 2), blk16>>>(c1);

    PathPtrs c2 = {{p1b[0], p1b[1]}, {pbp[0][2], pbp[1][2]}, {pbp[0][3], pbp[1][3]}, {p2b[0], p2b[1]}};
    conv2pool_both<<<dim3(17, 17, 2), blk16>>>(c2);

    // fused tconv1 + tconv2 + sigmoid + adjacency multiply + att0 deg/diag
    FAtt fa;
    for (int p = 0; p < 2; p++) {
        fa.p2[p] = p2b[p];
        fa.w1[p] = pbp[p][4]; fa.b1[p] = pbp[p][5];
        fa.w2[p] = pbp[p][6]; fa.b2[p] = pbp[p][7];
        fa.A[p] = Ab[p]; fa.att[p] = attb[p];
        fa.deg[p] = deg_ + p * NV; fa.diag[p] = diag_ + p * NV;
    }
    ftconv_att_both<<<(2 * NV * 512) / 256, 256>>>(fa);
    dinv_fix<<<(2 * NV + 255) / 256, 256>>>(deg_, diag_, dinv_, 2 * NV);

    // -------- M-chain, norms fused into GEMMs --------
    {
        GemS gs;
        gs.A[0] = attb[0];         gs.A[1] = attb[1];
        gs.B[0] = attb[0] + PLANE; gs.B[1] = attb[1] + PLANE;
        gs.C[0] = Mtb[0];          gs.C[1] = Mtb[1];
        gs.dv[0] = dinv_;          gs.dv[1] = dinv_ + NV;
        gs.deg[0] = deg_ + 2 * NV; gs.deg[1] = deg_ + 3 * NV;
        gs.diag[0] = diag_ + 2 * NV; gs.diag[1] = diag_ + 3 * NV;
        tf32gemm_s<<<dim3(NV / 64, NV / 128, 2), 256>>>(gs);
        dinv_fix<<<(2 * NV + 255) / 256, 256>>>(deg_ + 2 * NV, diag_ + 2 * NV, dinv_ + 2 * NV, 2 * NV);
    }
    {
        GemS gs;
        gs.A[0] = Mtb[1];
        gs.B[0] = attb[1] + 2 * PLANE;
        gs.C[0] = Mb[1];
        gs.dv[0] = dinv_ + 3 * NV;
        gs.deg[0] = deg_ + 4 * NV;
        gs.diag[0] = diag_ + 4 * NV;
        gs.A[1] = gs.A[0]; gs.B[1] = gs.B[0]; gs.C[1] = gs.C[0];
        gs.dv[1] = gs.dv[0]; gs.deg[1] = gs.deg[0]; gs.diag[1] = gs.diag[0];
        tf32gemm_s<<<dim3(NV / 64, NV / 128, 1), 256>>>(gs);
        dinv_fix<<<(NV + 255) / 256, 256>>>(deg_ + 4 * NV, diag_ + 4 * NV, dinv_ + 4 * NV, NV);
    }

    // -------- scaled merge + final dinv --------
    emax_dinv<<<NV, 256>>>(Mtb[0], dinv_ + 2 * NV, Mb[1], dinv_ + 4 * NV, An_, dinv_ + 5 * NV);

    // -------- GCN layers, final norm fused into A-loads --------
    sgemmKS<<<dim3(8, NV / 64), blk16>>>(An_, dinv_ + 5 * NV, XW_, H_, HIDD, NV, 8, nullptr);
    bias_relu64<<<(NV * HIDD + 255) / 256, 256>>>(H_, bias1);
    sgemm64<<<dim3(1, NV / 64), blk16>>>(H_, w2, HW_, NV, REPD, HIDD);
    sgemmKS<<<dim3(8, NV / 64), blk16>>>(An_, dinv_ + 5 * NV, HW_, out, REPD, NV, 8, bias2);
}

// round 8
// speedup vs baseline: 2.1715x; 1.0071x over previous
#include <cuda_runtime.h>
#include <math.h>
#include <stdint.h>

// Problem constants
#define NV 1024
#define NE 32768
#define EMBD 128
#define HIDD 64
#define REPD 32

// ---------------- scratch (static device globals) ----------------
__device__ float g_A[2][3][NV][NV];
__device__ float g_p1[2][16][512][512];
__device__ float g_p2[2][4][257][257];
__device__ float g_att[2][3][NV][NV];
__device__ float g_M[2][NV][NV];
__device__ float g_Mt[2][NV][NV];
__device__ float g_An[NV][NV];
__device__ float g_dinv[6][NV];
__device__ float g_deg[5][NV];
__device__ float g_diag[5][NV];
__device__ float g_XW[NV][HIDD];
__device__ float g_H[NV][HIDD];
__device__ float g_HW[NV][REPD];

// ---------------- param structs ----------------
struct Sc5 { const int* e[5]; float* A[5]; };
struct PathPtrs {
    const float* in[2]; const float* w[2]; const float* b[2]; float* out[2];
};
struct FAtt {
    const float* p2[2]; const float* w1[2]; const float* b1[2];
    const float* w2[2]; const float* b2[2]; const float* A[2]; float* att[2];
    float* deg[2]; float* diag[2];
};
struct GemS {
    const float* A[2]; const float* B[2]; float* C[2];
    const float* dv[2]; float* deg[2]; float* diag[2];
};

// ---------------- helpers ----------------
__device__ __forceinline__ uint32_t f2tf(float f) {
    uint32_t r;
    asm("cvt.rna.tf32.f32 %0, %1;" : "=r"(r) : "f"(f));
    return r;
}

__device__ __forceinline__ void mma_tf32(float* c, const uint32_t* a, uint32_t b0, uint32_t b1) {
    asm volatile(
        "mma.sync.aligned.m16n8k8.row.col.f32.tf32.tf32.f32 "
        "{%0,%1,%2,%3}, {%4,%5,%6,%7}, {%8,%9}, {%0,%1,%2,%3};"
        : "+f"(c[0]), "+f"(c[1]), "+f"(c[2]), "+f"(c[3])
        : "r"(a[0]), "r"(a[1]), "r"(a[2]), "r"(a[3]), "r"(b0), "r"(b1));
}

// ---------------- kernels ----------------

__global__ void scatter_all(Sc5 s) {
    int j = blockIdx.y;
    int k = blockIdx.x * blockDim.x + threadIdx.x;
    if (k < NE) {
        const int* e = s.e[j];
        atomicAdd(&s.A[j][e[k] * NV + e[NE + k]], 1.0f);
    }
}

// ---- conv1 (3x3, pad1, L->16) + relu + maxpool2 via tf32 tensor-core implicit GEMM ----
// Inputs are exact small integers (adjacency counts) -> exactly representable in tf32;
// only weights need hi/lo split, giving fp32-accurate results with 2 MMAs per k-step.
// Block 256 thr (8 warps) -> 16x16 pooled outputs. M=16 oc, K=L*9 (padded), N=8 conv-x.
template <int L>
__device__ __forceinline__ void conv1mma_impl(const float* __restrict__ A,
                                              const float* __restrict__ w,
                                              const float* __restrict__ b,
                                              float* __restrict__ p1,
                                              float* __restrict__ tile,
                                              float* __restrict__ whi,
                                              float* __restrict__ wlo,
                                              float* __restrict__ sb) {
    constexpr int KS = (L * 9 + 7) / 8;   // 3 (L=2) or 4 (L=3)
    int t = threadIdx.y * 16 + threadIdx.x;
    int lane = t & 31, wid = t >> 5;

    // stage weights as tf32 hi/lo, zero-padded to K=32
    for (int i = t; i < 512; i += 256) {
        int oc = i >> 5, k = i & 31;
        float wv = (k < L * 9) ? w[oc * L * 9 + k] : 0.0f;
        float hi = __uint_as_float(f2tf(wv));
        whi[i] = hi;
        wlo[i] = __uint_as_float(f2tf(wv - hi));
    }
    if (t < 16) sb[t] = b[t];

    // stage input tile (34x34 per channel, stride 36) — values are exact ints
    int gy0 = blockIdx.y * 32 - 1, gx0 = blockIdx.x * 32 - 1;
    for (int l = 0; l < L; l++)
        for (int i = t; i < 34 * 34; i += 256) {
            int r = i / 34, c = i % 34;
            int gy = gy0 + r, gx = gx0 + c;
            tile[(l * 34 + r) * 36 + c] = (gy >= 0 && gy < NV && gx >= 0 && gx < NV)
                                              ? A[((size_t)l * NV + gy) * NV + gx] : 0.0f;
        }
    __syncthreads();

    // A fragments (weights), loaded once
    uint32_t ahi[KS][4], alo[KS][4];
    int r0 = (lane >> 2) * 32, r1 = ((lane >> 2) + 8) * 32;
#pragma unroll
    for (int s = 0; s < KS; s++) {
        int c0 = 8 * s + (lane & 3);
        ahi[s][0] = __float_as_uint(whi[r0 + c0]);
        ahi[s][1] = __float_as_uint(whi[r1 + c0]);
        ahi[s][2] = __float_as_uint(whi[r0 + c0 + 4]);
        ahi[s][3] = __float_as_uint(whi[r1 + c0 + 4]);
        alo[s][0] = __float_as_uint(wlo[r0 + c0]);
        alo[s][1] = __float_as_uint(wlo[r1 + c0]);
        alo[s][2] = __float_as_uint(wlo[r0 + c0 + 4]);
        alo[s][3] = __float_as_uint(wlo[r1 + c0 + 4]);
    }

    // B fragment smem offsets per (s, half): k -> (l, ky, kx), col = lane>>2
    int boff[KS][2];
#pragma unroll
    for (int s = 0; s < KS; s++)
#pragma unroll
        for (int h = 0; h < 2; h++) {
            int k = 8 * s + (lane & 3) + 4 * h;
            if (k >= L * 9) k = 0;   // weight is zero there; any in-bounds value OK
            int l = k / 9, r = k % 9;
            boff[s][h] = (l * 34 + r / 3) * 36 + (r % 3) + (lane >> 2);
        }

    // units: u = py*4 + ux; each warp-unit = 1 pooled row x 4 pooled cols x 16 oc
    for (int u = wid; u < 64; u += 8) {
        int py = u >> 2, ux = u & 3;
        int base0 = (2 * py) * 36 + 8 * ux;   // conv row y
        int base1 = base0 + 36;               // conv row y+1
        float acc0[4] = {0.f, 0.f, 0.f, 0.f};
        float acc1[4] = {0.f, 0.f, 0.f, 0.f};
#pragma unroll
        for (int s = 0; s < KS; s++) {
            uint32_t b00 = __float_as_uint(tile[boff[s][0] + base0]);
            uint32_t b01 = __float_as_uint(tile[boff[s][1] + base0]);
            mma_tf32(acc0, ahi[s], b00, b01);
            mma_tf32(acc0, alo[s], b00, b01);
            uint32_t b10 = __float_as_uint(tile[boff[s][0] + base1]);
            uint32_t b11 = __float_as_uint(tile[boff[s][1] + base1]);
            mma_tf32(acc1, ahi[s], b10, b11);
            mma_tf32(acc1, alo[s], b10, b11);
        }
        // pool (x-pair intra-thread c0/c1, y-pair across acc0/acc1) + bias + relu
        int oc0 = lane >> 2, oc1 = oc0 + 8;
        int ox = blockIdx.x * 16 + 4 * ux + (lane & 3);
        int oy = blockIdx.y * 16 + py;
        float m0 = fmaxf(fmaxf(acc0[0], acc0[1]), fmaxf(acc1[0], acc1[1]));
        float m1 = fmaxf(fmaxf(acc0[2], acc0[3]), fmaxf(acc1[2], acc1[3]));
        p1[((size_t)oc0 * 512 + oy) * 512 + ox] = fmaxf(m0 + sb[oc0], 0.0f);
        p1[((size_t)oc1 * 512 + oy) * 512 + ox] = fmaxf(m1 + sb[oc1], 0.0f);
    }
}

__global__ void __launch_bounds__(256) conv1mma_both(PathPtrs p) {
    __shared__ float tile[3 * 34 * 36];
    __shared__ float whi[512], wlo[512];
    __shared__ float sb[16];
    int path = blockIdx.z;
    if (path == 0)
        conv1mma_impl<2>(p.in[0], p.w[0], p.b[0], p.out[0], tile, whi, wlo, sb);
    else
        conv1mma_impl<3>(p.in[1], p.w[1], p.b[1], p.out[1], tile, whi, wlo, sb);
}

// ---- conv2 (3x3, pad2, 16->4) + relu + maxpool2 (round-6 proven version) ----
__global__ void conv2pool_both(PathPtrs pp) {
    __shared__ float tile[36 * 38];
    __shared__ float sw[576];
    __shared__ float sb[4];
    int path = blockIdx.z;
    const float* p1 = pp.in[path];
    float* p2 = pp.out[path];
    int tx = threadIdx.x, ty = threadIdx.y;
    int t = ty * 16 + tx;
    for (int i = t; i < 576; i += 256) sw[i] = pp.w[path][i];
    if (t < 4) sb[t] = pp.b[path][t];

    int gy0 = blockIdx.y * 32 - 2, gx0 = blockIdx.x * 32 - 2;

    int srow[6], scol[6], sok[6];
    float r[6];
#pragma unroll
    for (int s = 0; s < 6; s++) {
        int i = t + s * 256;
        srow[s] = i / 36; scol[s] = i % 36;
        sok[s] = (i < 1296);
    }
#pragma unroll
    for (int s = 0; s < 6; s++) {
        if (sok[s]) {
            int gy = gy0 + srow[s], gx = gx0 + scol[s];
            r[s] = (gy >= 0 && gy < 512 && gx >= 0 && gx < 512)
                       ? p1[(size_t)gy * 512 + gx] : 0.0f;
        }
    }

    float acc[4][2][2];
#pragma unroll
    for (int oc = 0; oc < 4; oc++)
#pragma unroll
        for (int py = 0; py < 2; py++)
#pragma unroll
            for (int px = 0; px < 2; px++) acc[oc][py][px] = 0.0f;

    __syncthreads();

    for (int ci = 0; ci < 16; ci++) {
#pragma unroll
        for (int s = 0; s < 6; s++)
            if (sok[s]) tile[srow[s] * 38 + scol[s]] = r[s];
        __syncthreads();
        if (ci < 15) {
#pragma unroll
            for (int s = 0; s < 6; s++) {
                if (sok[s]) {
                    int gy = gy0 + srow[s], gx = gx0 + scol[s];
                    r[s] = (gy >= 0 && gy < 512 && gx >= 0 && gx < 512)
                               ? p1[((size_t)(ci + 1) * 512 + gy) * 512 + gx] : 0.0f;
                }
            }
        }
        float patch[4][4];
#pragma unroll
        for (int rw = 0; rw < 4; rw++)
#pragma unroll
            for (int c = 0; c < 4; c++)
                patch[rw][c] = tile[(2 * ty + rw) * 38 + 2 * tx + c];
#pragma unroll
        for (int oc = 0; oc < 4; oc++)
#pragma unroll
            for (int ky = 0; ky < 3; ky++)
#pragma unroll
                for (int kx = 0; kx < 3; kx++) {
                    float wv = sw[((oc * 16 + ci) * 3 + ky) * 3 + kx];
                    acc[oc][0][0] += wv * patch[ky][kx];
                    acc[oc][0][1] += wv * patch[ky][kx + 1];
                    acc[oc][1][0] += wv * patch[ky + 1][kx];
                    acc[oc][1][1] += wv * patch[ky + 1][kx + 1];
                }
        __syncthreads();
    }
    int x = blockIdx.x * 16 + tx, y = blockIdx.y * 16 + ty;
    if (x < 257 && y < 257) {
#pragma unroll
        for (int oc = 0; oc < 4; oc++) {
            float m = fmaxf(fmaxf(acc[oc][0][0], acc[oc][0][1]),
                            fmaxf(acc[oc][1][0], acc[oc][1][1])) + sb[oc];
            p2[((size_t)oc * 257 + y) * 257 + x] = fmaxf(m, 0.0f);
        }
    }
}

// ---- fused tconv1 + tconv2 + sigmoid + crop + adjacency multiply + att0 deg/diag ----
template <int L>
__device__ __forceinline__ void ftconv_impl(const float* __restrict__ p2,
                                            const float* __restrict__ sw1,
                                            const float* __restrict__ sb1,
                                            const float* __restrict__ sw2,
                                            const float* __restrict__ sb2,
                                            const float* __restrict__ A,
                                            float* __restrict__ att,
                                            float* __restrict__ deg,
                                            float* __restrict__ diag, int idx) {
    int m = idx & 511, y = idx >> 9;
    int ky2 = (y + 1) & 1;
    int iy1 = (y - 1 + ky2) >> 1;
    int ky1 = (iy1 + 1) & 1, kx1 = (m + 1) & 1;
    int iy0 = (iy1 - 1 + ky1) >> 1;
    int ix0 = (m - 1 + kx1) >> 1;

    float p[4];
#pragma unroll
    for (int cj = 0; cj < 4; cj++) p[cj] = p2[((size_t)cj * 257 + iy0) * 257 + ix0];

    float t1v[16];
#pragma unroll
    for (int ci = 0; ci < 16; ci++) {
        float s = sb1[ci];
#pragma unroll
        for (int cj = 0; cj < 4; cj++)
            s += sw1[((ci * 4 + cj) * 2 + ky1) * 2 + kx1] * p[cj];
        t1v[ci] = fmaxf(s, 0.0f);
    }

    float a0v0 = 0.0f, a0v1 = 0.0f;
#pragma unroll
    for (int l = 0; l < L; l++) {
        float s0 = sb2[l], s1 = sb2[l];
#pragma unroll
        for (int ci = 0; ci < 16; ci++) {
            float tv = t1v[ci];
            s0 += sw2[((l * 16 + ci) * 2 + ky2) * 2 + 1] * tv;
            s1 += sw2[((l * 16 + ci) * 2 + ky2) * 2 + 0] * tv;
        }
        float g0 = 1.0f / (1.0f + expf(-s0));
        float g1 = 1.0f / (1.0f + expf(-s1));
        size_t off = (size_t)l * NV * NV + (size_t)y * NV + 2 * m;
        float2 a = *(const float2*)&A[off];
        float v0 = a.x * g0, v1 = a.y * g1;
        *(float2*)&att[off] = make_float2(v0, v1);
        if (l == 0) { a0v0 = v0; a0v1 = v1; }
    }

    float s = a0v0 + a0v1;
#pragma unroll
    for (int o = 16; o > 0; o >>= 1) s += __shfl_xor_sync(0xFFFFFFFF, s, o);
    if ((threadIdx.x & 31) == 0) atomicAdd(&deg[y], s);
    if (2 * m == y) diag[y] = a0v0;
    else if (2 * m + 1 == y) diag[y] = a0v1;
}

__global__ void ftconv_att_both(FAtt fa) {
    __shared__ float sw1[256], sb1[16], sw2[192], sb2[3];
    int gidx = blockIdx.x * blockDim.x + threadIdx.x;
    const int PL = NV * 512;
    int path = gidx / PL;
    int idx = gidx - path * PL;
    const int L = (path == 0) ? 2 : 3;
    int t = threadIdx.x;
    if (t < 256) sw1[t] = fa.w1[path][t];
    if (t < 16) sb1[t] = fa.b1[path][t];
    for (int i = t; i < L * 64; i += 256) sw2[i] = fa.w2[path][i];
    if (t < L) sb2[t] = fa.b2[path][t];
    __syncthreads();
    if (path == 0)
        ftconv_impl<2>(fa.p2[0], sw1, sb1, sw2, sb2, fa.A[0], fa.att[0],
                       fa.deg[0], fa.diag[0], idx);
    else
        ftconv_impl<3>(fa.p2[1], sw1, sb1, sw2, sb2, fa.A[1], fa.att[1],
                       fa.deg[1], fa.diag[1], idx);
}

// ---- dinv from accumulated deg/diag ----
__global__ void dinv_fix(const float* __restrict__ deg, const float* __restrict__ diag,
                         float* __restrict__ dv, int n) {
    int i = blockIdx.x * blockDim.x + threadIdx.x;
    if (i < n) {
        float d = deg[i];
        if (diag[i] == 0.0f) d += 1.0f;
        dv[i] = d > 0.0f ? rsqrtf(d) : 0.0f;
    }
}

// ---- scaled max-merge + row-sum/dinv ----
__global__ void emax_dinv(const float* __restrict__ a, const float* __restrict__ dva,
                          const float* __restrict__ b, const float* __restrict__ dvb,
                          float* __restrict__ o, float* __restrict__ dv) {
    int row = blockIdx.x;
    float dar = dva[row], dbr = dvb[row];
    __shared__ float sh[256];
    __shared__ float sdiag;
    float s = 0.0f;
    for (int j = threadIdx.x; j < NV; j += 256) {
        float va = a[(size_t)row * NV + j];
        if (j == row && va == 0.0f) va = 1.0f;
        va *= dar * dva[j];
        float vb = b[(size_t)row * NV + j];
        if (j == row && vb == 0.0f) vb = 1.0f;
        vb *= dbr * dvb[j];
        float v = fmaxf(va, vb);
        o[(size_t)row * NV + j] = v;
        if (j == row) sdiag = v;
        s += v;
    }
    sh[threadIdx.x] = s;
    __syncthreads();
    for (int off = 128; off > 0; off >>= 1) {
        if (threadIdx.x < off) sh[threadIdx.x] += sh[threadIdx.x + off];
        __syncthreads();
    }
    if (threadIdx.x == 0) {
        float d = sh[0];
        if (sdiag == 0.0f) d += 1.0f;
        dv[row] = d > 0.0f ? rsqrtf(d) : 0.0f;
    }
}

__global__ void bias_relu64(float* __restrict__ H, const float* __restrict__ bias) {
    int idx = blockIdx.x * blockDim.x + threadIdx.x;
    if (idx < NV * HIDD) H[idx] = fmaxf(H[idx] + bias[idx & (HIDD - 1)], 0.0f);
}

// ---------------- tf32 GEMM with fused gcn-norm on A + deg/diag epilogue ----------------
__device__ __forceinline__ void fix_scale4(float4& v, int row, int kc, float dvr,
                                           const float* __restrict__ dv) {
    float4 dk = *(const float4*)&dv[kc];
    float* p = &v.x;
#pragma unroll
    for (int q = 0; q < 4; q++)
        if (row == kc + q && p[q] == 0.0f) p[q] = 1.0f;
    v.x *= dvr * dk.x; v.y *= dvr * dk.y; v.z *= dvr * dk.z; v.w *= dvr * dk.w;
}

__global__ void __launch_bounds__(256) tf32gemm_s(GemS g) {
    const float* __restrict__ A = g.A[blockIdx.z];
    const float* __restrict__ B = g.B[blockIdx.z];
    float* __restrict__ C = g.C[blockIdx.z];
    const float* __restrict__ dv = g.dv[blockIdx.z];
    float* __restrict__ deg = g.deg[blockIdx.z];
    float* __restrict__ diag = g.diag[blockIdx.z];
    const int Nn = NV, K = NV;

    __shared__ float As[2][16][136];
    __shared__ float Bs[2][16][72];

    const int tid = threadIdx.x;
    const int lane = tid & 31;
    const int wid = tid >> 5;
    const int wr = wid & 3;
    const int wc = wid >> 2;
    const int m0 = blockIdx.y * 128;
    const int n0 = blockIdx.x * 64;

    float acc[2][4][4];
#pragma unroll
    for (int mi = 0; mi < 2; mi++)
#pragma unroll
        for (int ni = 0; ni < 4; ni++)
#pragma unroll
            for (int r = 0; r < 4; r++) acc[mi][ni][r] = 0.0f;

    const int ar = tid >> 2;
    const int ac4 = (tid & 3) << 2;
    const int bk = tid >> 4;
    const int bn4 = (tid & 15) << 2;
    const int rowA0 = m0 + ar, rowA1 = m0 + 64 + ar;
    const float dvr0 = dv[rowA0], dvr1 = dv[rowA1];

    float4 av0, av1, bv;
    const int T = K >> 4;

    av0 = *(const float4*)&A[(size_t)rowA0 * K + ac4];
    av1 = *(const float4*)&A[(size_t)rowA1 * K + ac4];
    bv  = *(const float4*)&B[(size_t)bk * Nn + n0 + bn4];
    fix_scale4(av0, rowA0, ac4, dvr0, dv);
    fix_scale4(av1, rowA1, ac4, dvr1, dv);

    As[0][ac4 + 0][ar] = __uint_as_float(f2tf(av0.x));
    As[0][ac4 + 1][ar] = __uint_as_float(f2tf(av0.y));
    As[0][ac4 + 2][ar] = __uint_as_float(f2tf(av0.z));
    As[0][ac4 + 3][ar] = __uint_as_float(f2tf(av0.w));
    As[0][ac4 + 0][ar + 64] = __uint_as_float(f2tf(av1.x));
    As[0][ac4 + 1][ar + 64] = __uint_as_float(f2tf(av1.y));
    As[0][ac4 + 2][ar + 64] = __uint_as_float(f2tf(av1.z));
    As[0][ac4 + 3][ar + 64] = __uint_as_float(f2tf(av1.w));
    {
        float4 bt;
        bt.x = __uint_as_float(f2tf(bv.x));
        bt.y = __uint_as_float(f2tf(bv.y));
        bt.z = __uint_as_float(f2tf(bv.z));
        bt.w = __uint_as_float(f2tf(bv.w));
        *(float4*)&Bs[0][bk][bn4] = bt;
    }
    __syncthreads();

    for (int t = 0; t < T; t++) {
        int cur = t & 1;
        if (t + 1 < T) {
            int kb = (t + 1) << 4;
            av0 = *(const float4*)&A[(size_t)rowA0 * K + kb + ac4];
            av1 = *(const float4*)&A[(size_t)rowA1 * K + kb + ac4];
            bv  = *(const float4*)&B[(size_t)(kb + bk) * Nn + n0 + bn4];
            fix_scale4(av0, rowA0, kb + ac4, dvr0, dv);
            fix_scale4(av1, rowA1, kb + ac4, dvr1, dv);
        }
#pragma unroll
        for (int ks = 0; ks < 2; ks++) {
            const int k0 = ks * 8;
            uint32_t a[2][4], b[4][2];
            const int kl = k0 + (lane & 3);
            const int rl = lane >> 2;
#pragma unroll
            for (int mi = 0; mi < 2; mi++) {
                int m = wr * 32 + mi * 16 + rl;
                a[mi][0] = __float_as_uint(As[cur][kl][m]);
                a[mi][1] = __float_as_uint(As[cur][kl][m + 8]);
                a[mi][2] = __float_as_uint(As[cur][kl + 4][m]);
                a[mi][3] = __float_as_uint(As[cur][kl + 4][m + 8]);
            }
#pragma unroll
            for (int ni = 0; ni < 4; ni++) {
                int n = wc * 32 + ni * 8 + rl;
                b[ni][0] = __float_as_uint(Bs[cur][kl][n]);
                b[ni][1] = __float_as_uint(Bs[cur][kl + 4][n]);
            }
#pragma unroll
            for (int mi = 0; mi < 2; mi++)
#pragma unroll
                for (int ni = 0; ni < 4; ni++) {
                    asm volatile(
                        "mma.sync.aligned.m16n8k8.row.col.f32.tf32.tf32.f32 "
                        "{%0,%1,%2,%3}, {%4,%5,%6,%7}, {%8,%9}, {%0,%1,%2,%3};"
                        : "+f"(acc[mi][ni][0]), "+f"(acc[mi][ni][1]),
                          "+f"(acc[mi][ni][2]), "+f"(acc[mi][ni][3])
                        : "r"(a[mi][0]), "r"(a[mi][1]), "r"(a[mi][2]), "r"(a[mi][3]),
                          "r"(b[ni][0]), "r"(b[ni][1]));
                }
        }
        if (t + 1 < T) {
            int nxt = (t + 1) & 1;
            As[nxt][ac4 + 0][ar] = __uint_as_float(f2tf(av0.x));
            As[nxt][ac4 + 1][ar] = __uint_as_float(f2tf(av0.y));
            As[nxt][ac4 + 2][ar] = __uint_as_float(f2tf(av0.z));
            As[nxt][ac4 + 3][ar] = __uint_as_float(f2tf(av0.w));
            As[nxt][ac4 + 0][ar + 64] = __uint_as_float(f2tf(av1.x));
            As[nxt][ac4 + 1][ar + 64] = __uint_as_float(f2tf(av1.y));
            As[nxt][ac4 + 2][ar + 64] = __uint_as_float(f2tf(av1.z));
            As[nxt][ac4 + 3][ar + 64] = __uint_as_float(f2tf(av1.w));
            float4 bt;
            bt.x = __uint_as_float(f2tf(bv.x));
            bt.y = __uint_as_float(f2tf(bv.y));
            bt.z = __uint_as_float(f2tf(bv.z));
            bt.w = __uint_as_float(f2tf(bv.w));
            *(float4*)&Bs[nxt][bk][bn4] = bt;
            __syncthreads();
        }
    }

    const int rl = lane >> 2;
#pragma unroll
    for (int mi = 0; mi < 2; mi++) {
        int row = m0 + wr * 32 + mi * 16 + rl;
#pragma unroll
        for (int ni = 0; ni < 4; ni++) {
            int col = n0 + wc * 32 + ni * 8 + ((lane & 3) << 1);
            if (row == col) diag[row] = acc[mi][ni][0];
            if (row == col + 1) diag[row] = acc[mi][ni][1];
            if (row + 8 == col) diag[row + 8] = acc[mi][ni][2];
            if (row + 8 == col + 1) diag[row + 8] = acc[mi][ni][3];
            *(float2*)&C[(size_t)row * Nn + col] = make_float2(acc[mi][ni][0], acc[mi][ni][1]);
            *(float2*)&C[(size_t)(row + 8) * Nn + col] = make_float2(acc[mi][ni][2], acc[mi][ni][3]);
        }
    }
    float rs[4] = {0.0f, 0.0f, 0.0f, 0.0f};
#pragma unroll
    for (int mi = 0; mi < 2; mi++)
#pragma unroll
        for (int ni = 0; ni < 4; ni++) {
            rs[mi * 2 + 0] += acc[mi][ni][0] + acc[mi][ni][1];
            rs[mi * 2 + 1] += acc[mi][ni][2] + acc[mi][ni][3];
        }
#pragma unroll
    for (int q = 0; q < 4; q++) {
        rs[q] += __shfl_xor_sync(0xFFFFFFFF, rs[q], 1);
        rs[q] += __shfl_xor_sync(0xFFFFFFFF, rs[q], 2);
    }
    if ((lane & 3) == 0) {
        int rbase = m0 + wr * 32 + rl;
        atomicAdd(&deg[rbase], rs[0]);
        atomicAdd(&deg[rbase + 8], rs[1]);
        atomicAdd(&deg[rbase + 16], rs[2]);
        atomicAdd(&deg[rbase + 24], rs[3]);
    }
}

// plain fp32 64x64 tile GEMM (tiny x@w1, H@w2)
__global__ void sgemm64(const float* __restrict__ A, const float* __restrict__ B,
                        float* __restrict__ C, int M, int Nn, int K) {
    __shared__ float As[16][64];
    __shared__ float Bs[16][64];
    int tx = threadIdx.x, ty = threadIdx.y;
    int tid = ty * 16 + tx;
    int m0 = blockIdx.y * 64, n0 = blockIdx.x * 64;
    float acc[4][4];
#pragma unroll
    for (int i = 0; i < 4; i++)
#pragma unroll
        for (int j = 0; j < 4; j++) acc[i][j] = 0.0f;
    int la_r = tid / 16, la_k = tid % 16;
    int lb_k = tid / 64, lb_n = tid % 64;
    for (int k0 = 0; k0 < K; k0 += 16) {
#pragma unroll
        for (int r = 0; r < 4; r++)
            As[la_k][la_r + 16 * r] = A[(size_t)(m0 + la_r + 16 * r) * K + k0 + la_k];
#pragma unroll
        for (int r = 0; r < 4; r++) {
            int kk = lb_k + 4 * r;
            Bs[kk][lb_n] = (n0 + lb_n < Nn) ? B[(size_t)(k0 + kk) * Nn + n0 + lb_n] : 0.0f;
        }
        __syncthreads();
#pragma unroll
        for (int k = 0; k < 16; k++) {
            float a[4], b[4];
#pragma unroll
            for (int i = 0; i < 4; i++) a[i] = As[k][ty * 4 + i];
#pragma unroll
            for (int j = 0; j < 4; j++) b[j] = Bs[k][tx * 4 + j];
#pragma unroll
            for (int i = 0; i < 4; i++)
#pragma unroll
                for (int j = 0; j < 4; j++) acc[i][j] += a[i] * b[j];
        }
        __syncthreads();
    }
#pragma unroll
    for (int i = 0; i < 4; i++) {
        int row = m0 + ty * 4 + i;
#pragma unroll
        for (int j = 0; j < 4; j++) {
            int col = n0 + tx * 4 + j;
            if (col < Nn) C[(size_t)row * Nn + col] = acc[i][j];
        }
    }
}

// split-K fp32 GEMM with fused gcn-norm on A: C += (Dv fix(A) Dv) @ B.
__global__ void sgemmKS(const float* __restrict__ A, const float* __restrict__ dv,
                        const float* __restrict__ B, float* __restrict__ C,
                        int Nn, int K, int KS, const float* __restrict__ bias) {
    __shared__ float As[16][64];
    __shared__ float Bs[16][64];
    int tx = threadIdx.x, ty = threadIdx.y;
    int tid = ty * 16 + tx;
    int m0 = blockIdx.y * 64;
    int kLen = K / KS;
    int kStart = blockIdx.x * kLen;
    float acc[4][4];
#pragma unroll
    for (int i = 0; i < 4; i++)
#pragma unroll
        for (int j = 0; j < 4; j++) acc[i][j] = 0.0f;
    int la_r = tid / 16, la_k = tid % 16;
    int lb_k = tid / 64, lb_n = tid % 64;
    for (int k0 = kStart; k0 < kStart + kLen; k0 += 16) {
#pragma unroll
        for (int r = 0; r < 4; r++) {
            int row = m0 + la_r + 16 * r;
            int kc = k0 + la_k;
            float v = A[(size_t)row * K + kc];
            if (row == kc && v == 0.0f) v = 1.0f;
            As[la_k][la_r + 16 * r] = v * dv[row] * dv[kc];
        }
#pragma unroll
        for (int r = 0; r < 4; r++) {
            int kk = lb_k + 4 * r;
            Bs[kk][lb_n] = (lb_n < Nn) ? B[(size_t)(k0 + kk) * Nn + lb_n] : 0.0f;
        }
        __syncthreads();
#pragma unroll
        for (int k = 0; k < 16; k++) {
            float a[4], b[4];
#pragma unroll
            for (int i = 0; i < 4; i++) a[i] = As[k][ty * 4 + i];
#pragma unroll
            for (int j = 0; j < 4; j++) b[j] = Bs[k][tx * 4 + j];
#pragma unroll
            for (int i = 0; i < 4; i++)
#pragma unroll
                for (int j = 0; j < 4; j++) acc[i][j] += a[i] * b[j];
        }
        __syncthreads();
    }
#pragma unroll
    for (int i = 0; i < 4; i++) {
        int row = m0 + ty * 4 + i;
#pragma unroll
        for (int j = 0; j < 4; j++) {
            int col = tx * 4 + j;
            if (col < Nn) {
                float v = acc[i][j];
                if (bias != nullptr && kStart == 0) v += bias[col];
                atomicAdd(&C[(size_t)row * Nn + col], v);
            }
        }
    }
}

// ---------------- host orchestration ----------------

extern "C" void kernel_launch(void* const* d_in, const int* in_sizes, int n_in,
                              void* d_out, int out_size) {
    const float* x = (const float*)d_in[0];
    const int* edges[5];
    for (int i = 0; i < 5; i++) edges[i] = (const int*)d_in[1 + i];
    const float* pbp[2][8];
    for (int b = 0; b < 2; b++)
        for (int i = 0; i < 8; i++) pbp[b][i] = (const float*)d_in[6 + b * 8 + i];
    const float* w1    = (const float*)d_in[22];
    const float* bias1 = (const float*)d_in[23];
    const float* w2    = (const float*)d_in[24];
    const float* bias2 = (const float*)d_in[25];
    float* out = (float*)d_out;

    float *A_, *p1_, *p2_, *att_, *M_, *Mt_, *An_, *dinv_, *deg_, *diag_, *XW_, *H_, *HW_;
    cudaGetSymbolAddress((void**)&A_,    g_A);
    cudaGetSymbolAddress((void**)&p1_,   g_p1);
    cudaGetSymbolAddress((void**)&p2_,   g_p2);
    cudaGetSymbolAddress((void**)&att_,  g_att);
    cudaGetSymbolAddress((void**)&M_,    g_M);
    cudaGetSymbolAddress((void**)&Mt_,   g_Mt);
    cudaGetSymbolAddress((void**)&An_,   g_An);
    cudaGetSymbolAddress((void**)&dinv_, g_dinv);
    cudaGetSymbolAddress((void**)&deg_,  g_deg);
    cudaGetSymbolAddress((void**)&diag_, g_diag);
    cudaGetSymbolAddress((void**)&XW_,   g_XW);
    cudaGetSymbolAddress((void**)&H_,    g_H);
    cudaGetSymbolAddress((void**)&HW_,   g_HW);

    const size_t PLANE = (size_t)NV * NV;
    dim3 blk16(16, 16);

    float* Ab[2]   = { A_,   A_   + 3 * PLANE };
    float* p1b[2]  = { p1_,  p1_  + (size_t)16 * 512 * 512 };
    float* p2b[2]  = { p2_,  p2_  + (size_t)4 * 257 * 257 };
    float* attb[2] = { att_, att_ + 3 * PLANE };
    float* Mb[2]   = { M_,   M_   + PLANE };
    float* Mtb[2]  = { Mt_,  Mt_  + PLANE };

    // -------- setup --------
    cudaMemsetAsync(A_, 0, 6 * PLANE * sizeof(float), 0);
    cudaMemsetAsync(deg_, 0, 5 * NV * sizeof(float), 0);
    cudaMemsetAsync(H_, 0, (size_t)NV * HIDD * sizeof(float), 0);
    cudaMemsetAsync(out, 0, (size_t)NV * REPD * sizeof(float), 0);
    sgemm64<<<dim3(1, NV / 64), blk16>>>(x, w1, XW_, NV, HIDD, EMBD);

    // -------- scatter all 5 edge lists --------
    Sc5 sc;
    sc.e[0] = edges[0]; sc.A[0] = Ab[0];
    sc.e[1] = edges[1]; sc.A[1] = Ab[0] + PLANE;
    sc.e[2] = edges[2]; sc.A[2] = Ab[1];
    sc.e[3] = edges[3]; sc.A[3] = Ab[1] + PLANE;
    sc.e[4] = edges[4]; sc.A[4] = Ab[1] + 2 * PLANE;
    scatter_all<<<dim3((NE + 255) / 256, 5), 256>>>(sc);

    // -------- conv encoder (both paths batched) --------
    PathPtrs c1 = {{Ab[0], Ab[1]}, {pbp[0][0], pbp[1][0]}, {pbp[0][1], pbp[1][1]}, {p1b[0], p1b[1]}};
    conv1mma_both<<<dim3(32, 32, 2), blk16>>>(c1);

    PathPtrs c2 = {{p1b[0], p1b[1]}, {pbp[0][2], pbp[1][2]}, {pbp[0][3], pbp[1][3]}, {p2b[0], p2b[1]}};
    conv2pool_both<<<dim3(17, 17, 2), blk16>>>(c2);

    // fused tconv1 + tconv2 + sigmoid + adjacency multiply + att0 deg/diag
    FAtt fa;
    for (int p = 0; p < 2; p++) {
        fa.p2[p] = p2b[p];
        fa.w1[p] = pbp[p][4]; fa.b1[p] = pbp[p][5];
        fa.w2[p] = pbp[p][6]; fa.b2[p] = pbp[p][7];
        fa.A[p] = Ab[p]; fa.att[p] = attb[p];
        fa.deg[p] = deg_ + p * NV; fa.diag[p] = diag_ + p * NV;
    }
    ftconv_att_both<<<(2 * NV * 512) / 256, 256>>>(fa);
    dinv_fix<<<(2 * NV + 255) / 256, 256>>>(deg_, diag_, dinv_, 2 * NV);

    // -------- M-chain, norms fused into GEMMs --------
    {
        GemS gs;
        gs.A[0] = attb[0];         gs.A[1] = attb[1];
        gs.B[0] = attb[0] + PLANE; gs.B[1] = attb[1] + PLANE;
        gs.C[0] = Mtb[0];          gs.C[1] = Mtb[1];
        gs.dv[0] = dinv_;          gs.dv[1] = dinv_ + NV;
        gs.deg[0] = deg_ + 2 * NV; gs.deg[1] = deg_ + 3 * NV;
        gs.diag[0] = diag_ + 2 * NV; gs.diag[1] = diag_ + 3 * NV;
        tf32gemm_s<<<dim3(NV / 64, NV / 128, 2), 256>>>(gs);
        dinv_fix<<<(2 * NV + 255) / 256, 256>>>(deg_ + 2 * NV, diag_ + 2 * NV, dinv_ + 2 * NV, 2 * NV);
    }
    {
        GemS gs;
        gs.A[0] = Mtb[1];
        gs.B[0] = attb[1] + 2 * PLANE;
        gs.C[0] = Mb[1];
        gs.dv[0] = dinv_ + 3 * NV;
        gs.deg[0] = deg_ + 4 * NV;
        gs.diag[0] = diag_ + 4 * NV;
        gs.A[1] = gs.A[0]; gs.B[1] = gs.B[0]; gs.C[1] = gs.C[0];
        gs.dv[1] = gs.dv[0]; gs.deg[1] = gs.deg[0]; gs.diag[1] = gs.diag[0];
        tf32gemm_s<<<dim3(NV / 64, NV / 128, 1), 256>>>(gs);
        dinv_fix<<<(NV + 255) / 256, 256>>>(deg_ + 4 * NV, diag_ + 4 * NV, dinv_ + 4 * NV, NV);
    }

    // -------- scaled merge + final dinv --------
    emax_dinv<<<NV, 256>>>(Mtb[0], dinv_ + 2 * NV, Mb[1], dinv_ + 4 * NV, An_, dinv_ + 5 * NV);

    // -------- GCN layers, final norm fused into A-loads --------
    sgemmKS<<<dim3(8, NV / 64), blk16>>>(An_, dinv_ + 5 * NV, XW_, H_, HIDD, NV, 8, nullptr);
    bias_relu64<<<(NV * HIDD + 255) / 256, 256>>>(H_, bias1);
    sgemm64<<<dim3(1, NV / 64), blk16>>>(H_, w2, HW_, NV, REPD, HIDD);
    sgemmKS<<<dim3(8, NV / 64), blk16>>>(An_, dinv_ + 5 * NV, HW_, out, REPD, NV, 8, bias2);
}

// round 9
// speedup vs baseline: 2.1975x; 1.0120x over previous
#include <cuda_runtime.h>
#include <math.h>
#include <stdint.h>

// Problem constants
#define NV 1024
#define NE 32768
#define EMBD 128
#define HIDD 64
#define REPD 32

// ---------------- scratch (static device globals) ----------------
__device__ float g_A[2][3][NV][NV];
__device__ float g_p1[2][16][512][512];
__device__ float g_p2[2][4][257][257];
__device__ float g_att[2][3][NV][NV];
__device__ float g_M[2][NV][NV];
__device__ float g_Mt[2][NV][NV];
__device__ float g_An[NV][NV];
__device__ float g_dinv[6][NV];
__device__ float g_deg[5][NV];
__device__ float g_diag[5][NV];
__device__ float g_XW[NV][HIDD];
__device__ float g_H[NV][HIDD];
__device__ float g_HW[NV][REPD];

// ---------------- param structs ----------------
struct Sc5 { const int* e[5]; float* A[5]; float* degz; };
struct PathPtrs {
    const float* in[2]; const float* w[2]; const float* b[2]; float* out[2];
};
struct FAtt {
    const float* p2[2]; const float* w1[2]; const float* b1[2];
    const float* w2[2]; const float* b2[2]; const float* A[2]; float* att[2];
    float* deg[2]; float* diag[2];
};
struct GemS {
    const float* A[2]; const float* B[2]; float* C[2];
    const float* degIn[2]; const float* diagIn[2];
    float* deg[2]; float* diag[2];
};

// ---------------- helpers ----------------
__device__ __forceinline__ uint32_t f2tf(float f) {
    uint32_t r;
    asm("cvt.rna.tf32.f32 %0, %1;" : "=r"(r) : "f"(f));
    return r;
}

__device__ __forceinline__ void mma_tf32(float* c, const uint32_t* a, uint32_t b0, uint32_t b1) {
    asm volatile(
        "mma.sync.aligned.m16n8k8.row.col.f32.tf32.tf32.f32 "
        "{%0,%1,%2,%3}, {%4,%5,%6,%7}, {%8,%9}, {%0,%1,%2,%3};"
        : "+f"(c[0]), "+f"(c[1]), "+f"(c[2]), "+f"(c[3])
        : "r"(a[0]), "r"(a[1]), "r"(a[2]), "r"(a[3]), "r"(b0), "r"(b1));
}

// ---------------- kernels ----------------

__global__ void scatter_all(Sc5 s) {
    int j = blockIdx.y;
    int k = blockIdx.x * blockDim.x + threadIdx.x;
    if (j == 0 && k < 5 * NV) s.degz[k] = 0.0f;   // zero deg[] (used by ftconv + GEMMs)
    if (k < NE) {
        const int* e = s.e[j];
        atomicAdd(&s.A[j][e[k] * NV + e[NE + k]], 1.0f);
    }
}

// ---- conv1 (3x3, pad1, L->16) + relu + maxpool2 via tf32 MMA (fp32-exact hi/lo) ----
template <int L>
__device__ __forceinline__ void conv1mma_impl(const float* __restrict__ A,
                                              const float* __restrict__ w,
                                              const float* __restrict__ b,
                                              float* __restrict__ p1,
                                              float* __restrict__ tile,
                                              float* __restrict__ whi,
                                              float* __restrict__ wlo,
                                              float* __restrict__ sb) {
    constexpr int KS = (L * 9 + 7) / 8;
    int t = threadIdx.y * 16 + threadIdx.x;
    int lane = t & 31, wid = t >> 5;

    for (int i = t; i < 512; i += 256) {
        int oc = i >> 5, k = i & 31;
        float wv = (k < L * 9) ? w[oc * L * 9 + k] : 0.0f;
        float hi = __uint_as_float(f2tf(wv));
        whi[i] = hi;
        wlo[i] = __uint_as_float(f2tf(wv - hi));
    }
    if (t < 16) sb[t] = b[t];

    int gy0 = blockIdx.y * 32 - 1, gx0 = blockIdx.x * 32 - 1;
    for (int l = 0; l < L; l++)
        for (int i = t; i < 34 * 34; i += 256) {
            int r = i / 34, c = i % 34;
            int gy = gy0 + r, gx = gx0 + c;
            tile[(l * 34 + r) * 36 + c] = (gy >= 0 && gy < NV && gx >= 0 && gx < NV)
                                              ? A[((size_t)l * NV + gy) * NV + gx] : 0.0f;
        }
    __syncthreads();

    uint32_t ahi[KS][4], alo[KS][4];
    int r0 = (lane >> 2) * 32, r1 = ((lane >> 2) + 8) * 32;
#pragma unroll
    for (int s = 0; s < KS; s++) {
        int c0 = 8 * s + (lane & 3);
        ahi[s][0] = __float_as_uint(whi[r0 + c0]);
        ahi[s][1] = __float_as_uint(whi[r1 + c0]);
        ahi[s][2] = __float_as_uint(whi[r0 + c0 + 4]);
        ahi[s][3] = __float_as_uint(whi[r1 + c0 + 4]);
        alo[s][0] = __float_as_uint(wlo[r0 + c0]);
        alo[s][1] = __float_as_uint(wlo[r1 + c0]);
        alo[s][2] = __float_as_uint(wlo[r0 + c0 + 4]);
        alo[s][3] = __float_as_uint(wlo[r1 + c0 + 4]);
    }

    int boff[KS][2];
#pragma unroll
    for (int s = 0; s < KS; s++)
#pragma unroll
        for (int h = 0; h < 2; h++) {
            int k = 8 * s + (lane & 3) + 4 * h;
            if (k >= L * 9) k = 0;
            int l = k / 9, r = k % 9;
            boff[s][h] = (l * 34 + r / 3) * 36 + (r % 3) + (lane >> 2);
        }

    for (int u = wid; u < 64; u += 8) {
        int py = u >> 2, ux = u & 3;
        int base0 = (2 * py) * 36 + 8 * ux;
        int base1 = base0 + 36;
        float acc0[4] = {0.f, 0.f, 0.f, 0.f};
        float acc1[4] = {0.f, 0.f, 0.f, 0.f};
#pragma unroll
        for (int s = 0; s < KS; s++) {
            uint32_t b00 = __float_as_uint(tile[boff[s][0] + base0]);
            uint32_t b01 = __float_as_uint(tile[boff[s][1] + base0]);
            mma_tf32(acc0, ahi[s], b00, b01);
            mma_tf32(acc0, alo[s], b00, b01);
            uint32_t b10 = __float_as_uint(tile[boff[s][0] + base1]);
            uint32_t b11 = __float_as_uint(tile[boff[s][1] + base1]);
            mma_tf32(acc1, ahi[s], b10, b11);
            mma_tf32(acc1, alo[s], b10, b11);
        }
        int oc0 = lane >> 2, oc1 = oc0 + 8;
        int ox = blockIdx.x * 16 + 4 * ux + (lane & 3);
        int oy = blockIdx.y * 16 + py;
        float m0 = fmaxf(fmaxf(acc0[0], acc0[1]), fmaxf(acc1[0], acc1[1]));
        float m1 = fmaxf(fmaxf(acc0[2], acc0[3]), fmaxf(acc1[2], acc1[3]));
        p1[((size_t)oc0 * 512 + oy) * 512 + ox] = fmaxf(m0 + sb[oc0], 0.0f);
        p1[((size_t)oc1 * 512 + oy) * 512 + ox] = fmaxf(m1 + sb[oc1], 0.0f);
    }
}

__global__ void __launch_bounds__(256) conv1mma_both(PathPtrs p) {
    __shared__ float tile[3 * 34 * 36];
    __shared__ float whi[512], wlo[512];
    __shared__ float sb[16];
    int path = blockIdx.z;
    if (path == 0)
        conv1mma_impl<2>(p.in[0], p.w[0], p.b[0], p.out[0], tile, whi, wlo, sb);
    else
        conv1mma_impl<3>(p.in[1], p.w[1], p.b[1], p.out[1], tile, whi, wlo, sb);
}

// ---- conv2 (3x3, pad2, 16->4) + relu + maxpool2 (proven round-6 version) ----
__global__ void conv2pool_both(PathPtrs pp) {
    __shared__ float tile[36 * 38];
    __shared__ float sw[576];
    __shared__ float sb[4];
    int path = blockIdx.z;
    const float* p1 = pp.in[path];
    float* p2 = pp.out[path];
    int tx = threadIdx.x, ty = threadIdx.y;
    int t = ty * 16 + tx;
    for (int i = t; i < 576; i += 256) sw[i] = pp.w[path][i];
    if (t < 4) sb[t] = pp.b[path][t];

    int gy0 = blockIdx.y * 32 - 2, gx0 = blockIdx.x * 32 - 2;

    int srow[6], scol[6], sok[6];
    float r[6];
#pragma unroll
    for (int s = 0; s < 6; s++) {
        int i = t + s * 256;
        srow[s] = i / 36; scol[s] = i % 36;
        sok[s] = (i < 1296);
    }
#pragma unroll
    for (int s = 0; s < 6; s++) {
        if (sok[s]) {
            int gy = gy0 + srow[s], gx = gx0 + scol[s];
            r[s] = (gy >= 0 && gy < 512 && gx >= 0 && gx < 512)
                       ? p1[(size_t)gy * 512 + gx] : 0.0f;
        }
    }

    float acc[4][2][2];
#pragma unroll
    for (int oc = 0; oc < 4; oc++)
#pragma unroll
        for (int py = 0; py < 2; py++)
#pragma unroll
            for (int px = 0; px < 2; px++) acc[oc][py][px] = 0.0f;

    __syncthreads();

    for (int ci = 0; ci < 16; ci++) {
#pragma unroll
        for (int s = 0; s < 6; s++)
            if (sok[s]) tile[srow[s] * 38 + scol[s]] = r[s];
        __syncthreads();
        if (ci < 15) {
#pragma unroll
            for (int s = 0; s < 6; s++) {
                if (sok[s]) {
                    int gy = gy0 + srow[s], gx = gx0 + scol[s];
                    r[s] = (gy >= 0 && gy < 512 && gx >= 0 && gx < 512)
                               ? p1[((size_t)(ci + 1) * 512 + gy) * 512 + gx] : 0.0f;
                }
            }
        }
        float patch[4][4];
#pragma unroll
        for (int rw = 0; rw < 4; rw++)
#pragma unroll
            for (int c = 0; c < 4; c++)
                patch[rw][c] = tile[(2 * ty + rw) * 38 + 2 * tx + c];
#pragma unroll
        for (int oc = 0; oc < 4; oc++)
#pragma unroll
            for (int ky = 0; ky < 3; ky++)
#pragma unroll
                for (int kx = 0; kx < 3; kx++) {
                    float wv = sw[((oc * 16 + ci) * 3 + ky) * 3 + kx];
                    acc[oc][0][0] += wv * patch[ky][kx];
                    acc[oc][0][1] += wv * patch[ky][kx + 1];
                    acc[oc][1][0] += wv * patch[ky + 1][kx];
                    acc[oc][1][1] += wv * patch[ky + 1][kx + 1];
                }
        __syncthreads();
    }
    int x = blockIdx.x * 16 + tx, y = blockIdx.y * 16 + ty;
    if (x < 257 && y < 257) {
#pragma unroll
        for (int oc = 0; oc < 4; oc++) {
            float m = fmaxf(fmaxf(acc[oc][0][0], acc[oc][0][1]),
                            fmaxf(acc[oc][1][0], acc[oc][1][1])) + sb[oc];
            p2[((size_t)oc * 257 + y) * 257 + x] = fmaxf(m, 0.0f);
        }
    }
}

// ---- fused tconv1 + tconv2 + sigmoid + crop + adjacency multiply + att0 deg/diag ----
// 4 outputs per thread (x = 4q..4q+3): both parity pairs share the same p2 inputs.
template <int L>
__device__ __forceinline__ void ftconv4_impl(const float* __restrict__ p2,
                                             const float* __restrict__ sw1,
                                             const float* __restrict__ sb1,
                                             const float* __restrict__ sw2,
                                             const float* __restrict__ sb2,
                                             const float* __restrict__ A,
                                             float* __restrict__ att,
                                             float* __restrict__ deg,
                                             float* __restrict__ diag,
                                             int q, int y) {
    int ky2 = (y + 1) & 1;
    int iy1 = (y - 1 + ky2) >> 1;
    int ky1 = (iy1 + 1) & 1;
    int iy0 = (iy1 - 1 + ky1) >> 1;
    // both x-pairs (t1 cols 2q and 2q+1) map to p2 col q

    float p[4];
#pragma unroll
    for (int cj = 0; cj < 4; cj++) p[cj] = p2[((size_t)cj * 257 + iy0) * 257 + q];

    float tA[16], tB[16];   // t1 values for t1-col 2q (kx1=1) and 2q+1 (kx1=0)
#pragma unroll
    for (int ci = 0; ci < 16; ci++) {
        float sA = sb1[ci], sB = sb1[ci];
#pragma unroll
        for (int cj = 0; cj < 4; cj++) {
            int base = ((ci * 4 + cj) * 2 + ky1) * 2;
            sA += sw1[base + 1] * p[cj];
            sB += sw1[base + 0] * p[cj];
        }
        tA[ci] = fmaxf(sA, 0.0f);
        tB[ci] = fmaxf(sB, 0.0f);
    }

    float d0 = 0.f, d1 = 0.f, d2 = 0.f, d3 = 0.f;
#pragma unroll
    for (int l = 0; l < L; l++) {
        float s0A = sb2[l], s1A = sb2[l], s0B = sb2[l], s1B = sb2[l];
#pragma unroll
        for (int ci = 0; ci < 16; ci++) {
            int base = ((l * 16 + ci) * 2 + ky2) * 2;
            float w1v = sw2[base + 1], w0v = sw2[base + 0];
            s0A += w1v * tA[ci]; s1A += w0v * tA[ci];
            s0B += w1v * tB[ci]; s1B += w0v * tB[ci];
        }
        float g0 = 1.0f / (1.0f + expf(-s0A));
        float g1 = 1.0f / (1.0f + expf(-s1A));
        float g2 = 1.0f / (1.0f + expf(-s0B));
        float g3 = 1.0f / (1.0f + expf(-s1B));
        size_t off = (size_t)l * NV * NV + (size_t)y * NV + 4 * q;
        float4 a = *(const float4*)&A[off];
        float4 v = make_float4(a.x * g0, a.y * g1, a.z * g2, a.w * g3);
        *(float4*)&att[off] = v;
        if (l == 0) { d0 = v.x; d1 = v.y; d2 = v.z; d3 = v.w; }
    }

    float s = (d0 + d1) + (d2 + d3);
#pragma unroll
    for (int o = 16; o > 0; o >>= 1) s += __shfl_xor_sync(0xFFFFFFFF, s, o);
    if ((threadIdx.x & 31) == 0) atomicAdd(&deg[y], s);
    if ((y >> 2) == q) {
        int sel = y & 3;
        diag[y] = sel == 0 ? d0 : sel == 1 ? d1 : sel == 2 ? d2 : d3;
    }
}

__global__ void ftconv_att_both(FAtt fa) {
    __shared__ float sw1[256], sb1[16], sw2[192], sb2[3];
    int gidx = blockIdx.x * blockDim.x + threadIdx.x;
    const int PL = NV * 256;
    int path = gidx / PL;
    int idx = gidx - path * PL;
    int q = idx & 255, y = idx >> 8;
    const int L = (path == 0) ? 2 : 3;
    int t = threadIdx.x;
    if (t < 256) sw1[t] = fa.w1[path][t];
    if (t < 16) sb1[t] = fa.b1[path][t];
    for (int i = t; i < L * 64; i += 256) sw2[i] = fa.w2[path][i];
    if (t < L) sb2[t] = fa.b2[path][t];
    __syncthreads();
    if (path == 0)
        ftconv4_impl<2>(fa.p2[0], sw1, sb1, sw2, sb2, fa.A[0], fa.att[0],
                        fa.deg[0], fa.diag[0], q, y);
    else
        ftconv4_impl<3>(fa.p2[1], sw1, sb1, sw2, sb2, fa.A[1], fa.att[1],
                        fa.deg[1], fa.diag[1], q, y);
}

// ---- dinv from accumulated deg/diag ----
__global__ void dinv_fix(const float* __restrict__ deg, const float* __restrict__ diag,
                         float* __restrict__ dv, int n) {
    int i = blockIdx.x * blockDim.x + threadIdx.x;
    if (i < n) {
        float d = deg[i];
        if (diag[i] == 0.0f) d += 1.0f;
        dv[i] = d > 0.0f ? rsqrtf(d) : 0.0f;
    }
}

// ---- scaled max-merge + row-sum/dinv ----
__global__ void emax_dinv(const float* __restrict__ a, const float* __restrict__ dva,
                          const float* __restrict__ b, const float* __restrict__ dvb,
                          float* __restrict__ o, float* __restrict__ dv) {
    int row = blockIdx.x;
    float dar = dva[row], dbr = dvb[row];
    __shared__ float sh[256];
    __shared__ float sdiag;
    float s = 0.0f;
    for (int j = threadIdx.x; j < NV; j += 256) {
        float va = a[(size_t)row * NV + j];
        if (j == row && va == 0.0f) va = 1.0f;
        va *= dar * dva[j];
        float vb = b[(size_t)row * NV + j];
        if (j == row && vb == 0.0f) vb = 1.0f;
        vb *= dbr * dvb[j];
        float v = fmaxf(va, vb);
        o[(size_t)row * NV + j] = v;
        if (j == row) sdiag = v;
        s += v;
    }
    sh[threadIdx.x] = s;
    __syncthreads();
    for (int off = 128; off > 0; off >>= 1) {
        if (threadIdx.x < off) sh[threadIdx.x] += sh[threadIdx.x + off];
        __syncthreads();
    }
    if (threadIdx.x == 0) {
        float d = sh[0];
        if (sdiag == 0.0f) d += 1.0f;
        dv[row] = d > 0.0f ? rsqrtf(d) : 0.0f;
    }
}

// ---------------- tf32 GEMM: dv computed in prologue from deg/diag; norm fused ----
__device__ __forceinline__ void fix_scale4(float4& v, int row, int kc, float dvr,
                                           const float* __restrict__ dv) {
    float4 dk = *(const float4*)&dv[kc];
    float* p = &v.x;
#pragma unroll
    for (int q = 0; q < 4; q++)
        if (row == kc + q && p[q] == 0.0f) p[q] = 1.0f;
    v.x *= dvr * dk.x; v.y *= dvr * dk.y; v.z *= dvr * dk.z; v.w *= dvr * dk.w;
}

__global__ void __launch_bounds__(256) tf32gemm_s(GemS g) {
    const float* __restrict__ A = g.A[blockIdx.z];
    const float* __restrict__ B = g.B[blockIdx.z];
    float* __restrict__ C = g.C[blockIdx.z];
    const float* __restrict__ degIn = g.degIn[blockIdx.z];
    const float* __restrict__ diagIn = g.diagIn[blockIdx.z];
    float* __restrict__ deg = g.deg[blockIdx.z];
    float* __restrict__ diag = g.diag[blockIdx.z];
    const int Nn = NV, K = NV;

    __shared__ float As[2][16][136];
    __shared__ float Bs[2][16][72];
    __shared__ __align__(16) float sdv[NV];

    const int tid = threadIdx.x;
    const int lane = tid & 31;
    const int wid = tid >> 5;
    const int wr = wid & 3;
    const int wc = wid >> 2;
    const int m0 = blockIdx.y * 128;
    const int n0 = blockIdx.x * 64;

    // prologue: dv from deg/diag (removes dinv_fix launch)
    for (int i = tid; i < NV; i += 256) {
        float d = degIn[i];
        if (diagIn[i] == 0.0f) d += 1.0f;
        sdv[i] = d > 0.0f ? rsqrtf(d) : 0.0f;
    }
    __syncthreads();

    float acc[2][4][4];
#pragma unroll
    for (int mi = 0; mi < 2; mi++)
#pragma unroll
        for (int ni = 0; ni < 4; ni++)
#pragma unroll
            for (int r = 0; r < 4; r++) acc[mi][ni][r] = 0.0f;

    const int ar = tid >> 2;
    const int ac4 = (tid & 3) << 2;
    const int bk = tid >> 4;
    const int bn4 = (tid & 15) << 2;
    const int rowA0 = m0 + ar, rowA1 = m0 + 64 + ar;
    const float dvr0 = sdv[rowA0], dvr1 = sdv[rowA1];

    float4 av0, av1, bv;
    const int T = K >> 4;

    av0 = *(const float4*)&A[(size_t)rowA0 * K + ac4];
    av1 = *(const float4*)&A[(size_t)rowA1 * K + ac4];
    bv  = *(const float4*)&B[(size_t)bk * Nn + n0 + bn4];
    fix_scale4(av0, rowA0, ac4, dvr0, sdv);
    fix_scale4(av1, rowA1, ac4, dvr1, sdv);

    As[0][ac4 + 0][ar] = __uint_as_float(f2tf(av0.x));
    As[0][ac4 + 1][ar] = __uint_as_float(f2tf(av0.y));
    As[0][ac4 + 2][ar] = __uint_as_float(f2tf(av0.z));
    As[0][ac4 + 3][ar] = __uint_as_float(f2tf(av0.w));
    As[0][ac4 + 0][ar + 64] = __uint_as_float(f2tf(av1.x));
    As[0][ac4 + 1][ar + 64] = __uint_as_float(f2tf(av1.y));
    As[0][ac4 + 2][ar + 64] = __uint_as_float(f2tf(av1.z));
    As[0][ac4 + 3][ar + 64] = __uint_as_float(f2tf(av1.w));
    {
        float4 bt;
        bt.x = __uint_as_float(f2tf(bv.x));
        bt.y = __uint_as_float(f2tf(bv.y));
        bt.z = __uint_as_float(f2tf(bv.z));
        bt.w = __uint_as_float(f2tf(bv.w));
        *(float4*)&Bs[0][bk][bn4] = bt;
    }
    __syncthreads();

    for (int t = 0; t < T; t++) {
        int cur = t & 1;
        if (t + 1 < T) {
            int kb = (t + 1) << 4;
            av0 = *(const float4*)&A[(size_t)rowA0 * K + kb + ac4];
            av1 = *(const float4*)&A[(size_t)rowA1 * K + kb + ac4];
            bv  = *(const float4*)&B[(size_t)(kb + bk) * Nn + n0 + bn4];
            fix_scale4(av0, rowA0, kb + ac4, dvr0, sdv);
            fix_scale4(av1, rowA1, kb + ac4, dvr1, sdv);
        }
#pragma unroll
        for (int ks = 0; ks < 2; ks++) {
            const int k0 = ks * 8;
            uint32_t a[2][4], b[4][2];
            const int kl = k0 + (lane & 3);
            const int rl = lane >> 2;
#pragma unroll
            for (int mi = 0; mi < 2; mi++) {
                int m = wr * 32 + mi * 16 + rl;
                a[mi][0] = __float_as_uint(As[cur][kl][m]);
                a[mi][1] = __float_as_uint(As[cur][kl][m + 8]);
                a[mi][2] = __float_as_uint(As[cur][kl + 4][m]);
                a[mi][3] = __float_as_uint(As[cur][kl + 4][m + 8]);
            }
#pragma unroll
            for (int ni = 0; ni < 4; ni++) {
                int n = wc * 32 + ni * 8 + rl;
                b[ni][0] = __float_as_uint(Bs[cur][kl][n]);
                b[ni][1] = __float_as_uint(Bs[cur][kl + 4][n]);
            }
#pragma unroll
            for (int mi = 0; mi < 2; mi++)
#pragma unroll
                for (int ni = 0; ni < 4; ni++) {
                    asm volatile(
                        "mma.sync.aligned.m16n8k8.row.col.f32.tf32.tf32.f32 "
                        "{%0,%1,%2,%3}, {%4,%5,%6,%7}, {%8,%9}, {%0,%1,%2,%3};"
                        : "+f"(acc[mi][ni][0]), "+f"(acc[mi][ni][1]),
                          "+f"(acc[mi][ni][2]), "+f"(acc[mi][ni][3])
                        : "r"(a[mi][0]), "r"(a[mi][1]), "r"(a[mi][2]), "r"(a[mi][3]),
                          "r"(b[ni][0]), "r"(b[ni][1]));
                }
        }
        if (t + 1 < T) {
            int nxt = (t + 1) & 1;
            As[nxt][ac4 + 0][ar] = __uint_as_float(f2tf(av0.x));
            As[nxt][ac4 + 1][ar] = __uint_as_float(f2tf(av0.y));
            As[nxt][ac4 + 2][ar] = __uint_as_float(f2tf(av0.z));
            As[nxt][ac4 + 3][ar] = __uint_as_float(f2tf(av0.w));
            As[nxt][ac4 + 0][ar + 64] = __uint_as_float(f2tf(av1.x));
            As[nxt][ac4 + 1][ar + 64] = __uint_as_float(f2tf(av1.y));
            As[nxt][ac4 + 2][ar + 64] = __uint_as_float(f2tf(av1.z));
            As[nxt][ac4 + 3][ar + 64] = __uint_as_float(f2tf(av1.w));
            float4 bt;
            bt.x = __uint_as_float(f2tf(bv.x));
            bt.y = __uint_as_float(f2tf(bv.y));
            bt.z = __uint_as_float(f2tf(bv.z));
            bt.w = __uint_as_float(f2tf(bv.w));
            *(float4*)&Bs[nxt][bk][bn4] = bt;
            __syncthreads();
        }
    }

    const int rl = lane >> 2;
#pragma unroll
    for (int mi = 0; mi < 2; mi++) {
        int row = m0 + wr * 32 + mi * 16 + rl;
#pragma unroll
        for (int ni = 0; ni < 4; ni++) {
            int col = n0 + wc * 32 + ni * 8 + ((lane & 3) << 1);
            if (row == col) diag[row] = acc[mi][ni][0];
            if (row == col + 1) diag[row] = acc[mi][ni][1];
            if (row + 8 == col) diag[row + 8] = acc[mi][ni][2];
            if (row + 8 == col + 1) diag[row + 8] = acc[mi][ni][3];
            *(float2*)&C[(size_t)row * Nn + col] = make_float2(acc[mi][ni][0], acc[mi][ni][1]);
            *(float2*)&C[(size_t)(row + 8) * Nn + col] = make_float2(acc[mi][ni][2], acc[mi][ni][3]);
        }
    }
    float rs[4] = {0.0f, 0.0f, 0.0f, 0.0f};
#pragma unroll
    for (int mi = 0; mi < 2; mi++)
#pragma unroll
        for (int ni = 0; ni < 4; ni++) {
            rs[mi * 2 + 0] += acc[mi][ni][0] + acc[mi][ni][1];
            rs[mi * 2 + 1] += acc[mi][ni][2] + acc[mi][ni][3];
        }
#pragma unroll
    for (int q = 0; q < 4; q++) {
        rs[q] += __shfl_xor_sync(0xFFFFFFFF, rs[q], 1);
        rs[q] += __shfl_xor_sync(0xFFFFFFFF, rs[q], 2);
    }
    if ((lane & 3) == 0) {
        int rbase = m0 + wr * 32 + rl;
        atomicAdd(&deg[rbase], rs[0]);
        atomicAdd(&deg[rbase + 8], rs[1]);
        atomicAdd(&deg[rbase + 16], rs[2]);
        atomicAdd(&deg[rbase + 24], rs[3]);
    }
}

// plain fp32 64x64 tile GEMM; optional bias+relu applied to A-operand on load.
__global__ void sgemm64(const float* __restrict__ A, const float* __restrict__ B,
                        float* __restrict__ C, int M, int Nn, int K,
                        const float* __restrict__ abias) {
    __shared__ float As[16][64];
    __shared__ float Bs[16][64];
    int tx = threadIdx.x, ty = threadIdx.y;
    int tid = ty * 16 + tx;
    int m0 = blockIdx.y * 64, n0 = blockIdx.x * 64;
    float acc[4][4];
#pragma unroll
    for (int i = 0; i < 4; i++)
#pragma unroll
        for (int j = 0; j < 4; j++) acc[i][j] = 0.0f;
    int la_r = tid / 16, la_k = tid % 16;
    int lb_k = tid / 64, lb_n = tid % 64;
    for (int k0 = 0; k0 < K; k0 += 16) {
#pragma unroll
        for (int r = 0; r < 4; r++) {
            float v = A[(size_t)(m0 + la_r + 16 * r) * K + k0 + la_k];
            if (abias != nullptr) v = fmaxf(v + abias[k0 + la_k], 0.0f);
            As[la_k][la_r + 16 * r] = v;
        }
#pragma unroll
        for (int r = 0; r < 4; r++) {
            int kk = lb_k + 4 * r;
            Bs[kk][lb_n] = (n0 + lb_n < Nn) ? B[(size_t)(k0 + kk) * Nn + n0 + lb_n] : 0.0f;
        }
        __syncthreads();
#pragma unroll
        for (int k = 0; k < 16; k++) {
            float a[4], b[4];
#pragma unroll
            for (int i = 0; i < 4; i++) a[i] = As[k][ty * 4 + i];
#pragma unroll
            for (int j = 0; j < 4; j++) b[j] = Bs[k][tx * 4 + j];
#pragma unroll
            for (int i = 0; i < 4; i++)
#pragma unroll
                for (int j = 0; j < 4; j++) acc[i][j] += a[i] * b[j];
        }
        __syncthreads();
    }
#pragma unroll
    for (int i = 0; i < 4; i++) {
        int row = m0 + ty * 4 + i;
#pragma unroll
        for (int j = 0; j < 4; j++) {
            int col = n0 + tx * 4 + j;
            if (col < Nn) C[(size_t)row * Nn + col] = acc[i][j];
        }
    }
}

// split-K fp32 GEMM with fused gcn-norm on A: C += (Dv fix(A) Dv) @ B.
__global__ void sgemmKS(const float* __restrict__ A, const float* __restrict__ dv,
                        const float* __restrict__ B, float* __restrict__ C,
                        int Nn, int K, int KS, const float* __restrict__ bias) {
    __shared__ float As[16][64];
    __shared__ float Bs[16][64];
    int tx = threadIdx.x, ty = threadIdx.y;
    int tid = ty * 16 + tx;
    int m0 = blockIdx.y * 64;
    int kLen = K / KS;
    int kStart = blockIdx.x * kLen;
    float acc[4][4];
#pragma unroll
    for (int i = 0; i < 4; i++)
#pragma unroll
        for (int j = 0; j < 4; j++) acc[i][j] = 0.0f;
    int la_r = tid / 16, la_k = tid % 16;
    int lb_k = tid / 64, lb_n = tid % 64;
    for (int k0 = kStart; k0 < kStart + kLen; k0 += 16) {
#pragma unroll
        for (int r = 0; r < 4; r++) {
            int row = m0 + la_r + 16 * r;
            int kc = k0 + la_k;
            float v = A[(size_t)row * K + kc];
            if (row == kc && v == 0.0f) v = 1.0f;
            As[la_k][la_r + 16 * r] = v * dv[row] * dv[kc];
        }
#pragma unroll
        for (int r = 0; r < 4; r++) {
            int kk = lb_k + 4 * r;
            Bs[kk][lb_n] = (lb_n < Nn) ? B[(size_t)(k0 + kk) * Nn + lb_n] : 0.0f;
        }
        __syncthreads();
#pragma unroll
        for (int k = 0; k < 16; k++) {
            float a[4], b[4];
#pragma unroll
            for (int i = 0; i < 4; i++) a[i] = As[k][ty * 4 + i];
#pragma unroll
            for (int j = 0; j < 4; j++) b[j] = Bs[k][tx * 4 + j];
#pragma unroll
            for (int i = 0; i < 4; i++)
#pragma unroll
                for (int j = 0; j < 4; j++) acc[i][j] += a[i] * b[j];
        }
        __syncthreads();
    }
#pragma unroll
    for (int i = 0; i < 4; i++) {
        int row = m0 + ty * 4 + i;
#pragma unroll
        for (int j = 0; j < 4; j++) {
            int col = tx * 4 + j;
            if (col < Nn) {
                float v = acc[i][j];
                if (bias != nullptr && kStart == 0) v += bias[col];
                atomicAdd(&C[(size_t)row * Nn + col], v);
            }
        }
    }
}

// ---------------- host orchestration ----------------

extern "C" void kernel_launch(void* const* d_in, const int* in_sizes, int n_in,
                              void* d_out, int out_size) {
    const float* x = (const float*)d_in[0];
    const int* edges[5];
    for (int i = 0; i < 5; i++) edges[i] = (const int*)d_in[1 + i];
    const float* pbp[2][8];
    for (int b = 0; b < 2; b++)
        for (int i = 0; i < 8; i++) pbp[b][i] = (const float*)d_in[6 + b * 8 + i];
    const float* w1    = (const float*)d_in[22];
    const float* bias1 = (const float*)d_in[23];
    const float* w2    = (const float*)d_in[24];
    const float* bias2 = (const float*)d_in[25];
    float* out = (float*)d_out;

    float *A_, *p1_, *p2_, *att_, *M_, *Mt_, *An_, *dinv_, *deg_, *diag_, *XW_, *H_, *HW_;
    cudaGetSymbolAddress((void**)&A_,    g_A);
    cudaGetSymbolAddress((void**)&p1_,   g_p1);
    cudaGetSymbolAddress((void**)&p2_,   g_p2);
    cudaGetSymbolAddress((void**)&att_,  g_att);
    cudaGetSymbolAddress((void**)&M_,    g_M);
    cudaGetSymbolAddress((void**)&Mt_,   g_Mt);
    cudaGetSymbolAddress((void**)&An_,   g_An);
    cudaGetSymbolAddress((void**)&dinv_, g_dinv);
    cudaGetSymbolAddress((void**)&deg_,  g_deg);
    cudaGetSymbolAddress((void**)&diag_, g_diag);
    cudaGetSymbolAddress((void**)&XW_,   g_XW);
    cudaGetSymbolAddress((void**)&H_,    g_H);
    cudaGetSymbolAddress((void**)&HW_,   g_HW);

    const size_t PLANE = (size_t)NV * NV;
    dim3 blk16(16, 16);

    float* Ab[2]   = { A_,   A_   + 3 * PLANE };
    float* p1b[2]  = { p1_,  p1_  + (size_t)16 * 512 * 512 };
    float* p2b[2]  = { p2_,  p2_  + (size_t)4 * 257 * 257 };
    float* attb[2] = { att_, att_ + 3 * PLANE };
    float* Mb[2]   = { M_,   M_   + PLANE };
    float* Mtb[2]  = { Mt_,  Mt_  + PLANE };

    // -------- setup --------
    cudaMemsetAsync(A_, 0, 6 * PLANE * sizeof(float), 0);
    cudaMemsetAsync(H_, 0, (size_t)NV * HIDD * sizeof(float), 0);
    cudaMemsetAsync(out, 0, (size_t)NV * REPD * sizeof(float), 0);
    sgemm64<<<dim3(1, NV / 64), blk16>>>(x, w1, XW_, NV, HIDD, EMBD, nullptr);

    // -------- scatter all 5 edge lists (also zeros deg) --------
    Sc5 sc;
    sc.e[0] = edges[0]; sc.A[0] = Ab[0];
    sc.e[1] = edges[1]; sc.A[1] = Ab[0] + PLANE;
    sc.e[2] = edges[2]; sc.A[2] = Ab[1];
    sc.e[3] = edges[3]; sc.A[3] = Ab[1] + PLANE;
    sc.e[4] = edges[4]; sc.A[4] = Ab[1] + 2 * PLANE;
    sc.degz = deg_;
    scatter_all<<<dim3((NE + 255) / 256, 5), 256>>>(sc);

    // -------- conv encoder (both paths batched) --------
    PathPtrs c1 = {{Ab[0], Ab[1]}, {pbp[0][0], pbp[1][0]}, {pbp[0][1], pbp[1][1]}, {p1b[0], p1b[1]}};
    conv1mma_both<<<dim3(32, 32, 2), blk16>>>(c1);

    PathPtrs c2 = {{p1b[0], p1b[1]}, {pbp[0][2], pbp[1][2]}, {pbp[0][3], pbp[1][3]}, {p2b[0], p2b[1]}};
    conv2pool_both<<<dim3(17, 17, 2), blk16>>>(c2);

    // fused tconv1 + tconv2 + sigmoid + adjacency multiply + att0 deg/diag (4-wide)
    FAtt fa;
    for (int p = 0; p < 2; p++) {
        fa.p2[p] = p2b[p];
        fa.w1[p] = pbp[p][4]; fa.b1[p] = pbp[p][5];
        fa.w2[p] = pbp[p][6]; fa.b2[p] = pbp[p][7];
        fa.A[p] = Ab[p]; fa.att[p] = attb[p];
        fa.deg[p] = deg_ + p * NV; fa.diag[p] = diag_ + p * NV;
    }
    ftconv_att_both<<<2 * NV, 256>>>(fa);

    // -------- M-chain, norms + dv computed inside GEMMs --------
    {
        GemS gs;
        gs.A[0] = attb[0];          gs.A[1] = attb[1];
        gs.B[0] = attb[0] + PLANE;  gs.B[1] = attb[1] + PLANE;
        gs.C[0] = Mtb[0];           gs.C[1] = Mtb[1];
        gs.degIn[0] = deg_;         gs.degIn[1] = deg_ + NV;
        gs.diagIn[0] = diag_;       gs.diagIn[1] = diag_ + NV;
        gs.deg[0] = deg_ + 2 * NV;  gs.deg[1] = deg_ + 3 * NV;
        gs.diag[0] = diag_ + 2 * NV; gs.diag[1] = diag_ + 3 * NV;
        tf32gemm_s<<<dim3(NV / 64, NV / 128, 2), 256>>>(gs);
    }
    {
        GemS gs;
        gs.A[0] = Mtb[1];
        gs.B[0] = attb[1] + 2 * PLANE;
        gs.C[0] = Mb[1];
        gs.degIn[0] = deg_ + 3 * NV;
        gs.diagIn[0] = diag_ + 3 * NV;
        gs.deg[0] = deg_ + 4 * NV;
        gs.diag[0] = diag_ + 4 * NV;
        gs.A[1] = gs.A[0]; gs.B[1] = gs.B[0]; gs.C[1] = gs.C[0];
        gs.degIn[1] = gs.degIn[0]; gs.diagIn[1] = gs.diagIn[0];
        gs.deg[1] = gs.deg[0]; gs.diag[1] = gs.diag[0];
        tf32gemm_s<<<dim3(NV / 64, NV / 128, 1), 256>>>(gs);
    }
    // single dinv_fix for dv2..dv4 (emax needs dv2, dv4)
    dinv_fix<<<(3 * NV + 255) / 256, 256>>>(deg_ + 2 * NV, diag_ + 2 * NV, dinv_ + 2 * NV, 3 * NV);

    // -------- scaled merge + final dinv --------
    emax_dinv<<<NV, 256>>>(Mtb[0], dinv_ + 2 * NV, Mb[1], dinv_ + 4 * NV, An_, dinv_ + 5 * NV);

    // -------- GCN layers, final norm fused into A-loads --------
    sgemmKS<<<dim3(8, NV / 64), blk16>>>(An_, dinv_ + 5 * NV, XW_, H_, HIDD, NV, 8, nullptr);
    sgemm64<<<dim3(1, NV / 64), blk16>>>(H_, w2, HW_, NV, REPD, HIDD, bias1);  // relu(H+bias1) @ w2
    sgemmKS<<<dim3(8, NV / 64), blk16>>>(An_, dinv_ + 5 * NV, HW_, out, REPD, NV, 8, bias2);
}